// round 1
// baseline (speedup 1.0000x reference)
#include <cuda_runtime.h>

// ---------------- problem dims ----------------
#define NB     2
#define SEQ    1024
#define DIM    1024
#define NH     16
#define NKV    4
#define HSZ    64
#define NLAYER 6
#define VOCAB  32000
#define FFD    4096
#define NTOK   (NB*SEQ)          // 2048
#define KVD    (NKV*HSZ)         // 256

// ---------------- scratch (static device globals; no allocs allowed) ----------------
__device__ float g_x [NTOK*DIM];
__device__ float g_h [NTOK*DIM];
__device__ float g_q [NTOK*DIM];
__device__ float g_k [NTOK*KVD];
__device__ float g_v [NTOK*KVD];
__device__ float g_y [NTOK*DIM];
__device__ float g_ff[NTOK*FFD];

// ---------------- embedding: x = tok_emb[tokens] + pos_emb ----------------
__global__ void embed_kernel(const int* __restrict__ tok, const float* __restrict__ te,
                             const float* __restrict__ pe, float* __restrict__ x) {
    int idx = blockIdx.x * 256 + threadIdx.x;       // over NTOK*DIM
    int row = idx >> 10;                            // b*SEQ + t
    int d   = idx & (DIM - 1);
    int t   = row & (SEQ - 1);
    x[idx] = te[(size_t)tok[row] * DIM + d] + pe[t * DIM + d];
}

// ---------------- layernorm: one block per row, 256 thr, D=1024 ----------------
__global__ __launch_bounds__(256) void ln_kernel(const float* __restrict__ x,
                                                 const float* __restrict__ g,
                                                 const float* __restrict__ b,
                                                 float* __restrict__ y) {
    int row = blockIdx.x;
    int tid = threadIdx.x;
    const float* xr = x + (size_t)row * DIM;
    float4 v = *(const float4*)(xr + tid * 4);
    float sum = v.x + v.y + v.z + v.w;
    float sq  = v.x*v.x + v.y*v.y + v.z*v.z + v.w*v.w;
    #pragma unroll
    for (int o = 16; o > 0; o >>= 1) {
        sum += __shfl_xor_sync(0xffffffffu, sum, o);
        sq  += __shfl_xor_sync(0xffffffffu, sq,  o);
    }
    __shared__ float sh[18];
    int wid = tid >> 5, lane = tid & 31;
    if (lane == 0) { sh[wid] = sum; sh[8 + wid] = sq; }
    __syncthreads();
    if (tid == 0) {
        float a = 0.f, c = 0.f;
        #pragma unroll
        for (int w = 0; w < 8; w++) { a += sh[w]; c += sh[8 + w]; }
        float mu  = a * (1.0f / DIM);
        float var = c * (1.0f / DIM) - mu * mu;
        sh[16] = mu;
        sh[17] = rsqrtf(var + 1e-5f);
    }
    __syncthreads();
    float mu = sh[16], rstd = sh[17];
    float4 gg = *(const float4*)(g + tid * 4);
    float4 bb = *(const float4*)(b + tid * 4);
    float4 o4;
    o4.x = (v.x - mu) * rstd * gg.x + bb.x;
    o4.y = (v.y - mu) * rstd * gg.y + bb.y;
    o4.z = (v.z - mu) * rstd * gg.z + bb.z;
    o4.w = (v.w - mu) * rstd * gg.w + bb.w;
    *(float4*)(y + (size_t)row * DIM + tid * 4) = o4;
}

// ---------------- SGEMM: C = A(MxK) @ B(KxN) row-major, 128x128x8 tiles ----------------
// EPI: 0 plain, 1 +bias, 2 relu(+bias), 3 +bias+residual
template <int EPI>
__global__ __launch_bounds__(256) void sgemm(const float* __restrict__ A,
                                             const float* __restrict__ B,
                                             const float* __restrict__ bias,
                                             const float* __restrict__ res,
                                             float* __restrict__ C,
                                             int M, int N, int K) {
    __shared__ float As[8][128];
    __shared__ float Bs[8][128];
    int tid = threadIdx.x;
    int bm = blockIdx.y * 128, bn = blockIdx.x * 128;

    int arow = tid >> 1;               // 0..127
    int acol = (tid & 1) * 4;          // 0 or 4
    int brow = tid >> 5;               // 0..7
    int bcol = (tid & 31) * 4;         // 0..124

    const float* Aptr = A + (size_t)(bm + arow) * K + acol;
    const float* Bptr = B + (size_t)brow * N + bn + bcol;

    int tx = (tid & 15) * 8;           // col within tile
    int ty = (tid >> 4) * 8;           // row within tile
    float acc[8][8];
    #pragma unroll
    for (int i = 0; i < 8; i++)
        #pragma unroll
        for (int j = 0; j < 8; j++) acc[i][j] = 0.f;

    for (int k0 = 0; k0 < K; k0 += 8) {
        float4 a4 = *(const float4*)Aptr;  Aptr += 8;
        float4 b4 = *(const float4*)Bptr;  Bptr += (size_t)8 * N;
        As[acol + 0][arow] = a4.x;
        As[acol + 1][arow] = a4.y;
        As[acol + 2][arow] = a4.z;
        As[acol + 3][arow] = a4.w;
        *(float4*)&Bs[brow][bcol] = b4;
        __syncthreads();
        #pragma unroll
        for (int k = 0; k < 8; k++) {
            float ar[8], br[8];
            *(float4*)&ar[0] = *(const float4*)&As[k][ty];
            *(float4*)&ar[4] = *(const float4*)&As[k][ty + 4];
            *(float4*)&br[0] = *(const float4*)&Bs[k][tx];
            *(float4*)&br[4] = *(const float4*)&Bs[k][tx + 4];
            #pragma unroll
            for (int i = 0; i < 8; i++)
                #pragma unroll
                for (int j = 0; j < 8; j++)
                    acc[i][j] = fmaf(ar[i], br[j], acc[i][j]);
        }
        __syncthreads();
    }

    #pragma unroll
    for (int i = 0; i < 8; i++) {
        size_t row = (size_t)(bm + ty + i);
        #pragma unroll
        for (int j = 0; j < 8; j += 4) {
            int col = bn + tx + j;
            float4 o;
            o.x = acc[i][j]; o.y = acc[i][j+1]; o.z = acc[i][j+2]; o.w = acc[i][j+3];
            if (EPI >= 1) {
                float4 bb = *(const float4*)(bias + col);
                o.x += bb.x; o.y += bb.y; o.z += bb.z; o.w += bb.w;
            }
            if (EPI == 2) {
                o.x = fmaxf(o.x, 0.f); o.y = fmaxf(o.y, 0.f);
                o.z = fmaxf(o.z, 0.f); o.w = fmaxf(o.w, 0.f);
            }
            if (EPI == 3) {
                float4 r = *(const float4*)(res + row * N + col);
                o.x += r.x; o.y += r.y; o.z += r.z; o.w += r.w;
            }
            *(float4*)(C + row * N + col) = o;
        }
    }
}

// ---------------- fused causal GQA attention (flash-style, fp32) ----------------
// grid: (SEQ/64, NH, NB), 64 threads, each thread owns one query row.
__global__ __launch_bounds__(64) void attn_kernel(const float* __restrict__ Q,
                                                  const float* __restrict__ K,
                                                  const float* __restrict__ V,
                                                  float* __restrict__ Y) {
    __shared__ __align__(16) float ks[64][64];
    __shared__ __align__(16) float vs[64][64];
    __shared__ float ss[64][65];

    int itile = blockIdx.x;
    int h     = blockIdx.y;
    int b     = blockIdx.z;
    int kvh   = h >> 2;                      // REP = 4
    int tid   = threadIdx.x;
    int i     = itile * 64 + tid;

    const float scale = 0.125f;              // 1/sqrt(64)
    float q[64], o[64];
    const float* qrow = Q + ((size_t)(b * SEQ + i)) * DIM + h * HSZ;
    #pragma unroll
    for (int d = 0; d < 64; d += 4) {
        float4 t = *(const float4*)(qrow + d);
        q[d] = t.x * scale; q[d+1] = t.y * scale; q[d+2] = t.z * scale; q[d+3] = t.w * scale;
    }
    #pragma unroll
    for (int d = 0; d < 64; d++) o[d] = 0.f;
    float m = -1e30f, l = 0.f;

    for (int j0 = 0; j0 <= itile * 64; j0 += 64) {
        const float* krow = K + ((size_t)(b * SEQ + j0 + tid)) * KVD + kvh * HSZ;
        const float* vrow = V + ((size_t)(b * SEQ + j0 + tid)) * KVD + kvh * HSZ;
        #pragma unroll
        for (int d = 0; d < 64; d += 4) {
            *(float4*)&ks[tid][d] = *(const float4*)(krow + d);
            *(float4*)&vs[tid][d] = *(const float4*)(vrow + d);
        }
        __syncthreads();

        float mt = m;
        #pragma unroll 4
        for (int j = 0; j < 64; j++) {
            float acc = 0.f;
            #pragma unroll
            for (int d = 0; d < 64; d += 4) {
                float4 kk = *(const float4*)&ks[j][d];
                acc = fmaf(q[d],   kk.x, acc);
                acc = fmaf(q[d+1], kk.y, acc);
                acc = fmaf(q[d+2], kk.z, acc);
                acc = fmaf(q[d+3], kk.w, acc);
            }
            if (j0 + j > i) acc = -1e30f;
            ss[tid][j] = acc;
            mt = fmaxf(mt, acc);
        }

        float corr = __expf(m - mt);
        l *= corr;
        #pragma unroll
        for (int d = 0; d < 64; d++) o[d] *= corr;

        #pragma unroll 2
        for (int j = 0; j < 64; j++) {
            float p = __expf(ss[tid][j] - mt);
            l += p;
            #pragma unroll
            for (int d = 0; d < 64; d += 4) {
                float4 vv = *(const float4*)&vs[j][d];
                o[d]   = fmaf(p, vv.x, o[d]);
                o[d+1] = fmaf(p, vv.y, o[d+1]);
                o[d+2] = fmaf(p, vv.z, o[d+2]);
                o[d+3] = fmaf(p, vv.w, o[d+3]);
            }
        }
        m = mt;
        __syncthreads();
    }

    float inv = 1.0f / l;
    float* yrow = Y + ((size_t)(b * SEQ + i)) * DIM + h * HSZ;
    #pragma unroll
    for (int d = 0; d < 64; d += 4) {
        float4 t;
        t.x = o[d] * inv; t.y = o[d+1] * inv; t.z = o[d+2] * inv; t.w = o[d+3] * inv;
        *(float4*)(yrow + d) = t;
    }
}

// ---------------- host ----------------
template <typename Tp>
static float* sym_addr(Tp& s) {
    void* p = nullptr;
    cudaGetSymbolAddress(&p, s);
    return (float*)p;
}

static void launch_gemm(int epi, const float* A, const float* B, const float* bias,
                        const float* res, float* C, int M, int N, int K) {
    dim3 grid(N / 128, M / 128);
    switch (epi) {
        case 0: sgemm<0><<<grid, 256>>>(A, B, bias, res, C, M, N, K); break;
        case 1: sgemm<1><<<grid, 256>>>(A, B, bias, res, C, M, N, K); break;
        case 2: sgemm<2><<<grid, 256>>>(A, B, bias, res, C, M, N, K); break;
        case 3: sgemm<3><<<grid, 256>>>(A, B, bias, res, C, M, N, K); break;
    }
}

extern "C" void kernel_launch(void* const* d_in, const int* in_sizes, int n_in,
                              void* d_out, int out_size) {
    const int*   tok   = (const int*)  d_in[0];
    const float* te    = (const float*)d_in[1];
    const float* pe    = (const float*)d_in[2];
    const float* ln1g  = (const float*)d_in[3];
    const float* ln1b  = (const float*)d_in[4];
    const float* Wq    = (const float*)d_in[5];
    const float* Wk    = (const float*)d_in[6];
    const float* Wv    = (const float*)d_in[7];
    const float* Wo    = (const float*)d_in[8];
    const float* bo    = (const float*)d_in[9];
    const float* ln2g  = (const float*)d_in[10];
    const float* ln2b  = (const float*)d_in[11];
    const float* W1    = (const float*)d_in[12];
    const float* b1    = (const float*)d_in[13];
    const float* W2    = (const float*)d_in[14];
    const float* b2    = (const float*)d_in[15];
    const float* lnfg  = (const float*)d_in[16];
    const float* lnfb  = (const float*)d_in[17];
    const float* Wlm   = (const float*)d_in[18];
    const float* blm   = (const float*)d_in[19];
    float* out = (float*)d_out;

    float* x  = sym_addr(g_x);
    float* h  = sym_addr(g_h);
    float* q  = sym_addr(g_q);
    float* k  = sym_addr(g_k);
    float* v  = sym_addr(g_v);
    float* y  = sym_addr(g_y);
    float* ff = sym_addr(g_ff);

    embed_kernel<<<NTOK * DIM / 256, 256>>>(tok, te, pe, x);

    for (int l = 0; l < NLAYER; l++) {
        const float* wq = Wq + (size_t)l * DIM * DIM;
        const float* wk = Wk + (size_t)l * DIM * KVD;
        const float* wv = Wv + (size_t)l * DIM * KVD;
        const float* wo = Wo + (size_t)l * DIM * DIM;
        const float* w1 = W1 + (size_t)l * DIM * FFD;
        const float* w2 = W2 + (size_t)l * FFD * DIM;

        ln_kernel<<<NTOK, 256>>>(x, ln1g + l * DIM, ln1b + l * DIM, h);

        launch_gemm(0, h, wq, nullptr, nullptr, q, NTOK, DIM, DIM);
        launch_gemm(0, h, wk, nullptr, nullptr, k, NTOK, KVD, DIM);
        launch_gemm(0, h, wv, nullptr, nullptr, v, NTOK, KVD, DIM);

        attn_kernel<<<dim3(SEQ / 64, NH, NB), 64>>>(q, k, v, y);

        // x = x + y @ wo + bo
        launch_gemm(3, y, wo, bo + l * DIM, x, x, NTOK, DIM, DIM);

        ln_kernel<<<NTOK, 256>>>(x, ln2g + l * DIM, ln2b + l * DIM, h);

        // ff = relu(h @ w1 + b1)
        launch_gemm(2, h, w1, b1 + (size_t)l * FFD, nullptr, ff, NTOK, FFD, DIM);
        // x = x + ff @ w2 + b2
        launch_gemm(3, ff, w2, b2 + l * DIM, x, x, NTOK, DIM, FFD);
    }

    ln_kernel<<<NTOK, 256>>>(x, lnfg, lnfb, h);
    // logits = h @ Wlm + blm
    launch_gemm(1, h, Wlm, blm, nullptr, out, NTOK, VOCAB, DIM);
}

// round 2
// speedup vs baseline: 1.2909x; 1.2909x over previous
#include <cuda_runtime.h>
#include <cuda_bf16.h>

// ---------------- problem dims ----------------
#define NB     2
#define SEQ    1024
#define DIM    1024
#define NH     16
#define NKV    4
#define HSZ    64
#define NLAYER 6
#define VOCAB  32000
#define FFD    4096
#define NTOK   (NB*SEQ)          // 2048
#define KVD    (NKV*HSZ)         // 256
#define QKVD   (DIM + 2*KVD)     // 1536

// ---------------- scratch ----------------
__device__ float g_x   [NTOK*DIM];
__device__ float g_h   [NTOK*DIM];
__device__ float g_qkv [NTOK*QKVD];
__device__ float g_y   [NTOK*DIM];
__device__ float g_ff  [NTOK*FFD];
__device__ float g_wqkv[DIM*QKVD];

// ---------------- embedding ----------------
__global__ void embed_kernel(const int* __restrict__ tok, const float* __restrict__ te,
                             const float* __restrict__ pe, float* __restrict__ x) {
    int idx = blockIdx.x * 256 + threadIdx.x;
    int row = idx >> 10;
    int d   = idx & (DIM - 1);
    int t   = row & (SEQ - 1);
    x[idx] = te[(size_t)tok[row] * DIM + d] + pe[t * DIM + d];
}

// ---------------- concat Wq|Wk|Wv -> [DIM][QKVD] ----------------
__global__ void concat_qkv(const float* __restrict__ wq, const float* __restrict__ wk,
                           const float* __restrict__ wv, float* __restrict__ w) {
    int idx4 = blockIdx.x * 256 + threadIdx.x;          // over DIM*QKVD/4
    int row  = idx4 / (QKVD / 4);
    int col  = (idx4 % (QKVD / 4)) * 4;
    float4 v;
    if (col < DIM)            v = *(const float4*)(wq + (size_t)row * DIM + col);
    else if (col < DIM + KVD) v = *(const float4*)(wk + (size_t)row * KVD + (col - DIM));
    else                      v = *(const float4*)(wv + (size_t)row * KVD + (col - DIM - KVD));
    *(float4*)(w + (size_t)row * QKVD + col) = v;
}

// ---------------- layernorm ----------------
__global__ __launch_bounds__(256) void ln_kernel(const float* __restrict__ x,
                                                 const float* __restrict__ g,
                                                 const float* __restrict__ b,
                                                 float* __restrict__ y) {
    int row = blockIdx.x;
    int tid = threadIdx.x;
    const float* xr = x + (size_t)row * DIM;
    float4 v = *(const float4*)(xr + tid * 4);
    float sum = v.x + v.y + v.z + v.w;
    float sq  = v.x*v.x + v.y*v.y + v.z*v.z + v.w*v.w;
    #pragma unroll
    for (int o = 16; o > 0; o >>= 1) {
        sum += __shfl_xor_sync(0xffffffffu, sum, o);
        sq  += __shfl_xor_sync(0xffffffffu, sq,  o);
    }
    __shared__ float sh[18];
    int wid = tid >> 5, lane = tid & 31;
    if (lane == 0) { sh[wid] = sum; sh[8 + wid] = sq; }
    __syncthreads();
    if (tid == 0) {
        float a = 0.f, c = 0.f;
        #pragma unroll
        for (int w = 0; w < 8; w++) { a += sh[w]; c += sh[8 + w]; }
        float mu  = a * (1.0f / DIM);
        float var = c * (1.0f / DIM) - mu * mu;
        sh[16] = mu;
        sh[17] = rsqrtf(var + 1e-5f);
    }
    __syncthreads();
    float mu = sh[16], rstd = sh[17];
    float4 gg = *(const float4*)(g + tid * 4);
    float4 bb = *(const float4*)(b + tid * 4);
    float4 o4;
    o4.x = (v.x - mu) * rstd * gg.x + bb.x;
    o4.y = (v.y - mu) * rstd * gg.y + bb.y;
    o4.z = (v.z - mu) * rstd * gg.z + bb.z;
    o4.w = (v.w - mu) * rstd * gg.w + bb.w;
    *(float4*)(y + (size_t)row * DIM + tid * 4) = o4;
}

// =====================================================================
// Split-bf16 tensor-core GEMM: C = A(MxK) @ B(KxN), fp32 in/out.
// A = Ah + Al, B = Bh + Bl (bf16); acc += Ah*Bh + Ah*Bl + Al*Bh (fp32).
// 128x128 CTA tile, BK=32, 8 warps in 2(M)x4(N), mma.m16n8k16.
// EPI: 0 plain, 1 +bias, 2 relu(+bias), 3 +bias+residual
// =====================================================================
#define BK 32
#define SPAD 40   // smem row stride in bf16 elems (conflict-free: 20 banks)

__device__ __forceinline__ void mma16816(float* c, const unsigned* a, const unsigned* b) {
    asm volatile(
        "mma.sync.aligned.m16n8k16.row.col.f32.bf16.bf16.f32 "
        "{%0,%1,%2,%3}, {%4,%5,%6,%7}, {%8,%9}, {%0,%1,%2,%3};\n"
        : "+f"(c[0]), "+f"(c[1]), "+f"(c[2]), "+f"(c[3])
        : "r"(a[0]), "r"(a[1]), "r"(a[2]), "r"(a[3]), "r"(b[0]), "r"(b[1]));
}

template <int EPI>
__global__ __launch_bounds__(256, 1) void sgemm_tc(const float* __restrict__ A,
                                                   const float* __restrict__ B,
                                                   const float* __restrict__ bias,
                                                   const float* __restrict__ res,
                                                   float* __restrict__ C,
                                                   int M, int N, int K) {
    __shared__ __nv_bfloat16 Ah[128][SPAD], Al[128][SPAD];
    __shared__ __nv_bfloat16 Bh[128][SPAD], Bl[128][SPAD];

    int tid = threadIdx.x;
    int bm = blockIdx.y * 128, bn = blockIdx.x * 128;
    int wid = tid >> 5, lane = tid & 31;
    int wm = (wid & 1) * 64;          // warp M offset
    int wn = (wid >> 1) * 32;         // warp N offset
    int g  = lane >> 2, tg = lane & 3;

    // fill indices: A tile [128][32] floats, B tile [32][128] floats
    int aR[4], aC[4], bK[4], bNc[4];
    #pragma unroll
    for (int i = 0; i < 4; i++) {
        int idx = tid + i * 256;
        aR[i] = idx >> 3;        aC[i]  = (idx & 7) * 4;
        bK[i] = idx >> 5;        bNc[i] = (idx & 31) * 4;
    }

    float4 aReg[4], bReg[4];
    #pragma unroll
    for (int i = 0; i < 4; i++) {
        aReg[i] = *(const float4*)(A + (size_t)(bm + aR[i]) * K + aC[i]);
        bReg[i] = *(const float4*)(B + (size_t)bK[i] * N + bn + bNc[i]);
    }

    float acc[4][4][4];
    #pragma unroll
    for (int a = 0; a < 4; a++)
        #pragma unroll
        for (int b = 0; b < 4; b++)
            #pragma unroll
            for (int c = 0; c < 4; c++) acc[a][b][c] = 0.f;

    for (int k0 = 0; k0 < K; k0 += BK) {
        // convert + store to smem
        #pragma unroll
        for (int i = 0; i < 4; i++) {
            float av[4] = {aReg[i].x, aReg[i].y, aReg[i].z, aReg[i].w};
            #pragma unroll
            for (int j = 0; j < 4; j++) {
                __nv_bfloat16 h = __float2bfloat16(av[j]);
                Ah[aR[i]][aC[i] + j] = h;
                Al[aR[i]][aC[i] + j] = __float2bfloat16(av[j] - __bfloat162float(h));
            }
            float bv[4] = {bReg[i].x, bReg[i].y, bReg[i].z, bReg[i].w};
            #pragma unroll
            for (int j = 0; j < 4; j++) {
                __nv_bfloat16 h = __float2bfloat16(bv[j]);
                Bh[bNc[i] + j][bK[i]] = h;
                Bl[bNc[i] + j][bK[i]] = __float2bfloat16(bv[j] - __bfloat162float(h));
            }
        }
        __syncthreads();

        if (k0 + BK < K) {
            #pragma unroll
            for (int i = 0; i < 4; i++) {
                aReg[i] = *(const float4*)(A + (size_t)(bm + aR[i]) * K + (k0 + BK) + aC[i]);
                bReg[i] = *(const float4*)(B + (size_t)(k0 + BK + bK[i]) * N + bn + bNc[i]);
            }
        }

        #pragma unroll
        for (int kk = 0; kk < BK; kk += 16) {
            unsigned afh[4][4], afl[4][4];
            #pragma unroll
            for (int mt = 0; mt < 4; mt++) {
                int r0 = wm + mt * 16 + g;
                int c0 = kk + tg * 2;
                afh[mt][0] = *(const unsigned*)&Ah[r0    ][c0    ];
                afh[mt][1] = *(const unsigned*)&Ah[r0 + 8][c0    ];
                afh[mt][2] = *(const unsigned*)&Ah[r0    ][c0 + 8];
                afh[mt][3] = *(const unsigned*)&Ah[r0 + 8][c0 + 8];
                afl[mt][0] = *(const unsigned*)&Al[r0    ][c0    ];
                afl[mt][1] = *(const unsigned*)&Al[r0 + 8][c0    ];
                afl[mt][2] = *(const unsigned*)&Al[r0    ][c0 + 8];
                afl[mt][3] = *(const unsigned*)&Al[r0 + 8][c0 + 8];
            }
            #pragma unroll
            for (int nt = 0; nt < 4; nt++) {
                int nc = wn + nt * 8 + g;
                int c0 = kk + tg * 2;
                unsigned bfh[2], bfl[2];
                bfh[0] = *(const unsigned*)&Bh[nc][c0    ];
                bfh[1] = *(const unsigned*)&Bh[nc][c0 + 8];
                bfl[0] = *(const unsigned*)&Bl[nc][c0    ];
                bfl[1] = *(const unsigned*)&Bl[nc][c0 + 8];
                #pragma unroll
                for (int mt = 0; mt < 4; mt++) {
                    mma16816(acc[mt][nt], afh[mt], bfh);
                    mma16816(acc[mt][nt], afh[mt], bfl);
                    mma16816(acc[mt][nt], afl[mt], bfh);
                }
            }
        }
        __syncthreads();
    }

    // epilogue
    #pragma unroll
    for (int mt = 0; mt < 4; mt++) {
        #pragma unroll
        for (int nt = 0; nt < 4; nt++) {
            int row = bm + wm + mt * 16 + g;
            int col = bn + wn + nt * 8 + tg * 2;
            float2 o0 = make_float2(acc[mt][nt][0], acc[mt][nt][1]);
            float2 o1 = make_float2(acc[mt][nt][2], acc[mt][nt][3]);
            if (EPI >= 1) {
                float2 bb = *(const float2*)(bias + col);
                o0.x += bb.x; o0.y += bb.y; o1.x += bb.x; o1.y += bb.y;
            }
            if (EPI == 2) {
                o0.x = fmaxf(o0.x, 0.f); o0.y = fmaxf(o0.y, 0.f);
                o1.x = fmaxf(o1.x, 0.f); o1.y = fmaxf(o1.y, 0.f);
            }
            if (EPI == 3) {
                float2 r0 = *(const float2*)(res + (size_t)row * N + col);
                float2 r1 = *(const float2*)(res + (size_t)(row + 8) * N + col);
                o0.x += r0.x; o0.y += r0.y; o1.x += r1.x; o1.y += r1.y;
            }
            *(float2*)(C + (size_t)row * N + col) = o0;
            *(float2*)(C + (size_t)(row + 8) * N + col) = o1;
        }
    }
}

// ---------------- fused causal GQA attention (flash-style, fp32) ----------------
// QKV packed: row stride QKVD; Q at h*64, K at DIM + kvh*64, V at DIM+KVD + kvh*64
__global__ __launch_bounds__(64) void attn_kernel(const float* __restrict__ QKV,
                                                  float* __restrict__ Y) {
    __shared__ __align__(16) float ks[64][64];
    __shared__ __align__(16) float vs[64][64];
    __shared__ float ss[64][65];

    int itile = blockIdx.x;
    int h     = blockIdx.y;
    int b     = blockIdx.z;
    int kvh   = h >> 2;
    int tid   = threadIdx.x;
    int i     = itile * 64 + tid;

    const float scale = 0.125f;
    float q[64], o[64];
    const float* qrow = QKV + ((size_t)(b * SEQ + i)) * QKVD + h * HSZ;
    #pragma unroll
    for (int d = 0; d < 64; d += 4) {
        float4 t = *(const float4*)(qrow + d);
        q[d] = t.x * scale; q[d+1] = t.y * scale; q[d+2] = t.z * scale; q[d+3] = t.w * scale;
    }
    #pragma unroll
    for (int d = 0; d < 64; d++) o[d] = 0.f;
    float m = -1e30f, l = 0.f;

    for (int j0 = 0; j0 <= itile * 64; j0 += 64) {
        const float* krow = QKV + ((size_t)(b * SEQ + j0 + tid)) * QKVD + DIM + kvh * HSZ;
        const float* vrow = krow + KVD;
        #pragma unroll
        for (int d = 0; d < 64; d += 4) {
            *(float4*)&ks[tid][d] = *(const float4*)(krow + d);
            *(float4*)&vs[tid][d] = *(const float4*)(vrow + d);
        }
        __syncthreads();

        float mt = m;
        #pragma unroll 4
        for (int j = 0; j < 64; j++) {
            float acc = 0.f;
            #pragma unroll
            for (int d = 0; d < 64; d += 4) {
                float4 kk = *(const float4*)&ks[j][d];
                acc = fmaf(q[d],   kk.x, acc);
                acc = fmaf(q[d+1], kk.y, acc);
                acc = fmaf(q[d+2], kk.z, acc);
                acc = fmaf(q[d+3], kk.w, acc);
            }
            if (j0 + j > i) acc = -1e30f;
            ss[tid][j] = acc;
            mt = fmaxf(mt, acc);
        }

        float corr = __expf(m - mt);
        l *= corr;
        #pragma unroll
        for (int d = 0; d < 64; d++) o[d] *= corr;

        #pragma unroll 2
        for (int j = 0; j < 64; j++) {
            float p = __expf(ss[tid][j] - mt);
            l += p;
            #pragma unroll
            for (int d = 0; d < 64; d += 4) {
                float4 vv = *(const float4*)&vs[j][d];
                o[d]   = fmaf(p, vv.x, o[d]);
                o[d+1] = fmaf(p, vv.y, o[d+1]);
                o[d+2] = fmaf(p, vv.z, o[d+2]);
                o[d+3] = fmaf(p, vv.w, o[d+3]);
            }
        }
        m = mt;
        __syncthreads();
    }

    float inv = 1.0f / l;
    float* yrow = Y + ((size_t)(b * SEQ + i)) * DIM + h * HSZ;
    #pragma unroll
    for (int d = 0; d < 64; d += 4) {
        float4 t;
        t.x = o[d] * inv; t.y = o[d+1] * inv; t.z = o[d+2] * inv; t.w = o[d+3] * inv;
        *(float4*)(yrow + d) = t;
    }
}

// ---------------- host ----------------
template <typename Tp>
static float* sym_addr(Tp& s) {
    void* p = nullptr;
    cudaGetSymbolAddress(&p, s);
    return (float*)p;
}

static void launch_gemm(int epi, const float* A, const float* B, const float* bias,
                        const float* res, float* C, int M, int N, int K) {
    dim3 grid(N / 128, M / 128);
    switch (epi) {
        case 0: sgemm_tc<0><<<grid, 256>>>(A, B, bias, res, C, M, N, K); break;
        case 1: sgemm_tc<1><<<grid, 256>>>(A, B, bias, res, C, M, N, K); break;
        case 2: sgemm_tc<2><<<grid, 256>>>(A, B, bias, res, C, M, N, K); break;
        case 3: sgemm_tc<3><<<grid, 256>>>(A, B, bias, res, C, M, N, K); break;
    }
}

extern "C" void kernel_launch(void* const* d_in, const int* in_sizes, int n_in,
                              void* d_out, int out_size) {
    const int*   tok   = (const int*)  d_in[0];
    const float* te    = (const float*)d_in[1];
    const float* pe    = (const float*)d_in[2];
    const float* ln1g  = (const float*)d_in[3];
    const float* ln1b  = (const float*)d_in[4];
    const float* Wq    = (const float*)d_in[5];
    const float* Wk    = (const float*)d_in[6];
    const float* Wv    = (const float*)d_in[7];
    const float* Wo    = (const float*)d_in[8];
    const float* bo    = (const float*)d_in[9];
    const float* ln2g  = (const float*)d_in[10];
    const float* ln2b  = (const float*)d_in[11];
    const float* W1    = (const float*)d_in[12];
    const float* b1    = (const float*)d_in[13];
    const float* W2    = (const float*)d_in[14];
    const float* b2    = (const float*)d_in[15];
    const float* lnfg  = (const float*)d_in[16];
    const float* lnfb  = (const float*)d_in[17];
    const float* Wlm   = (const float*)d_in[18];
    const float* blm   = (const float*)d_in[19];
    float* out = (float*)d_out;

    float* x    = sym_addr(g_x);
    float* h    = sym_addr(g_h);
    float* qkv  = sym_addr(g_qkv);
    float* y    = sym_addr(g_y);
    float* ff   = sym_addr(g_ff);
    float* wqkv = sym_addr(g_wqkv);

    embed_kernel<<<NTOK * DIM / 256, 256>>>(tok, te, pe, x);

    for (int l = 0; l < NLAYER; l++) {
        const float* wq = Wq + (size_t)l * DIM * DIM;
        const float* wk = Wk + (size_t)l * DIM * KVD;
        const float* wv = Wv + (size_t)l * DIM * KVD;
        const float* wo = Wo + (size_t)l * DIM * DIM;
        const float* w1 = W1 + (size_t)l * DIM * FFD;
        const float* w2 = W2 + (size_t)l * FFD * DIM;

        concat_qkv<<<DIM * QKVD / 4 / 256, 256>>>(wq, wk, wv, wqkv);

        ln_kernel<<<NTOK, 256>>>(x, ln1g + l * DIM, ln1b + l * DIM, h);

        // qkv = h @ wqkv   (no bias)
        launch_gemm(0, h, wqkv, nullptr, nullptr, qkv, NTOK, QKVD, DIM);

        attn_kernel<<<dim3(SEQ / 64, NH, NB), 64>>>(qkv, y);

        // x = x + y @ wo + bo
        launch_gemm(3, y, wo, bo + l * DIM, x, x, NTOK, DIM, DIM);

        ln_kernel<<<NTOK, 256>>>(x, ln2g + l * DIM, ln2b + l * DIM, h);

        // ff = relu(h @ w1 + b1)
        launch_gemm(2, h, w1, b1 + (size_t)l * FFD, nullptr, ff, NTOK, FFD, DIM);
        // x = x + ff @ w2 + b2
        launch_gemm(3, ff, w2, b2 + l * DIM, x, x, NTOK, DIM, FFD);
    }

    ln_kernel<<<NTOK, 256>>>(x, lnfg, lnfb, h);
    // logits = h @ Wlm + blm
    launch_gemm(1, h, Wlm, blm, nullptr, out, NTOK, VOCAB, DIM);
}

// round 3
// speedup vs baseline: 2.1788x; 1.6879x over previous
#include <cuda_runtime.h>
#include <cuda_bf16.h>

// ---------------- problem dims ----------------
#define NB     2
#define SEQ    1024
#define DIM    1024
#define NH     16
#define NKV    4
#define HSZ    64
#define NLAYER 6
#define VOCAB  32000
#define FFD    4096
#define NTOK   (NB*SEQ)          // 2048
#define KVD    (NKV*HSZ)         // 256
#define QKVD   (DIM + 2*KVD)     // 1536

// ---------------- scratch ----------------
__device__ float g_x   [NTOK*DIM];
__device__ float g_h   [NTOK*DIM];
__device__ float g_qkv [NTOK*QKVD];
__device__ float g_y   [NTOK*DIM];
__device__ float g_ff  [NTOK*FFD];
__device__ float g_wqkv[DIM*QKVD];

// ---------------- embedding ----------------
__global__ void embed_kernel(const int* __restrict__ tok, const float* __restrict__ te,
                             const float* __restrict__ pe, float* __restrict__ x) {
    int idx = blockIdx.x * 256 + threadIdx.x;
    int row = idx >> 10;
    int d   = idx & (DIM - 1);
    int t   = row & (SEQ - 1);
    x[idx] = te[(size_t)tok[row] * DIM + d] + pe[t * DIM + d];
}

// ---------------- concat Wq|Wk|Wv -> [DIM][QKVD] ----------------
__global__ void concat_qkv(const float* __restrict__ wq, const float* __restrict__ wk,
                           const float* __restrict__ wv, float* __restrict__ w) {
    int idx4 = blockIdx.x * 256 + threadIdx.x;
    int row  = idx4 / (QKVD / 4);
    int col  = (idx4 % (QKVD / 4)) * 4;
    float4 v;
    if (col < DIM)            v = *(const float4*)(wq + (size_t)row * DIM + col);
    else if (col < DIM + KVD) v = *(const float4*)(wk + (size_t)row * KVD + (col - DIM));
    else                      v = *(const float4*)(wv + (size_t)row * KVD + (col - DIM - KVD));
    *(float4*)(w + (size_t)row * QKVD + col) = v;
}

// ---------------- layernorm ----------------
__global__ __launch_bounds__(256) void ln_kernel(const float* __restrict__ x,
                                                 const float* __restrict__ g,
                                                 const float* __restrict__ b,
                                                 float* __restrict__ y) {
    int row = blockIdx.x;
    int tid = threadIdx.x;
    const float* xr = x + (size_t)row * DIM;
    float4 v = *(const float4*)(xr + tid * 4);
    float sum = v.x + v.y + v.z + v.w;
    float sq  = v.x*v.x + v.y*v.y + v.z*v.z + v.w*v.w;
    #pragma unroll
    for (int o = 16; o > 0; o >>= 1) {
        sum += __shfl_xor_sync(0xffffffffu, sum, o);
        sq  += __shfl_xor_sync(0xffffffffu, sq,  o);
    }
    __shared__ float sh[18];
    int wid = tid >> 5, lane = tid & 31;
    if (lane == 0) { sh[wid] = sum; sh[8 + wid] = sq; }
    __syncthreads();
    if (tid == 0) {
        float a = 0.f, c = 0.f;
        #pragma unroll
        for (int w = 0; w < 8; w++) { a += sh[w]; c += sh[8 + w]; }
        float mu  = a * (1.0f / DIM);
        float var = c * (1.0f / DIM) - mu * mu;
        sh[16] = mu;
        sh[17] = rsqrtf(var + 1e-5f);
    }
    __syncthreads();
    float mu = sh[16], rstd = sh[17];
    float4 gg = *(const float4*)(g + tid * 4);
    float4 bb = *(const float4*)(b + tid * 4);
    float4 o4;
    o4.x = (v.x - mu) * rstd * gg.x + bb.x;
    o4.y = (v.y - mu) * rstd * gg.y + bb.y;
    o4.z = (v.z - mu) * rstd * gg.z + bb.z;
    o4.w = (v.w - mu) * rstd * gg.w + bb.w;
    *(float4*)(y + (size_t)row * DIM + tid * 4) = o4;
}

// =====================================================================
// Split-bf16 tensor-core GEMM, ldmatrix + double-buffered smem.
// C = A(MxK) @ B(KxN). A = Ah+Al, B = Bh+Bl (bf16); fp32 accumulate
// of Ah*Bh + Ah*Bl + Al*Bh.  128x128 CTA, BK=32, 8 warps (2M x 4N).
// A smem: [m][k] stride 40 bf16 (conflict-free ldmatrix).
// B smem: [k][n] stride 136 bf16, loaded with ldmatrix.trans.
// =====================================================================
#define BK    32
#define SPADA 40
#define SPADB 136

__device__ __forceinline__ void mma16816(float* c, const unsigned* a, const unsigned* b) {
    asm volatile(
        "mma.sync.aligned.m16n8k16.row.col.f32.bf16.bf16.f32 "
        "{%0,%1,%2,%3}, {%4,%5,%6,%7}, {%8,%9}, {%0,%1,%2,%3};\n"
        : "+f"(c[0]), "+f"(c[1]), "+f"(c[2]), "+f"(c[3])
        : "r"(a[0]), "r"(a[1]), "r"(a[2]), "r"(a[3]), "r"(b[0]), "r"(b[1]));
}

__device__ __forceinline__ void ldsm4(unsigned* r, unsigned addr) {
    asm volatile("ldmatrix.sync.aligned.m8n8.x4.shared.b16 {%0,%1,%2,%3}, [%4];\n"
                 : "=r"(r[0]), "=r"(r[1]), "=r"(r[2]), "=r"(r[3]) : "r"(addr));
}
__device__ __forceinline__ void ldsm4t(unsigned* r, unsigned addr) {
    asm volatile("ldmatrix.sync.aligned.m8n8.x4.trans.shared.b16 {%0,%1,%2,%3}, [%4];\n"
                 : "=r"(r[0]), "=r"(r[1]), "=r"(r[2]), "=r"(r[3]) : "r"(addr));
}

__device__ __forceinline__ unsigned pack2(float x, float y) {
    __nv_bfloat162 t = __floats2bfloat162_rn(x, y);
    return *(unsigned*)&t;
}

template <int EPI>
__global__ __launch_bounds__(256, 1) void sgemm_tc(const float* __restrict__ A,
                                                   const float* __restrict__ B,
                                                   const float* __restrict__ bias,
                                                   const float* __restrict__ res,
                                                   float* __restrict__ C,
                                                   int M, int N, int K) {
    __shared__ __nv_bfloat16 Ah[2][128][SPADA], Al[2][128][SPADA];
    __shared__ __nv_bfloat16 Bh[2][BK][SPADB],  Bl[2][BK][SPADB];

    int tid = threadIdx.x;
    int bm = blockIdx.y * 128, bn = blockIdx.x * 128;
    int wid = tid >> 5, lane = tid & 31;
    int wm = (wid & 1) * 64;
    int wn = (wid >> 1) * 32;
    int g  = lane >> 2, tg = lane & 3;

    // fill indices
    int aR[4], aC[4], bK_[4], bNc[4];
    #pragma unroll
    for (int i = 0; i < 4; i++) {
        int idx = tid + i * 256;
        aR[i]  = idx >> 3;  aC[i]  = (idx & 7) * 4;
        bK_[i] = idx >> 5;  bNc[i] = (idx & 31) * 4;
    }

    // ldmatrix lane address components
    int a_row_l = wm + (lane & 15);
    int a_col_l = (lane >> 4) * 8;
    int b_krow_l = (lane & 7) + ((lane >> 3) & 1) * 8;
    int b_ncol_l = wn + (lane >> 4) * 8;

    unsigned baseAh[2], baseAl[2], baseBh[2], baseBl[2];
    #pragma unroll
    for (int s = 0; s < 2; s++) {
        baseAh[s] = (unsigned)__cvta_generic_to_shared(&Ah[s][0][0]);
        baseAl[s] = (unsigned)__cvta_generic_to_shared(&Al[s][0][0]);
        baseBh[s] = (unsigned)__cvta_generic_to_shared(&Bh[s][0][0]);
        baseBl[s] = (unsigned)__cvta_generic_to_shared(&Bl[s][0][0]);
    }

    float4 aReg[4], bReg[4];
    #pragma unroll
    for (int i = 0; i < 4; i++) {
        aReg[i] = *(const float4*)(A + (size_t)(bm + aR[i]) * K + aC[i]);
        bReg[i] = *(const float4*)(B + (size_t)bK_[i] * N + bn + bNc[i]);
    }

    float acc[4][4][4];
    #pragma unroll
    for (int a = 0; a < 4; a++)
        #pragma unroll
        for (int b = 0; b < 4; b++)
            #pragma unroll
            for (int c = 0; c < 4; c++) acc[a][b][c] = 0.f;

    // convert + store current regs into stage s
    auto cvt_store = [&](int s) {
        #pragma unroll
        for (int i = 0; i < 4; i++) {
            float av[4] = {aReg[i].x, aReg[i].y, aReg[i].z, aReg[i].w};
            float ah[4], al[4];
            #pragma unroll
            for (int j = 0; j < 4; j++) {
                __nv_bfloat16 hh = __float2bfloat16(av[j]);
                ah[j] = __bfloat162float(hh);
                al[j] = av[j] - ah[j];
            }
            uint2 ph, pl;
            ph.x = pack2(ah[0], ah[1]); ph.y = pack2(ah[2], ah[3]);
            pl.x = pack2(al[0], al[1]); pl.y = pack2(al[2], al[3]);
            *(uint2*)&Ah[s][aR[i]][aC[i]] = ph;
            *(uint2*)&Al[s][aR[i]][aC[i]] = pl;

            float bv[4] = {bReg[i].x, bReg[i].y, bReg[i].z, bReg[i].w};
            float bh[4], bl[4];
            #pragma unroll
            for (int j = 0; j < 4; j++) {
                __nv_bfloat16 hh = __float2bfloat16(bv[j]);
                bh[j] = __bfloat162float(hh);
                bl[j] = bv[j] - bh[j];
            }
            uint2 qh, ql;
            qh.x = pack2(bh[0], bh[1]); qh.y = pack2(bh[2], bh[3]);
            ql.x = pack2(bl[0], bl[1]); ql.y = pack2(bl[2], bl[3]);
            *(uint2*)&Bh[s][bK_[i]][bNc[i]] = qh;
            *(uint2*)&Bl[s][bK_[i]][bNc[i]] = ql;
        }
    };

    // compute one stage
    auto compute = [&](int s) {
        #pragma unroll
        for (int kk = 0; kk < BK; kk += 16) {
            unsigned afh[4][4], afl[4][4];
            #pragma unroll
            for (int mt = 0; mt < 4; mt++) {
                unsigned off = ((a_row_l + mt * 16) * SPADA + a_col_l + kk) * 2;
                ldsm4(afh[mt], baseAh[s] + off);
                ldsm4(afl[mt], baseAl[s] + off);
            }
            unsigned bfh[2][4], bfl[2][4];
            #pragma unroll
            for (int p = 0; p < 2; p++) {
                unsigned off = ((kk + b_krow_l) * SPADB + b_ncol_l + p * 16) * 2;
                ldsm4t(bfh[p], baseBh[s] + off);
                ldsm4t(bfl[p], baseBl[s] + off);
            }
            #pragma unroll
            for (int mt = 0; mt < 4; mt++) {
                #pragma unroll
                for (int nt = 0; nt < 4; nt++) {
                    unsigned* bh2 = &bfh[nt >> 1][(nt & 1) * 2];
                    unsigned* bl2 = &bfl[nt >> 1][(nt & 1) * 2];
                    mma16816(acc[mt][nt], afh[mt], bh2);
                    mma16816(acc[mt][nt], afh[mt], bl2);
                    mma16816(acc[mt][nt], afl[mt], bh2);
                }
            }
        }
    };

    cvt_store(0);
    __syncthreads();
    int stage = 0;
    for (int k0 = BK; k0 <= K; k0 += BK) {
        bool more = (k0 < K);
        if (more) {
            #pragma unroll
            for (int i = 0; i < 4; i++) {
                aReg[i] = *(const float4*)(A + (size_t)(bm + aR[i]) * K + k0 + aC[i]);
                bReg[i] = *(const float4*)(B + (size_t)(k0 + bK_[i]) * N + bn + bNc[i]);
            }
        }
        compute(stage);
        if (more) cvt_store(stage ^ 1);
        __syncthreads();
        stage ^= 1;
    }

    // epilogue
    #pragma unroll
    for (int mt = 0; mt < 4; mt++) {
        #pragma unroll
        for (int nt = 0; nt < 4; nt++) {
            int row = bm + wm + mt * 16 + g;
            int col = bn + wn + nt * 8 + tg * 2;
            float2 o0 = make_float2(acc[mt][nt][0], acc[mt][nt][1]);
            float2 o1 = make_float2(acc[mt][nt][2], acc[mt][nt][3]);
            if (EPI >= 1) {
                float2 bb = *(const float2*)(bias + col);
                o0.x += bb.x; o0.y += bb.y; o1.x += bb.x; o1.y += bb.y;
            }
            if (EPI == 2) {
                o0.x = fmaxf(o0.x, 0.f); o0.y = fmaxf(o0.y, 0.f);
                o1.x = fmaxf(o1.x, 0.f); o1.y = fmaxf(o1.y, 0.f);
            }
            if (EPI == 3) {
                float2 r0 = *(const float2*)(res + (size_t)row * N + col);
                float2 r1 = *(const float2*)(res + (size_t)(row + 8) * N + col);
                o0.x += r0.x; o0.y += r0.y; o1.x += r1.x; o1.y += r1.y;
            }
            *(float2*)(C + (size_t)row * N + col) = o0;
            *(float2*)(C + (size_t)(row + 8) * N + col) = o1;
        }
    }
}

// ---------------- fused causal GQA attention (flash-style, fp32) ----------------
__global__ __launch_bounds__(64) void attn_kernel(const float* __restrict__ QKV,
                                                  float* __restrict__ Y) {
    __shared__ __align__(16) float ks[64][64];
    __shared__ __align__(16) float vs[64][64];
    __shared__ float ss[64][65];

    int itile = blockIdx.x;
    int h     = blockIdx.y;
    int b     = blockIdx.z;
    int kvh   = h >> 2;
    int tid   = threadIdx.x;
    int i     = itile * 64 + tid;

    const float scale = 0.125f;
    float q[64], o[64];
    const float* qrow = QKV + ((size_t)(b * SEQ + i)) * QKVD + h * HSZ;
    #pragma unroll
    for (int d = 0; d < 64; d += 4) {
        float4 t = *(const float4*)(qrow + d);
        q[d] = t.x * scale; q[d+1] = t.y * scale; q[d+2] = t.z * scale; q[d+3] = t.w * scale;
    }
    #pragma unroll
    for (int d = 0; d < 64; d++) o[d] = 0.f;
    float m = -1e30f, l = 0.f;

    for (int j0 = 0; j0 <= itile * 64; j0 += 64) {
        const float* krow = QKV + ((size_t)(b * SEQ + j0 + tid)) * QKVD + DIM + kvh * HSZ;
        const float* vrow = krow + KVD;
        #pragma unroll
        for (int d = 0; d < 64; d += 4) {
            *(float4*)&ks[tid][d] = *(const float4*)(krow + d);
            *(float4*)&vs[tid][d] = *(const float4*)(vrow + d);
        }
        __syncthreads();

        float mt = m;
        #pragma unroll 4
        for (int j = 0; j < 64; j++) {
            float acc = 0.f;
            #pragma unroll
            for (int d = 0; d < 64; d += 4) {
                float4 kk = *(const float4*)&ks[j][d];
                acc = fmaf(q[d],   kk.x, acc);
                acc = fmaf(q[d+1], kk.y, acc);
                acc = fmaf(q[d+2], kk.z, acc);
                acc = fmaf(q[d+3], kk.w, acc);
            }
            if (j0 + j > i) acc = -1e30f;
            ss[tid][j] = acc;
            mt = fmaxf(mt, acc);
        }

        float corr = __expf(m - mt);
        l *= corr;
        #pragma unroll
        for (int d = 0; d < 64; d++) o[d] *= corr;

        #pragma unroll 2
        for (int j = 0; j < 64; j++) {
            float p = __expf(ss[tid][j] - mt);
            l += p;
            #pragma unroll
            for (int d = 0; d < 64; d += 4) {
                float4 vv = *(const float4*)&vs[j][d];
                o[d]   = fmaf(p, vv.x, o[d]);
                o[d+1] = fmaf(p, vv.y, o[d+1]);
                o[d+2] = fmaf(p, vv.z, o[d+2]);
                o[d+3] = fmaf(p, vv.w, o[d+3]);
            }
        }
        m = mt;
        __syncthreads();
    }

    float inv = 1.0f / l;
    float* yrow = Y + ((size_t)(b * SEQ + i)) * DIM + h * HSZ;
    #pragma unroll
    for (int d = 0; d < 64; d += 4) {
        float4 t;
        t.x = o[d] * inv; t.y = o[d+1] * inv; t.z = o[d+2] * inv; t.w = o[d+3] * inv;
        *(float4*)(yrow + d) = t;
    }
}

// ---------------- host ----------------
template <typename Tp>
static float* sym_addr(Tp& s) {
    void* p = nullptr;
    cudaGetSymbolAddress(&p, s);
    return (float*)p;
}

static void launch_gemm(int epi, const float* A, const float* B, const float* bias,
                        const float* res, float* C, int M, int N, int K) {
    dim3 grid(N / 128, M / 128);
    switch (epi) {
        case 0: sgemm_tc<0><<<grid, 256>>>(A, B, bias, res, C, M, N, K); break;
        case 1: sgemm_tc<1><<<grid, 256>>>(A, B, bias, res, C, M, N, K); break;
        case 2: sgemm_tc<2><<<grid, 256>>>(A, B, bias, res, C, M, N, K); break;
        case 3: sgemm_tc<3><<<grid, 256>>>(A, B, bias, res, C, M, N, K); break;
    }
}

extern "C" void kernel_launch(void* const* d_in, const int* in_sizes, int n_in,
                              void* d_out, int out_size) {
    const int*   tok   = (const int*)  d_in[0];
    const float* te    = (const float*)d_in[1];
    const float* pe    = (const float*)d_in[2];
    const float* ln1g  = (const float*)d_in[3];
    const float* ln1b  = (const float*)d_in[4];
    const float* Wq    = (const float*)d_in[5];
    const float* Wk    = (const float*)d_in[6];
    const float* Wv    = (const float*)d_in[7];
    const float* Wo    = (const float*)d_in[8];
    const float* bo    = (const float*)d_in[9];
    const float* ln2g  = (const float*)d_in[10];
    const float* ln2b  = (const float*)d_in[11];
    const float* W1    = (const float*)d_in[12];
    const float* b1    = (const float*)d_in[13];
    const float* W2    = (const float*)d_in[14];
    const float* b2    = (const float*)d_in[15];
    const float* lnfg  = (const float*)d_in[16];
    const float* lnfb  = (const float*)d_in[17];
    const float* Wlm   = (const float*)d_in[18];
    const float* blm   = (const float*)d_in[19];
    float* out = (float*)d_out;

    float* x    = sym_addr(g_x);
    float* h    = sym_addr(g_h);
    float* qkv  = sym_addr(g_qkv);
    float* y    = sym_addr(g_y);
    float* ff   = sym_addr(g_ff);
    float* wqkv = sym_addr(g_wqkv);

    embed_kernel<<<NTOK * DIM / 256, 256>>>(tok, te, pe, x);

    for (int l = 0; l < NLAYER; l++) {
        const float* wq = Wq + (size_t)l * DIM * DIM;
        const float* wk = Wk + (size_t)l * DIM * KVD;
        const float* wv = Wv + (size_t)l * DIM * KVD;
        const float* wo = Wo + (size_t)l * DIM * DIM;
        const float* w1 = W1 + (size_t)l * DIM * FFD;
        const float* w2 = W2 + (size_t)l * FFD * DIM;

        concat_qkv<<<DIM * QKVD / 4 / 256, 256>>>(wq, wk, wv, wqkv);

        ln_kernel<<<NTOK, 256>>>(x, ln1g + l * DIM, ln1b + l * DIM, h);

        launch_gemm(0, h, wqkv, nullptr, nullptr, qkv, NTOK, QKVD, DIM);

        attn_kernel<<<dim3(SEQ / 64, NH, NB), 64>>>(qkv, y);

        launch_gemm(3, y, wo, bo + l * DIM, x, x, NTOK, DIM, DIM);

        ln_kernel<<<NTOK, 256>>>(x, ln2g + l * DIM, ln2b + l * DIM, h);

        launch_gemm(2, h, w1, b1 + (size_t)l * FFD, nullptr, ff, NTOK, FFD, DIM);
        launch_gemm(3, ff, w2, b2 + l * DIM, x, x, NTOK, DIM, FFD);
    }

    ln_kernel<<<NTOK, 256>>>(x, lnfg, lnfb, h);
    launch_gemm(1, h, Wlm, blm, nullptr, out, NTOK, VOCAB, DIM);
}

// round 6
// speedup vs baseline: 2.2469x; 1.0312x over previous
#include <cuda_runtime.h>
#include <cuda_bf16.h>

// ---------------- problem dims ----------------
#define NB     2
#define SEQ    1024
#define DIM    1024
#define NH     16
#define NKV    4
#define HSZ    64
#define NLAYER 6
#define VOCAB  32000
#define FFD    4096
#define NTOK   (NB*SEQ)          // 2048
#define KVD    (NKV*HSZ)         // 256
#define QKVD   (DIM + 2*KVD)     // 1536

typedef __nv_bfloat16 bf16;

// ---------------- scratch (256B-aligned) ----------------
__device__ __align__(256) float g_x  [NTOK*DIM];
__device__ __align__(256) float g_qkv[NTOK*QKVD];
__device__ __align__(256) bf16 g_h_hi [NTOK*DIM];
__device__ __align__(256) bf16 g_h_lo [NTOK*DIM];
__device__ __align__(256) bf16 g_y_hi [NTOK*DIM];
__device__ __align__(256) bf16 g_y_lo [NTOK*DIM];
__device__ __align__(256) bf16 g_ff_hi[NTOK*FFD];
__device__ __align__(256) bf16 g_ff_lo[NTOK*FFD];
__device__ __align__(256) bf16 g_wqkv_hi[NLAYER*DIM*QKVD];
__device__ __align__(256) bf16 g_wqkv_lo[NLAYER*DIM*QKVD];
__device__ __align__(256) bf16 g_wo_hi  [NLAYER*DIM*DIM];
__device__ __align__(256) bf16 g_wo_lo  [NLAYER*DIM*DIM];
__device__ __align__(256) bf16 g_w1_hi  [NLAYER*DIM*FFD];
__device__ __align__(256) bf16 g_w1_lo  [NLAYER*DIM*FFD];
__device__ __align__(256) bf16 g_w2_hi  [NLAYER*FFD*DIM];
__device__ __align__(256) bf16 g_w2_lo  [NLAYER*FFD*DIM];
__device__ __align__(256) bf16 g_wlm_hi [DIM*VOCAB];
__device__ __align__(256) bf16 g_wlm_lo [DIM*VOCAB];

// ---------------- helpers ----------------
__device__ __forceinline__ unsigned packbf2(float a, float b) {
    __nv_bfloat162 t = __floats2bfloat162_rn(a, b);
    return *(unsigned*)&t;
}
__device__ __forceinline__ void split2(float a, float b, unsigned& hi, unsigned& lo) {
    bf16 ha = __float2bfloat16(a), hb = __float2bfloat16(b);
    float la = a - __bfloat162float(ha);
    float lb = b - __bfloat162float(hb);
    __nv_bfloat162 h2 = __halves2bfloat162(ha, hb);
    hi = *(unsigned*)&h2;
    lo = packbf2(la, lb);
}

// ---------------- embedding ----------------
__global__ void embed_kernel(const int* __restrict__ tok, const float* __restrict__ te,
                             const float* __restrict__ pe, float* __restrict__ x) {
    int idx = blockIdx.x * 256 + threadIdx.x;
    int row = idx >> 10;
    int d   = idx & (DIM - 1);
    int t   = row & (SEQ - 1);
    x[idx] = te[(size_t)tok[row] * DIM + d] + pe[t * DIM + d];
}

// ---------------- split fp32 -> bf16 hi/lo (bulk, float4) ----------------
__global__ void split_kernel(const float* __restrict__ src, bf16* __restrict__ hi,
                             bf16* __restrict__ lo, int n4) {
    int i = blockIdx.x * 256 + threadIdx.x;
    if (i >= n4) return;
    float4 v = ((const float4*)src)[i];
    uint2 ph, pl;
    split2(v.x, v.y, ph.x, pl.x);
    split2(v.z, v.w, ph.y, pl.y);
    ((uint2*)hi)[i] = ph;
    ((uint2*)lo)[i] = pl;
}

// ---------------- concat Wq|Wk|Wv (all layers) + split ----------------
__global__ void concat_split_qkv(const float* __restrict__ Wq, const float* __restrict__ Wk,
                                 const float* __restrict__ Wv,
                                 bf16* __restrict__ hi, bf16* __restrict__ lo) {
    int idx4 = blockIdx.x * 256 + threadIdx.x;
    if (idx4 >= NLAYER * DIM * (QKVD / 4)) return;
    int l   = idx4 / (DIM * (QKVD / 4));
    int r   = idx4 % (DIM * (QKVD / 4));
    int row = r / (QKVD / 4);
    int col = (r % (QKVD / 4)) * 4;
    float4 v;
    if (col < DIM)            v = *(const float4*)(Wq + ((size_t)l * DIM + row) * DIM + col);
    else if (col < DIM + KVD) v = *(const float4*)(Wk + ((size_t)l * DIM + row) * KVD + (col - DIM));
    else                      v = *(const float4*)(Wv + ((size_t)l * DIM + row) * KVD + (col - DIM - KVD));
    uint2 ph, pl;
    split2(v.x, v.y, ph.x, pl.x);
    split2(v.z, v.w, ph.y, pl.y);
    size_t o = ((size_t)l * DIM + row) * QKVD + col;
    *(uint2*)(hi + o) = ph;
    *(uint2*)(lo + o) = pl;
}

// ---------------- layernorm -> split bf16 hi/lo ----------------
__global__ __launch_bounds__(256) void ln_kernel(const float* __restrict__ x,
                                                 const float* __restrict__ g,
                                                 const float* __restrict__ b,
                                                 bf16* __restrict__ yhi,
                                                 bf16* __restrict__ ylo) {
    int row = blockIdx.x;
    int tid = threadIdx.x;
    const float* xr = x + (size_t)row * DIM;
    float4 v = *(const float4*)(xr + tid * 4);
    float sum = v.x + v.y + v.z + v.w;
    float sq  = v.x*v.x + v.y*v.y + v.z*v.z + v.w*v.w;
    #pragma unroll
    for (int o = 16; o > 0; o >>= 1) {
        sum += __shfl_xor_sync(0xffffffffu, sum, o);
        sq  += __shfl_xor_sync(0xffffffffu, sq,  o);
    }
    __shared__ float sh[18];
    int wid = tid >> 5, lane = tid & 31;
    if (lane == 0) { sh[wid] = sum; sh[8 + wid] = sq; }
    __syncthreads();
    if (tid == 0) {
        float a = 0.f, c = 0.f;
        #pragma unroll
        for (int w = 0; w < 8; w++) { a += sh[w]; c += sh[8 + w]; }
        float mu  = a * (1.0f / DIM);
        float var = c * (1.0f / DIM) - mu * mu;
        sh[16] = mu;
        sh[17] = rsqrtf(var + 1e-5f);
    }
    __syncthreads();
    float mu = sh[16], rstd = sh[17];
    float4 gg = *(const float4*)(g + tid * 4);
    float4 bb = *(const float4*)(b + tid * 4);
    float o0 = (v.x - mu) * rstd * gg.x + bb.x;
    float o1 = (v.y - mu) * rstd * gg.y + bb.y;
    float o2 = (v.z - mu) * rstd * gg.z + bb.z;
    float o3 = (v.w - mu) * rstd * gg.w + bb.w;
    uint2 ph, pl;
    split2(o0, o1, ph.x, pl.x);
    split2(o2, o3, ph.y, pl.y);
    *(uint2*)(yhi + (size_t)row * DIM + tid * 4) = ph;
    *(uint2*)(ylo + (size_t)row * DIM + tid * 4) = pl;
}

// =====================================================================
// bf16 split-GEMM — round-3 skeleton (256 thr, reg-staged loads,
// double-buffered smem, ldmatrix + mma), pre-split bf16 operands.
// C = (Ah+Al)(MxK) @ (Bh+Bl)(KxN), acc = AhBh + AhBl + AlBh (fp32).
// EPI: 0 plain, 1 +bias, 3 +bias+res, 4 +bias+relu -> bf16 hi/lo
// =====================================================================
#define BK    32
#define SPADA 40
#define SPADB 136

__device__ __forceinline__ void mma16816(float* c, const unsigned* a, const unsigned* b) {
    asm volatile(
        "mma.sync.aligned.m16n8k16.row.col.f32.bf16.bf16.f32 "
        "{%0,%1,%2,%3}, {%4,%5,%6,%7}, {%8,%9}, {%0,%1,%2,%3};\n"
        : "+f"(c[0]), "+f"(c[1]), "+f"(c[2]), "+f"(c[3])
        : "r"(a[0]), "r"(a[1]), "r"(a[2]), "r"(a[3]), "r"(b[0]), "r"(b[1]));
}
__device__ __forceinline__ void ldsm4(unsigned* r, unsigned addr) {
    asm volatile("ldmatrix.sync.aligned.m8n8.x4.shared.b16 {%0,%1,%2,%3}, [%4];\n"
                 : "=r"(r[0]), "=r"(r[1]), "=r"(r[2]), "=r"(r[3]) : "r"(addr));
}
__device__ __forceinline__ void ldsm4t(unsigned* r, unsigned addr) {
    asm volatile("ldmatrix.sync.aligned.m8n8.x4.trans.shared.b16 {%0,%1,%2,%3}, [%4];\n"
                 : "=r"(r[0]), "=r"(r[1]), "=r"(r[2]), "=r"(r[3]) : "r"(addr));
}

template <int EPI>
__global__ __launch_bounds__(256, 1) void gemm_bf(const bf16* __restrict__ Ah_g,
                                                  const bf16* __restrict__ Al_g,
                                                  const bf16* __restrict__ Bh_g,
                                                  const bf16* __restrict__ Bl_g,
                                                  const float* __restrict__ bias,
                                                  const float* __restrict__ res,
                                                  float* __restrict__ C,
                                                  bf16* __restrict__ Chi,
                                                  bf16* __restrict__ Clo,
                                                  int M, int N, int K) {
    __shared__ bf16 Ah[2][128][SPADA], Al[2][128][SPADA];
    __shared__ bf16 Bh[2][BK][SPADB],  Bl[2][BK][SPADB];

    int tid = threadIdx.x;
    int bm = blockIdx.y * 128, bn = blockIdx.x * 128;
    int wid = tid >> 5, lane = tid & 31;
    int wm = (wid & 1) * 64;
    int wn = (wid >> 1) * 32;
    int g  = lane >> 2, tg = lane & 3;

    // fill indices: A tile 128x32, B tile 32x128; 4 elems per thread per iter
    int aR[4], aC[4], bK_[4], bNc[4];
    #pragma unroll
    for (int i = 0; i < 4; i++) {
        int idx = tid + i * 256;
        aR[i]  = idx >> 3;  aC[i]  = (idx & 7) * 4;
        bK_[i] = idx >> 5;  bNc[i] = (idx & 31) * 4;
    }

    // ldmatrix lane addressing (round-3 identical)
    int a_row_l  = wm + (lane & 15);
    int a_col_l  = (lane >> 4) * 8;
    int b_krow_l = lane & 15;
    int b_ncol_l = wn + (lane >> 4) * 8;

    unsigned baseAh[2], baseAl[2], baseBh[2], baseBl[2];
    #pragma unroll
    for (int s = 0; s < 2; s++) {
        baseAh[s] = (unsigned)__cvta_generic_to_shared(&Ah[s][0][0]);
        baseAl[s] = (unsigned)__cvta_generic_to_shared(&Al[s][0][0]);
        baseBh[s] = (unsigned)__cvta_generic_to_shared(&Bh[s][0][0]);
        baseBl[s] = (unsigned)__cvta_generic_to_shared(&Bl[s][0][0]);
    }

    uint2 aRh[4], aRl[4], bRh[4], bRl[4];
    #pragma unroll
    for (int i = 0; i < 4; i++) {
        size_t ao = (size_t)(bm + aR[i]) * K + aC[i];
        size_t bo = (size_t)bK_[i] * N + bn + bNc[i];
        aRh[i] = *(const uint2*)(Ah_g + ao);
        aRl[i] = *(const uint2*)(Al_g + ao);
        bRh[i] = *(const uint2*)(Bh_g + bo);
        bRl[i] = *(const uint2*)(Bl_g + bo);
    }

    float acc[4][4][4];
    #pragma unroll
    for (int a = 0; a < 4; a++)
        #pragma unroll
        for (int b = 0; b < 4; b++)
            #pragma unroll
            for (int c = 0; c < 4; c++) acc[a][b][c] = 0.f;

    auto store_stage = [&](int s) {
        #pragma unroll
        for (int i = 0; i < 4; i++) {
            *(uint2*)&Ah[s][aR[i]][aC[i]]   = aRh[i];
            *(uint2*)&Al[s][aR[i]][aC[i]]   = aRl[i];
            *(uint2*)&Bh[s][bK_[i]][bNc[i]] = bRh[i];
            *(uint2*)&Bl[s][bK_[i]][bNc[i]] = bRl[i];
        }
    };

    auto compute = [&](int s) {
        #pragma unroll
        for (int kk = 0; kk < BK; kk += 16) {
            unsigned afh[4][4], afl[4][4];
            #pragma unroll
            for (int mt = 0; mt < 4; mt++) {
                unsigned off = ((a_row_l + mt * 16) * SPADA + a_col_l + kk) * 2;
                ldsm4(afh[mt], baseAh[s] + off);
                ldsm4(afl[mt], baseAl[s] + off);
            }
            unsigned bfh[2][4], bfl[2][4];
            #pragma unroll
            for (int p = 0; p < 2; p++) {
                unsigned off = ((kk + b_krow_l) * SPADB + b_ncol_l + p * 16) * 2;
                ldsm4t(bfh[p], baseBh[s] + off);
                ldsm4t(bfl[p], baseBl[s] + off);
            }
            #pragma unroll
            for (int mt = 0; mt < 4; mt++) {
                #pragma unroll
                for (int nt = 0; nt < 4; nt++) {
                    unsigned* bh2 = &bfh[nt >> 1][(nt & 1) * 2];
                    unsigned* bl2 = &bfl[nt >> 1][(nt & 1) * 2];
                    mma16816(acc[mt][nt], afh[mt], bh2);
                    mma16816(acc[mt][nt], afh[mt], bl2);
                    mma16816(acc[mt][nt], afl[mt], bh2);
                }
            }
        }
    };

    store_stage(0);
    __syncthreads();
    int stage = 0;
    for (int k0 = BK; k0 <= K; k0 += BK) {
        bool more = (k0 < K);
        if (more) {
            #pragma unroll
            for (int i = 0; i < 4; i++) {
                size_t ao = (size_t)(bm + aR[i]) * K + k0 + aC[i];
                size_t bo = (size_t)(k0 + bK_[i]) * N + bn + bNc[i];
                aRh[i] = *(const uint2*)(Ah_g + ao);
                aRl[i] = *(const uint2*)(Al_g + ao);
                bRh[i] = *(const uint2*)(Bh_g + bo);
                bRl[i] = *(const uint2*)(Bl_g + bo);
            }
        }
        compute(stage);
        if (more) store_stage(stage ^ 1);
        __syncthreads();
        stage ^= 1;
    }

    // epilogue
    #pragma unroll
    for (int mt = 0; mt < 4; mt++) {
        #pragma unroll
        for (int nt = 0; nt < 4; nt++) {
            int row = bm + wm + mt * 16 + g;
            int col = bn + wn + nt * 8 + tg * 2;
            float2 o0 = make_float2(acc[mt][nt][0], acc[mt][nt][1]);
            float2 o1 = make_float2(acc[mt][nt][2], acc[mt][nt][3]);
            if (EPI >= 1) {
                float2 bb = *(const float2*)(bias + col);
                o0.x += bb.x; o0.y += bb.y; o1.x += bb.x; o1.y += bb.y;
            }
            if (EPI == 3) {
                float2 r0 = *(const float2*)(res + (size_t)row * N + col);
                float2 r1 = *(const float2*)(res + (size_t)(row + 8) * N + col);
                o0.x += r0.x; o0.y += r0.y; o1.x += r1.x; o1.y += r1.y;
            }
            if (EPI == 4) {
                o0.x = fmaxf(o0.x, 0.f); o0.y = fmaxf(o0.y, 0.f);
                o1.x = fmaxf(o1.x, 0.f); o1.y = fmaxf(o1.y, 0.f);
                unsigned h0, l0, h1, l1;
                split2(o0.x, o0.y, h0, l0);
                split2(o1.x, o1.y, h1, l1);
                *(unsigned*)(Chi + (size_t)row * N + col)       = h0;
                *(unsigned*)(Clo + (size_t)row * N + col)       = l0;
                *(unsigned*)(Chi + (size_t)(row + 8) * N + col) = h1;
                *(unsigned*)(Clo + (size_t)(row + 8) * N + col) = l1;
            } else {
                *(float2*)(C + (size_t)row * N + col) = o0;
                *(float2*)(C + (size_t)(row + 8) * N + col) = o1;
            }
        }
    }
}

// ---------------- fused causal GQA attention (fp32 in, bf16-split out) ----------------
__global__ __launch_bounds__(64) void attn_kernel(const float* __restrict__ QKV,
                                                  bf16* __restrict__ Yhi,
                                                  bf16* __restrict__ Ylo) {
    __shared__ __align__(16) float ks[64][64];
    __shared__ __align__(16) float vs[64][64];
    __shared__ float ss[64][65];

    int itile = blockIdx.x;
    int h     = blockIdx.y;
    int b     = blockIdx.z;
    int kvh   = h >> 2;
    int tid   = threadIdx.x;
    int i     = itile * 64 + tid;

    const float scale = 0.125f;
    float q[64], o[64];
    const float* qrow = QKV + ((size_t)(b * SEQ + i)) * QKVD + h * HSZ;
    #pragma unroll
    for (int d = 0; d < 64; d += 4) {
        float4 t = *(const float4*)(qrow + d);
        q[d] = t.x * scale; q[d+1] = t.y * scale; q[d+2] = t.z * scale; q[d+3] = t.w * scale;
    }
    #pragma unroll
    for (int d = 0; d < 64; d++) o[d] = 0.f;
    float m = -1e30f, l = 0.f;

    for (int j0 = 0; j0 <= itile * 64; j0 += 64) {
        const float* krow = QKV + ((size_t)(b * SEQ + j0 + tid)) * QKVD + DIM + kvh * HSZ;
        const float* vrow = krow + KVD;
        #pragma unroll
        for (int d = 0; d < 64; d += 4) {
            *(float4*)&ks[tid][d] = *(const float4*)(krow + d);
            *(float4*)&vs[tid][d] = *(const float4*)(vrow + d);
        }
        __syncthreads();

        float mt = m;
        #pragma unroll 4
        for (int j = 0; j < 64; j++) {
            float acc = 0.f;
            #pragma unroll
            for (int d = 0; d < 64; d += 4) {
                float4 kk = *(const float4*)&ks[j][d];
                acc = fmaf(q[d],   kk.x, acc);
                acc = fmaf(q[d+1], kk.y, acc);
                acc = fmaf(q[d+2], kk.z, acc);
                acc = fmaf(q[d+3], kk.w, acc);
            }
            if (j0 + j > i) acc = -1e30f;
            ss[tid][j] = acc;
            mt = fmaxf(mt, acc);
        }

        float corr = __expf(m - mt);
        l *= corr;
        #pragma unroll
        for (int d = 0; d < 64; d++) o[d] *= corr;

        #pragma unroll 2
        for (int j = 0; j < 64; j++) {
            float p = __expf(ss[tid][j] - mt);
            l += p;
            #pragma unroll
            for (int d = 0; d < 64; d += 4) {
                float4 vv = *(const float4*)&vs[j][d];
                o[d]   = fmaf(p, vv.x, o[d]);
                o[d+1] = fmaf(p, vv.y, o[d+1]);
                o[d+2] = fmaf(p, vv.z, o[d+2]);
                o[d+3] = fmaf(p, vv.w, o[d+3]);
            }
        }
        m = mt;
        __syncthreads();
    }

    float inv = 1.0f / l;
    size_t yo = ((size_t)(b * SEQ + i)) * DIM + h * HSZ;
    #pragma unroll
    for (int d = 0; d < 64; d += 4) {
        uint2 ph, pl;
        split2(o[d] * inv,   o[d+1] * inv, ph.x, pl.x);
        split2(o[d+2] * inv, o[d+3] * inv, ph.y, pl.y);
        *(uint2*)(Yhi + yo + d) = ph;
        *(uint2*)(Ylo + yo + d) = pl;
    }
}

// ---------------- host ----------------
template <typename Tp>
static void* sym_addr(Tp& s) {
    void* p = nullptr;
    cudaGetSymbolAddress(&p, s);
    return p;
}

static void launch_gemm(int epi, const bf16* Ah, const bf16* Al,
                        const bf16* Bh, const bf16* Bl,
                        const float* bias, const float* res,
                        float* C, bf16* Chi, bf16* Clo, int M, int N, int K) {
    dim3 grid(N / 128, M / 128);
    switch (epi) {
        case 0: gemm_bf<0><<<grid, 256>>>(Ah, Al, Bh, Bl, bias, res, C, Chi, Clo, M, N, K); break;
        case 1: gemm_bf<1><<<grid, 256>>>(Ah, Al, Bh, Bl, bias, res, C, Chi, Clo, M, N, K); break;
        case 3: gemm_bf<3><<<grid, 256>>>(Ah, Al, Bh, Bl, bias, res, C, Chi, Clo, M, N, K); break;
        case 4: gemm_bf<4><<<grid, 256>>>(Ah, Al, Bh, Bl, bias, res, C, Chi, Clo, M, N, K); break;
    }
}

extern "C" void kernel_launch(void* const* d_in, const int* in_sizes, int n_in,
                              void* d_out, int out_size) {
    const int*   tok   = (const int*)  d_in[0];
    const float* te    = (const float*)d_in[1];
    const float* pe    = (const float*)d_in[2];
    const float* ln1g  = (const float*)d_in[3];
    const float* ln1b  = (const float*)d_in[4];
    const float* Wq    = (const float*)d_in[5];
    const float* Wk    = (const float*)d_in[6];
    const float* Wv    = (const float*)d_in[7];
    const float* Wo    = (const float*)d_in[8];
    const float* bo    = (const float*)d_in[9];
    const float* ln2g  = (const float*)d_in[10];
    const float* ln2b  = (const float*)d_in[11];
    const float* W1    = (const float*)d_in[12];
    const float* b1    = (const float*)d_in[13];
    const float* W2    = (const float*)d_in[14];
    const float* b2    = (const float*)d_in[15];
    const float* lnfg  = (const float*)d_in[16];
    const float* lnfb  = (const float*)d_in[17];
    const float* Wlm   = (const float*)d_in[18];
    const float* blm   = (const float*)d_in[19];
    float* out = (float*)d_out;

    float* x    = (float*)sym_addr(g_x);
    float* qkv  = (float*)sym_addr(g_qkv);
    bf16* h_hi  = (bf16*)sym_addr(g_h_hi),  * h_lo  = (bf16*)sym_addr(g_h_lo);
    bf16* y_hi  = (bf16*)sym_addr(g_y_hi),  * y_lo  = (bf16*)sym_addr(g_y_lo);
    bf16* ff_hi = (bf16*)sym_addr(g_ff_hi), * ff_lo = (bf16*)sym_addr(g_ff_lo);
    bf16* wqkv_hi = (bf16*)sym_addr(g_wqkv_hi), * wqkv_lo = (bf16*)sym_addr(g_wqkv_lo);
    bf16* wo_hi   = (bf16*)sym_addr(g_wo_hi),   * wo_lo   = (bf16*)sym_addr(g_wo_lo);
    bf16* w1_hi   = (bf16*)sym_addr(g_w1_hi),   * w1_lo   = (bf16*)sym_addr(g_w1_lo);
    bf16* w2_hi   = (bf16*)sym_addr(g_w2_hi),   * w2_lo   = (bf16*)sym_addr(g_w2_lo);
    bf16* wlm_hi  = (bf16*)sym_addr(g_wlm_hi),  * wlm_lo  = (bf16*)sym_addr(g_wlm_lo);

    // --- weight pre-split (once per pass) ---
    {
        int n4;
        n4 = NLAYER * DIM * (QKVD / 4);
        concat_split_qkv<<<(n4 + 255) / 256, 256>>>(Wq, Wk, Wv, wqkv_hi, wqkv_lo);
        n4 = NLAYER * DIM * DIM / 4;
        split_kernel<<<(n4 + 255) / 256, 256>>>(Wo, wo_hi, wo_lo, n4);
        n4 = NLAYER * DIM * FFD / 4;
        split_kernel<<<(n4 + 255) / 256, 256>>>(W1, w1_hi, w1_lo, n4);
        n4 = NLAYER * FFD * DIM / 4;
        split_kernel<<<(n4 + 255) / 256, 256>>>(W2, w2_hi, w2_lo, n4);
        n4 = DIM * VOCAB / 4;
        split_kernel<<<(n4 + 255) / 256, 256>>>(Wlm, wlm_hi, wlm_lo, n4);
    }

    embed_kernel<<<NTOK * DIM / 256, 256>>>(tok, te, pe, x);

    for (int l = 0; l < NLAYER; l++) {
        const bf16* wqh = wqkv_hi + (size_t)l * DIM * QKVD;
        const bf16* wql = wqkv_lo + (size_t)l * DIM * QKVD;
        const bf16* woh = wo_hi   + (size_t)l * DIM * DIM;
        const bf16* wol = wo_lo   + (size_t)l * DIM * DIM;
        const bf16* w1h = w1_hi   + (size_t)l * DIM * FFD;
        const bf16* w1l = w1_lo   + (size_t)l * DIM * FFD;
        const bf16* w2h = w2_hi   + (size_t)l * FFD * DIM;
        const bf16* w2l = w2_lo   + (size_t)l * FFD * DIM;

        ln_kernel<<<NTOK, 256>>>(x, ln1g + l * DIM, ln1b + l * DIM, h_hi, h_lo);

        launch_gemm(0, h_hi, h_lo, wqh, wql, nullptr, nullptr, qkv, nullptr, nullptr,
                    NTOK, QKVD, DIM);

        attn_kernel<<<dim3(SEQ / 64, NH, NB), 64>>>(qkv, y_hi, y_lo);

        launch_gemm(3, y_hi, y_lo, woh, wol, bo + l * DIM, x, x, nullptr, nullptr,
                    NTOK, DIM, DIM);

        ln_kernel<<<NTOK, 256>>>(x, ln2g + l * DIM, ln2b + l * DIM, h_hi, h_lo);

        launch_gemm(4, h_hi, h_lo, w1h, w1l, b1 + (size_t)l * FFD, nullptr,
                    nullptr, ff_hi, ff_lo, NTOK, FFD, DIM);
        launch_gemm(3, ff_hi, ff_lo, w2h, w2l, b2 + l * DIM, x, x, nullptr, nullptr,
                    NTOK, DIM, FFD);
    }

    ln_kernel<<<NTOK, 256>>>(x, lnfg, lnfb, h_hi, h_lo);
    launch_gemm(1, h_hi, h_lo, wlm_hi, wlm_lo, blm, nullptr, out, nullptr, nullptr,
                NTOK, VOCAB, DIM);
}

// round 8
// speedup vs baseline: 2.3090x; 1.0276x over previous
#include <cuda_runtime.h>
#include <cuda_bf16.h>

// ---------------- problem dims ----------------
#define NB     2
#define SEQ    1024
#define DIM    1024
#define NH     16
#define NKV    4
#define HSZ    64
#define NLAYER 6
#define VOCAB  32000
#define FFD    4096
#define NTOK   (NB*SEQ)          // 2048
#define KVD    (NKV*HSZ)         // 256
#define QKVD   (DIM + 2*KVD)     // 1536

typedef __nv_bfloat16 bf16;

// ---------------- scratch (256B-aligned) ----------------
__device__ __align__(256) float g_x  [NTOK*DIM];
__device__ __align__(256) float g_qkv[NTOK*QKVD];
__device__ __align__(256) bf16 g_h_hi [NTOK*DIM];
__device__ __align__(256) bf16 g_h_lo [NTOK*DIM];
__device__ __align__(256) bf16 g_y_hi [NTOK*DIM];
__device__ __align__(256) bf16 g_y_lo [NTOK*DIM];
__device__ __align__(256) bf16 g_ff_hi[NTOK*FFD];
__device__ __align__(256) bf16 g_ff_lo[NTOK*FFD];
__device__ __align__(256) bf16 g_wqkv_hi[NLAYER*DIM*QKVD];
__device__ __align__(256) bf16 g_wqkv_lo[NLAYER*DIM*QKVD];
__device__ __align__(256) bf16 g_wo_hi  [NLAYER*DIM*DIM];
__device__ __align__(256) bf16 g_wo_lo  [NLAYER*DIM*DIM];
__device__ __align__(256) bf16 g_w1_hi  [NLAYER*DIM*FFD];
__device__ __align__(256) bf16 g_w1_lo  [NLAYER*DIM*FFD];
__device__ __align__(256) bf16 g_w2_hi  [NLAYER*FFD*DIM];
__device__ __align__(256) bf16 g_w2_lo  [NLAYER*FFD*DIM];
__device__ __align__(256) bf16 g_wlm_hi [DIM*VOCAB];
__device__ __align__(256) bf16 g_wlm_lo [DIM*VOCAB];

// ---------------- helpers ----------------
__device__ __forceinline__ unsigned packbf2(float a, float b) {
    __nv_bfloat162 t = __floats2bfloat162_rn(a, b);
    return *(unsigned*)&t;
}
__device__ __forceinline__ void split2(float a, float b, unsigned& hi, unsigned& lo) {
    bf16 ha = __float2bfloat16(a), hb = __float2bfloat16(b);
    float la = a - __bfloat162float(ha);
    float lb = b - __bfloat162float(hb);
    __nv_bfloat162 h2 = __halves2bfloat162(ha, hb);
    hi = *(unsigned*)&h2;
    lo = packbf2(la, lb);
}

// ---------------- embedding ----------------
__global__ void embed_kernel(const int* __restrict__ tok, const float* __restrict__ te,
                             const float* __restrict__ pe, float* __restrict__ x) {
    int idx = blockIdx.x * 256 + threadIdx.x;
    int row = idx >> 10;
    int d   = idx & (DIM - 1);
    int t   = row & (SEQ - 1);
    x[idx] = te[(size_t)tok[row] * DIM + d] + pe[t * DIM + d];
}

// ---------------- split fp32 -> bf16 hi/lo (bulk, float4) ----------------
__global__ void split_kernel(const float* __restrict__ src, bf16* __restrict__ hi,
                             bf16* __restrict__ lo, int n4) {
    int i = blockIdx.x * 256 + threadIdx.x;
    if (i >= n4) return;
    float4 v = ((const float4*)src)[i];
    uint2 ph, pl;
    split2(v.x, v.y, ph.x, pl.x);
    split2(v.z, v.w, ph.y, pl.y);
    ((uint2*)hi)[i] = ph;
    ((uint2*)lo)[i] = pl;
}

// ---------------- concat Wq|Wk|Wv (all layers) + split ----------------
__global__ void concat_split_qkv(const float* __restrict__ Wq, const float* __restrict__ Wk,
                                 const float* __restrict__ Wv,
                                 bf16* __restrict__ hi, bf16* __restrict__ lo) {
    int idx4 = blockIdx.x * 256 + threadIdx.x;
    if (idx4 >= NLAYER * DIM * (QKVD / 4)) return;
    int l   = idx4 / (DIM * (QKVD / 4));
    int r   = idx4 % (DIM * (QKVD / 4));
    int row = r / (QKVD / 4);
    int col = (r % (QKVD / 4)) * 4;
    float4 v;
    if (col < DIM)            v = *(const float4*)(Wq + ((size_t)l * DIM + row) * DIM + col);
    else if (col < DIM + KVD) v = *(const float4*)(Wk + ((size_t)l * DIM + row) * KVD + (col - DIM));
    else                      v = *(const float4*)(Wv + ((size_t)l * DIM + row) * KVD + (col - DIM - KVD));
    uint2 ph, pl;
    split2(v.x, v.y, ph.x, pl.x);
    split2(v.z, v.w, ph.y, pl.y);
    size_t o = ((size_t)l * DIM + row) * QKVD + col;
    *(uint2*)(hi + o) = ph;
    *(uint2*)(lo + o) = pl;
}

// ---------------- layernorm -> split bf16 hi/lo ----------------
__global__ __launch_bounds__(256) void ln_kernel(const float* __restrict__ x,
                                                 const float* __restrict__ g,
                                                 const float* __restrict__ b,
                                                 bf16* __restrict__ yhi,
                                                 bf16* __restrict__ ylo) {
    int row = blockIdx.x;
    int tid = threadIdx.x;
    const float* xr = x + (size_t)row * DIM;
    float4 v = *(const float4*)(xr + tid * 4);
    float sum = v.x + v.y + v.z + v.w;
    float sq  = v.x*v.x + v.y*v.y + v.z*v.z + v.w*v.w;
    #pragma unroll
    for (int o = 16; o > 0; o >>= 1) {
        sum += __shfl_xor_sync(0xffffffffu, sum, o);
        sq  += __shfl_xor_sync(0xffffffffu, sq,  o);
    }
    __shared__ float sh[18];
    int wid = tid >> 5, lane = tid & 31;
    if (lane == 0) { sh[wid] = sum; sh[8 + wid] = sq; }
    __syncthreads();
    if (tid == 0) {
        float a = 0.f, c = 0.f;
        #pragma unroll
        for (int w = 0; w < 8; w++) { a += sh[w]; c += sh[8 + w]; }
        float mu  = a * (1.0f / DIM);
        float var = c * (1.0f / DIM) - mu * mu;
        sh[16] = mu;
        sh[17] = rsqrtf(var + 1e-5f);
    }
    __syncthreads();
    float mu = sh[16], rstd = sh[17];
    float4 gg = *(const float4*)(g + tid * 4);
    float4 bb = *(const float4*)(b + tid * 4);
    float o0 = (v.x - mu) * rstd * gg.x + bb.x;
    float o1 = (v.y - mu) * rstd * gg.y + bb.y;
    float o2 = (v.z - mu) * rstd * gg.z + bb.z;
    float o3 = (v.w - mu) * rstd * gg.w + bb.w;
    uint2 ph, pl;
    split2(o0, o1, ph.x, pl.x);
    split2(o2, o3, ph.y, pl.y);
    *(uint2*)(yhi + (size_t)row * DIM + tid * 4) = ph;
    *(uint2*)(ylo + (size_t)row * DIM + tid * 4) = pl;
}

// =====================================================================
// bf16 split-GEMM — 512 threads / 16 warps (4M x 4N, 32x32 warp tiles),
// register-staged uint2 loads (round-6 proven), double-buffered smem,
// ldmatrix + mma.  C = (Ah+Al)(MxK) @ (Bh+Bl)(KxN), 3-term fp32 acc.
// EPI: 0 plain, 1 +bias, 3 +bias+res, 4 +bias+relu -> bf16 hi/lo
// =====================================================================
#define BK    32
#define SPADA 40
#define SPADB 136

__device__ __forceinline__ void mma16816(float* c, const unsigned* a, const unsigned* b) {
    asm volatile(
        "mma.sync.aligned.m16n8k16.row.col.f32.bf16.bf16.f32 "
        "{%0,%1,%2,%3}, {%4,%5,%6,%7}, {%8,%9}, {%0,%1,%2,%3};\n"
        : "+f"(c[0]), "+f"(c[1]), "+f"(c[2]), "+f"(c[3])
        : "r"(a[0]), "r"(a[1]), "r"(a[2]), "r"(a[3]), "r"(b[0]), "r"(b[1]));
}
__device__ __forceinline__ void ldsm4(unsigned* r, unsigned addr) {
    asm volatile("ldmatrix.sync.aligned.m8n8.x4.shared.b16 {%0,%1,%2,%3}, [%4];\n"
                 : "=r"(r[0]), "=r"(r[1]), "=r"(r[2]), "=r"(r[3]) : "r"(addr));
}
__device__ __forceinline__ void ldsm4t(unsigned* r, unsigned addr) {
    asm volatile("ldmatrix.sync.aligned.m8n8.x4.trans.shared.b16 {%0,%1,%2,%3}, [%4];\n"
                 : "=r"(r[0]), "=r"(r[1]), "=r"(r[2]), "=r"(r[3]) : "r"(addr));
}

template <int EPI>
__global__ __launch_bounds__(512, 1) void gemm_bf(const bf16* __restrict__ Ah_g,
                                                  const bf16* __restrict__ Al_g,
                                                  const bf16* __restrict__ Bh_g,
                                                  const bf16* __restrict__ Bl_g,
                                                  const float* __restrict__ bias,
                                                  const float* __restrict__ res,
                                                  float* __restrict__ C,
                                                  bf16* __restrict__ Chi,
                                                  bf16* __restrict__ Clo,
                                                  int M, int N, int K) {
    __shared__ __align__(16) bf16 Ah[2][128][SPADA], Al[2][128][SPADA];
    __shared__ __align__(16) bf16 Bh[2][BK][SPADB],  Bl[2][BK][SPADB];

    int tid = threadIdx.x;
    int bm = blockIdx.y * 128, bn = blockIdx.x * 128;
    int wid = tid >> 5, lane = tid & 31;
    int wm = (wid & 3) * 32;           // 4 warps along M
    int wn = (wid >> 2) * 32;          // 4 warps along N
    int g  = lane >> 2, tg = lane & 3;

    // fill indices: A tile 128x32 (4096 elems), B tile 32x128 (4096 elems);
    // 512 threads * 2 iters * 4 elems
    int aR[2], aC[2], bK_[2], bNc[2];
    #pragma unroll
    for (int i = 0; i < 2; i++) {
        int idx = tid + i * 512;
        aR[i]  = idx >> 3;  aC[i]  = (idx & 7) * 4;
        bK_[i] = idx >> 5;  bNc[i] = (idx & 31) * 4;
    }

    // ldmatrix lane addressing
    int a_row_l  = wm + (lane & 15);
    int a_col_l  = (lane >> 4) * 8;
    int b_krow_l = lane & 15;
    int b_ncol_l = wn + (lane >> 4) * 8;

    unsigned baseAh[2], baseAl[2], baseBh[2], baseBl[2];
    #pragma unroll
    for (int s = 0; s < 2; s++) {
        baseAh[s] = (unsigned)__cvta_generic_to_shared(&Ah[s][0][0]);
        baseAl[s] = (unsigned)__cvta_generic_to_shared(&Al[s][0][0]);
        baseBh[s] = (unsigned)__cvta_generic_to_shared(&Bh[s][0][0]);
        baseBl[s] = (unsigned)__cvta_generic_to_shared(&Bl[s][0][0]);
    }

    uint2 aRh[2], aRl[2], bRh[2], bRl[2];
    #pragma unroll
    for (int i = 0; i < 2; i++) {
        size_t ao = (size_t)(bm + aR[i]) * K + aC[i];
        size_t bo = (size_t)bK_[i] * N + bn + bNc[i];
        aRh[i] = *(const uint2*)(Ah_g + ao);
        aRl[i] = *(const uint2*)(Al_g + ao);
        bRh[i] = *(const uint2*)(Bh_g + bo);
        bRl[i] = *(const uint2*)(Bl_g + bo);
    }

    float acc[2][4][4];
    #pragma unroll
    for (int a = 0; a < 2; a++)
        #pragma unroll
        for (int b = 0; b < 4; b++)
            #pragma unroll
            for (int c = 0; c < 4; c++) acc[a][b][c] = 0.f;

    auto store_stage = [&](int s) {
        #pragma unroll
        for (int i = 0; i < 2; i++) {
            *(uint2*)&Ah[s][aR[i]][aC[i]]   = aRh[i];
            *(uint2*)&Al[s][aR[i]][aC[i]]   = aRl[i];
            *(uint2*)&Bh[s][bK_[i]][bNc[i]] = bRh[i];
            *(uint2*)&Bl[s][bK_[i]][bNc[i]] = bRl[i];
        }
    };

    auto compute = [&](int s) {
        #pragma unroll
        for (int kk = 0; kk < BK; kk += 16) {
            unsigned afh[2][4], afl[2][4];
            #pragma unroll
            for (int mt = 0; mt < 2; mt++) {
                unsigned off = ((a_row_l + mt * 16) * SPADA + a_col_l + kk) * 2;
                ldsm4(afh[mt], baseAh[s] + off);
                ldsm4(afl[mt], baseAl[s] + off);
            }
            unsigned bfh[2][4], bfl[2][4];
            #pragma unroll
            for (int p = 0; p < 2; p++) {
                unsigned off = ((kk + b_krow_l) * SPADB + b_ncol_l + p * 16) * 2;
                ldsm4t(bfh[p], baseBh[s] + off);
                ldsm4t(bfl[p], baseBl[s] + off);
            }
            #pragma unroll
            for (int mt = 0; mt < 2; mt++) {
                #pragma unroll
                for (int nt = 0; nt < 4; nt++) {
                    unsigned* bh2 = &bfh[nt >> 1][(nt & 1) * 2];
                    unsigned* bl2 = &bfl[nt >> 1][(nt & 1) * 2];
                    mma16816(acc[mt][nt], afh[mt], bh2);
                    mma16816(acc[mt][nt], afh[mt], bl2);
                    mma16816(acc[mt][nt], afl[mt], bh2);
                }
            }
        }
    };

    store_stage(0);
    __syncthreads();
    int stage = 0;
    for (int k0 = BK; k0 <= K; k0 += BK) {
        bool more = (k0 < K);
        if (more) {
            #pragma unroll
            for (int i = 0; i < 2; i++) {
                size_t ao = (size_t)(bm + aR[i]) * K + k0 + aC[i];
                size_t bo = (size_t)(k0 + bK_[i]) * N + bn + bNc[i];
                aRh[i] = *(const uint2*)(Ah_g + ao);
                aRl[i] = *(const uint2*)(Al_g + ao);
                bRh[i] = *(const uint2*)(Bh_g + bo);
                bRl[i] = *(const uint2*)(Bl_g + bo);
            }
        }
        compute(stage);
        if (more) store_stage(stage ^ 1);
        __syncthreads();
        stage ^= 1;
    }

    // epilogue
    #pragma unroll
    for (int mt = 0; mt < 2; mt++) {
        #pragma unroll
        for (int nt = 0; nt < 4; nt++) {
            int row = bm + wm + mt * 16 + g;
            int col = bn + wn + nt * 8 + tg * 2;
            float2 o0 = make_float2(acc[mt][nt][0], acc[mt][nt][1]);
            float2 o1 = make_float2(acc[mt][nt][2], acc[mt][nt][3]);
            if (EPI >= 1) {
                float2 bb = *(const float2*)(bias + col);
                o0.x += bb.x; o0.y += bb.y; o1.x += bb.x; o1.y += bb.y;
            }
            if (EPI == 3) {
                float2 r0 = *(const float2*)(res + (size_t)row * N + col);
                float2 r1 = *(const float2*)(res + (size_t)(row + 8) * N + col);
                o0.x += r0.x; o0.y += r0.y; o1.x += r1.x; o1.y += r1.y;
            }
            if (EPI == 4) {
                o0.x = fmaxf(o0.x, 0.f); o0.y = fmaxf(o0.y, 0.f);
                o1.x = fmaxf(o1.x, 0.f); o1.y = fmaxf(o1.y, 0.f);
                unsigned h0, l0, h1, l1;
                split2(o0.x, o0.y, h0, l0);
                split2(o1.x, o1.y, h1, l1);
                *(unsigned*)(Chi + (size_t)row * N + col)       = h0;
                *(unsigned*)(Clo + (size_t)row * N + col)       = l0;
                *(unsigned*)(Chi + (size_t)(row + 8) * N + col) = h1;
                *(unsigned*)(Clo + (size_t)(row + 8) * N + col) = l1;
            } else {
                *(float2*)(C + (size_t)row * N + col) = o0;
                *(float2*)(C + (size_t)(row + 8) * N + col) = o1;
            }
        }
    }
}

// ---------------- fused causal GQA attention (fp32 in, bf16-split out) ----------------
__global__ __launch_bounds__(64) void attn_kernel(const float* __restrict__ QKV,
                                                  bf16* __restrict__ Yhi,
                                                  bf16* __restrict__ Ylo) {
    __shared__ __align__(16) float ks[64][64];
    __shared__ __align__(16) float vs[64][64];
    __shared__ float ss[64][65];

    int itile = blockIdx.x;
    int h     = blockIdx.y;
    int b     = blockIdx.z;
    int kvh   = h >> 2;
    int tid   = threadIdx.x;
    int i     = itile * 64 + tid;

    const float scale = 0.125f;
    float q[64], o[64];
    const float* qrow = QKV + ((size_t)(b * SEQ + i)) * QKVD + h * HSZ;
    #pragma unroll
    for (int d = 0; d < 64; d += 4) {
        float4 t = *(const float4*)(qrow + d);
        q[d] = t.x * scale; q[d+1] = t.y * scale; q[d+2] = t.z * scale; q[d+3] = t.w * scale;
    }
    #pragma unroll
    for (int d = 0; d < 64; d++) o[d] = 0.f;
    float m = -1e30f, l = 0.f;

    for (int j0 = 0; j0 <= itile * 64; j0 += 64) {
        const float* krow = QKV + ((size_t)(b * SEQ + j0 + tid)) * QKVD + DIM + kvh * HSZ;
        const float* vrow = krow + KVD;
        #pragma unroll
        for (int d = 0; d < 64; d += 4) {
            *(float4*)&ks[tid][d] = *(const float4*)(krow + d);
            *(float4*)&vs[tid][d] = *(const float4*)(vrow + d);
        }
        __syncthreads();

        float mt = m;
        #pragma unroll 4
        for (int j = 0; j < 64; j++) {
            float acc = 0.f;
            #pragma unroll
            for (int d = 0; d < 64; d += 4) {
                float4 kk = *(const float4*)&ks[j][d];
                acc = fmaf(q[d],   kk.x, acc);
                acc = fmaf(q[d+1], kk.y, acc);
                acc = fmaf(q[d+2], kk.z, acc);
                acc = fmaf(q[d+3], kk.w, acc);
            }
            if (j0 + j > i) acc = -1e30f;
            ss[tid][j] = acc;
            mt = fmaxf(mt, acc);
        }

        float corr = __expf(m - mt);
        l *= corr;
        #pragma unroll
        for (int d = 0; d < 64; d++) o[d] *= corr;

        #pragma unroll 2
        for (int j = 0; j < 64; j++) {
            float p = __expf(ss[tid][j] - mt);
            l += p;
            #pragma unroll
            for (int d = 0; d < 64; d += 4) {
                float4 vv = *(const float4*)&vs[j][d];
                o[d]   = fmaf(p, vv.x, o[d]);
                o[d+1] = fmaf(p, vv.y, o[d+1]);
                o[d+2] = fmaf(p, vv.z, o[d+2]);
                o[d+3] = fmaf(p, vv.w, o[d+3]);
            }
        }
        m = mt;
        __syncthreads();
    }

    float inv = 1.0f / l;
    size_t yo = ((size_t)(b * SEQ + i)) * DIM + h * HSZ;
    #pragma unroll
    for (int d = 0; d < 64; d += 4) {
        uint2 ph, pl;
        split2(o[d] * inv,   o[d+1] * inv, ph.x, pl.x);
        split2(o[d+2] * inv, o[d+3] * inv, ph.y, pl.y);
        *(uint2*)(Yhi + yo + d) = ph;
        *(uint2*)(Ylo + yo + d) = pl;
    }
}

// ---------------- host ----------------
template <typename Tp>
static void* sym_addr(Tp& s) {
    void* p = nullptr;
    cudaGetSymbolAddress(&p, s);
    return p;
}

static void launch_gemm(int epi, const bf16* Ah, const bf16* Al,
                        const bf16* Bh, const bf16* Bl,
                        const float* bias, const float* res,
                        float* C, bf16* Chi, bf16* Clo, int M, int N, int K) {
    dim3 grid(N / 128, M / 128);
    switch (epi) {
        case 0: gemm_bf<0><<<grid, 512>>>(Ah, Al, Bh, Bl, bias, res, C, Chi, Clo, M, N, K); break;
        case 1: gemm_bf<1><<<grid, 512>>>(Ah, Al, Bh, Bl, bias, res, C, Chi, Clo, M, N, K); break;
        case 3: gemm_bf<3><<<grid, 512>>>(Ah, Al, Bh, Bl, bias, res, C, Chi, Clo, M, N, K); break;
        case 4: gemm_bf<4><<<grid, 512>>>(Ah, Al, Bh, Bl, bias, res, C, Chi, Clo, M, N, K); break;
    }
}

extern "C" void kernel_launch(void* const* d_in, const int* in_sizes, int n_in,
                              void* d_out, int out_size) {
    const int*   tok   = (const int*)  d_in[0];
    const float* te    = (const float*)d_in[1];
    const float* pe    = (const float*)d_in[2];
    const float* ln1g  = (const float*)d_in[3];
    const float* ln1b  = (const float*)d_in[4];
    const float* Wq    = (const float*)d_in[5];
    const float* Wk    = (const float*)d_in[6];
    const float* Wv    = (const float*)d_in[7];
    const float* Wo    = (const float*)d_in[8];
    const float* bo    = (const float*)d_in[9];
    const float* ln2g  = (const float*)d_in[10];
    const float* ln2b  = (const float*)d_in[11];
    const float* W1    = (const float*)d_in[12];
    const float* b1    = (const float*)d_in[13];
    const float* W2    = (const float*)d_in[14];
    const float* b2    = (const float*)d_in[15];
    const float* lnfg  = (const float*)d_in[16];
    const float* lnfb  = (const float*)d_in[17];
    const float* Wlm   = (const float*)d_in[18];
    const float* blm   = (const float*)d_in[19];
    float* out = (float*)d_out;

    float* x    = (float*)sym_addr(g_x);
    float* qkv  = (float*)sym_addr(g_qkv);
    bf16* h_hi  = (bf16*)sym_addr(g_h_hi),  * h_lo  = (bf16*)sym_addr(g_h_lo);
    bf16* y_hi  = (bf16*)sym_addr(g_y_hi),  * y_lo  = (bf16*)sym_addr(g_y_lo);
    bf16* ff_hi = (bf16*)sym_addr(g_ff_hi), * ff_lo = (bf16*)sym_addr(g_ff_lo);
    bf16* wqkv_hi = (bf16*)sym_addr(g_wqkv_hi), * wqkv_lo = (bf16*)sym_addr(g_wqkv_lo);
    bf16* wo_hi   = (bf16*)sym_addr(g_wo_hi),   * wo_lo   = (bf16*)sym_addr(g_wo_lo);
    bf16* w1_hi   = (bf16*)sym_addr(g_w1_hi),   * w1_lo   = (bf16*)sym_addr(g_w1_lo);
    bf16* w2_hi   = (bf16*)sym_addr(g_w2_hi),   * w2_lo   = (bf16*)sym_addr(g_w2_lo);
    bf16* wlm_hi  = (bf16*)sym_addr(g_wlm_hi),  * wlm_lo  = (bf16*)sym_addr(g_wlm_lo);

    // --- weight pre-split (once per pass) ---
    {
        int n4;
        n4 = NLAYER * DIM * (QKVD / 4);
        concat_split_qkv<<<(n4 + 255) / 256, 256>>>(Wq, Wk, Wv, wqkv_hi, wqkv_lo);
        n4 = NLAYER * DIM * DIM / 4;
        split_kernel<<<(n4 + 255) / 256, 256>>>(Wo, wo_hi, wo_lo, n4);
        n4 = NLAYER * DIM * FFD / 4;
        split_kernel<<<(n4 + 255) / 256, 256>>>(W1, w1_hi, w1_lo, n4);
        n4 = NLAYER * FFD * DIM / 4;
        split_kernel<<<(n4 + 255) / 256, 256>>>(W2, w2_hi, w2_lo, n4);
        n4 = DIM * VOCAB / 4;
        split_kernel<<<(n4 + 255) / 256, 256>>>(Wlm, wlm_hi, wlm_lo, n4);
    }

    embed_kernel<<<NTOK * DIM / 256, 256>>>(tok, te, pe, x);

    for (int l = 0; l < NLAYER; l++) {
        const bf16* wqh = wqkv_hi + (size_t)l * DIM * QKVD;
        const bf16* wql = wqkv_lo + (size_t)l * DIM * QKVD;
        const bf16* woh = wo_hi   + (size_t)l * DIM * DIM;
        const bf16* wol = wo_lo   + (size_t)l * DIM * DIM;
        const bf16* w1h = w1_hi   + (size_t)l * DIM * FFD;
        const bf16* w1l = w1_lo   + (size_t)l * DIM * FFD;
        const bf16* w2h = w2_hi   + (size_t)l * FFD * DIM;
        const bf16* w2l = w2_lo   + (size_t)l * FFD * DIM;

        ln_kernel<<<NTOK, 256>>>(x, ln1g + l * DIM, ln1b + l * DIM, h_hi, h_lo);

        launch_gemm(0, h_hi, h_lo, wqh, wql, nullptr, nullptr, qkv, nullptr, nullptr,
                    NTOK, QKVD, DIM);

        attn_kernel<<<dim3(SEQ / 64, NH, NB), 64>>>(qkv, y_hi, y_lo);

        launch_gemm(3, y_hi, y_lo, woh, wol, bo + l * DIM, x, x, nullptr, nullptr,
                    NTOK, DIM, DIM);

        ln_kernel<<<NTOK, 256>>>(x, ln2g + l * DIM, ln2b + l * DIM, h_hi, h_lo);

        launch_gemm(4, h_hi, h_lo, w1h, w1l, b1 + (size_t)l * FFD, nullptr,
                    nullptr, ff_hi, ff_lo, NTOK, FFD, DIM);
        launch_gemm(3, ff_hi, ff_lo, w2h, w2l, b2 + l * DIM, x, x, nullptr, nullptr,
                    NTOK, DIM, FFD);
    }

    ln_kernel<<<NTOK, 256>>>(x, lnfg, lnfb, h_hi, h_lo);
    launch_gemm(1, h_hi, h_lo, wlm_hi, wlm_lo, blm, nullptr, out, nullptr, nullptr,
                NTOK, VOCAB, DIM);
}

// round 9
// speedup vs baseline: 2.5015x; 1.0834x over previous
#include <cuda_runtime.h>
#include <cuda_bf16.h>

// ---------------- problem dims ----------------
#define NB     2
#define SEQ    1024
#define DIM    1024
#define NH     16
#define NKV    4
#define HSZ    64
#define NLAYER 6
#define VOCAB  32000
#define FFD    4096
#define NTOK   (NB*SEQ)          // 2048
#define KVD    (NKV*HSZ)         // 256
#define QKVD   (DIM + 2*KVD)     // 1536

typedef __nv_bfloat16 bf16;

// ---------------- scratch (256B-aligned) ----------------
__device__ __align__(256) float g_x  [NTOK*DIM];
__device__ __align__(256) float g_qkv[NTOK*QKVD];
__device__ __align__(256) bf16 g_h_hi [NTOK*DIM];
__device__ __align__(256) bf16 g_h_lo [NTOK*DIM];
__device__ __align__(256) bf16 g_y_hi [NTOK*DIM];
__device__ __align__(256) bf16 g_y_lo [NTOK*DIM];
__device__ __align__(256) bf16 g_ff_hi[NTOK*FFD];
__device__ __align__(256) bf16 g_ff_lo[NTOK*FFD];
__device__ __align__(256) bf16 g_wqkv_hi[NLAYER*DIM*QKVD];
__device__ __align__(256) bf16 g_wqkv_lo[NLAYER*DIM*QKVD];
__device__ __align__(256) bf16 g_wo_hi  [NLAYER*DIM*DIM];
__device__ __align__(256) bf16 g_wo_lo  [NLAYER*DIM*DIM];
__device__ __align__(256) bf16 g_w1_hi  [NLAYER*DIM*FFD];
__device__ __align__(256) bf16 g_w1_lo  [NLAYER*DIM*FFD];
__device__ __align__(256) bf16 g_w2_hi  [NLAYER*FFD*DIM];
__device__ __align__(256) bf16 g_w2_lo  [NLAYER*FFD*DIM];
__device__ __align__(256) bf16 g_wlm_hi [DIM*VOCAB];
__device__ __align__(256) bf16 g_wlm_lo [DIM*VOCAB];

// ---------------- helpers ----------------
__device__ __forceinline__ unsigned packbf2(float a, float b) {
    __nv_bfloat162 t = __floats2bfloat162_rn(a, b);
    return *(unsigned*)&t;
}
__device__ __forceinline__ void split2(float a, float b, unsigned& hi, unsigned& lo) {
    bf16 ha = __float2bfloat16(a), hb = __float2bfloat16(b);
    float la = a - __bfloat162float(ha);
    float lb = b - __bfloat162float(hb);
    __nv_bfloat162 h2 = __halves2bfloat162(ha, hb);
    hi = *(unsigned*)&h2;
    lo = packbf2(la, lb);
}

// ---------------- embedding ----------------
__global__ void embed_kernel(const int* __restrict__ tok, const float* __restrict__ te,
                             const float* __restrict__ pe, float* __restrict__ x) {
    int idx = blockIdx.x * 256 + threadIdx.x;
    int row = idx >> 10;
    int d   = idx & (DIM - 1);
    int t   = row & (SEQ - 1);
    x[idx] = te[(size_t)tok[row] * DIM + d] + pe[t * DIM + d];
}

// ---------------- split fp32 -> bf16 hi/lo (bulk, float4) ----------------
__global__ void split_kernel(const float* __restrict__ src, bf16* __restrict__ hi,
                             bf16* __restrict__ lo, int n4) {
    int i = blockIdx.x * 256 + threadIdx.x;
    if (i >= n4) return;
    float4 v = ((const float4*)src)[i];
    uint2 ph, pl;
    split2(v.x, v.y, ph.x, pl.x);
    split2(v.z, v.w, ph.y, pl.y);
    ((uint2*)hi)[i] = ph;
    ((uint2*)lo)[i] = pl;
}

// ---------------- concat Wq|Wk|Wv (all layers) + split ----------------
__global__ void concat_split_qkv(const float* __restrict__ Wq, const float* __restrict__ Wk,
                                 const float* __restrict__ Wv,
                                 bf16* __restrict__ hi, bf16* __restrict__ lo) {
    int idx4 = blockIdx.x * 256 + threadIdx.x;
    if (idx4 >= NLAYER * DIM * (QKVD / 4)) return;
    int l   = idx4 / (DIM * (QKVD / 4));
    int r   = idx4 % (DIM * (QKVD / 4));
    int row = r / (QKVD / 4);
    int col = (r % (QKVD / 4)) * 4;
    float4 v;
    if (col < DIM)            v = *(const float4*)(Wq + ((size_t)l * DIM + row) * DIM + col);
    else if (col < DIM + KVD) v = *(const float4*)(Wk + ((size_t)l * DIM + row) * KVD + (col - DIM));
    else                      v = *(const float4*)(Wv + ((size_t)l * DIM + row) * KVD + (col - DIM - KVD));
    uint2 ph, pl;
    split2(v.x, v.y, ph.x, pl.x);
    split2(v.z, v.w, ph.y, pl.y);
    size_t o = ((size_t)l * DIM + row) * QKVD + col;
    *(uint2*)(hi + o) = ph;
    *(uint2*)(lo + o) = pl;
}

// ---------------- layernorm -> split bf16 hi/lo ----------------
__global__ __launch_bounds__(256) void ln_kernel(const float* __restrict__ x,
                                                 const float* __restrict__ g,
                                                 const float* __restrict__ b,
                                                 bf16* __restrict__ yhi,
                                                 bf16* __restrict__ ylo) {
    int row = blockIdx.x;
    int tid = threadIdx.x;
    const float* xr = x + (size_t)row * DIM;
    float4 v = *(const float4*)(xr + tid * 4);
    float sum = v.x + v.y + v.z + v.w;
    float sq  = v.x*v.x + v.y*v.y + v.z*v.z + v.w*v.w;
    #pragma unroll
    for (int o = 16; o > 0; o >>= 1) {
        sum += __shfl_xor_sync(0xffffffffu, sum, o);
        sq  += __shfl_xor_sync(0xffffffffu, sq,  o);
    }
    __shared__ float sh[18];
    int wid = tid >> 5, lane = tid & 31;
    if (lane == 0) { sh[wid] = sum; sh[8 + wid] = sq; }
    __syncthreads();
    if (tid == 0) {
        float a = 0.f, c = 0.f;
        #pragma unroll
        for (int w = 0; w < 8; w++) { a += sh[w]; c += sh[8 + w]; }
        float mu  = a * (1.0f / DIM);
        float var = c * (1.0f / DIM) - mu * mu;
        sh[16] = mu;
        sh[17] = rsqrtf(var + 1e-5f);
    }
    __syncthreads();
    float mu = sh[16], rstd = sh[17];
    float4 gg = *(const float4*)(g + tid * 4);
    float4 bb = *(const float4*)(b + tid * 4);
    float o0 = (v.x - mu) * rstd * gg.x + bb.x;
    float o1 = (v.y - mu) * rstd * gg.y + bb.y;
    float o2 = (v.z - mu) * rstd * gg.z + bb.z;
    float o3 = (v.w - mu) * rstd * gg.w + bb.w;
    uint2 ph, pl;
    split2(o0, o1, ph.x, pl.x);
    split2(o2, o3, ph.y, pl.y);
    *(uint2*)(yhi + (size_t)row * DIM + tid * 4) = ph;
    *(uint2*)(ylo + (size_t)row * DIM + tid * 4) = pl;
}

// =====================================================================
// bf16 split-GEMM — 512 threads / 16 warps (4M x 4N, 32x32 warp tiles),
// cp.async 3-stage pipeline (16B-aligned smem), ldmatrix + mma.
// C = (Ah+Al)(MxK) @ (Bh+Bl)(KxN), 3-term fp32 acc.
// EPI: 0 plain, 1 +bias, 3 +bias+res, 4 +bias+relu -> bf16 hi/lo
// =====================================================================
#define BK     32
#define SPADA  40
#define SPADB  136
#define NSTAGE 3

__device__ __forceinline__ void mma16816(float* c, const unsigned* a, const unsigned* b) {
    asm volatile(
        "mma.sync.aligned.m16n8k16.row.col.f32.bf16.bf16.f32 "
        "{%0,%1,%2,%3}, {%4,%5,%6,%7}, {%8,%9}, {%0,%1,%2,%3};\n"
        : "+f"(c[0]), "+f"(c[1]), "+f"(c[2]), "+f"(c[3])
        : "r"(a[0]), "r"(a[1]), "r"(a[2]), "r"(a[3]), "r"(b[0]), "r"(b[1]));
}
__device__ __forceinline__ void ldsm4(unsigned* r, unsigned addr) {
    asm volatile("ldmatrix.sync.aligned.m8n8.x4.shared.b16 {%0,%1,%2,%3}, [%4];\n"
                 : "=r"(r[0]), "=r"(r[1]), "=r"(r[2]), "=r"(r[3]) : "r"(addr));
}
__device__ __forceinline__ void ldsm4t(unsigned* r, unsigned addr) {
    asm volatile("ldmatrix.sync.aligned.m8n8.x4.trans.shared.b16 {%0,%1,%2,%3}, [%4];\n"
                 : "=r"(r[0]), "=r"(r[1]), "=r"(r[2]), "=r"(r[3]) : "r"(addr));
}
__device__ __forceinline__ void cpa16(unsigned dst, const void* src) {
    asm volatile("cp.async.cg.shared.global [%0], [%1], 16;\n" :: "r"(dst), "l"(src) : "memory");
}
__device__ __forceinline__ void cpa_commit() {
    asm volatile("cp.async.commit_group;\n" ::: "memory");
}
template <int Npend>
__device__ __forceinline__ void cpa_wait() {
    asm volatile("cp.async.wait_group %0;\n" :: "n"(Npend) : "memory");
}

template <int EPI>
__global__ __launch_bounds__(512, 1) void gemm_bf(const bf16* __restrict__ Ah_g,
                                                  const bf16* __restrict__ Al_g,
                                                  const bf16* __restrict__ Bh_g,
                                                  const bf16* __restrict__ Bl_g,
                                                  const float* __restrict__ bias,
                                                  const float* __restrict__ res,
                                                  float* __restrict__ C,
                                                  bf16* __restrict__ Chi,
                                                  bf16* __restrict__ Clo,
                                                  int M, int N, int K) {
    __shared__ __align__(16) bf16 Ah[NSTAGE][128][SPADA], Al[NSTAGE][128][SPADA];
    __shared__ __align__(16) bf16 Bh[NSTAGE][BK][SPADB],  Bl[NSTAGE][BK][SPADB];

    int tid = threadIdx.x;
    int bm = blockIdx.y * 128, bn = blockIdx.x * 128;
    int wid = tid >> 5, lane = tid & 31;
    int wm = (wid & 3) * 32;           // 4 warps along M
    int wn = (wid >> 2) * 32;          // 4 warps along N
    int g  = lane >> 2, tg = lane & 3;

    // cp.async fill mapping: one 16B chunk per thread per array per stage
    int a_row = tid >> 2,  a_col = (tid & 3) * 8;    // A tile 128x32
    int b_row = tid >> 4,  b_col = (tid & 15) * 8;   // B tile 32x128

    unsigned baseAh[NSTAGE], baseAl[NSTAGE], baseBh[NSTAGE], baseBl[NSTAGE];
    #pragma unroll
    for (int s = 0; s < NSTAGE; s++) {
        baseAh[s] = (unsigned)__cvta_generic_to_shared(&Ah[s][0][0]);
        baseAl[s] = (unsigned)__cvta_generic_to_shared(&Al[s][0][0]);
        baseBh[s] = (unsigned)__cvta_generic_to_shared(&Bh[s][0][0]);
        baseBl[s] = (unsigned)__cvta_generic_to_shared(&Bl[s][0][0]);
    }
    unsigned dA = (a_row * SPADA + a_col) * 2;   // 16B-aligned: SPADA*2=80, a_col*2 mult of 16
    unsigned dB = (b_row * SPADB + b_col) * 2;   // SPADB*2=272, b_col*2 mult of 16

    auto issue = [&](int s, int k0) {
        cpa16(baseAh[s] + dA, Ah_g + (size_t)(bm + a_row) * K + k0 + a_col);
        cpa16(baseAl[s] + dA, Al_g + (size_t)(bm + a_row) * K + k0 + a_col);
        cpa16(baseBh[s] + dB, Bh_g + (size_t)(k0 + b_row) * N + bn + b_col);
        cpa16(baseBl[s] + dB, Bl_g + (size_t)(k0 + b_row) * N + bn + b_col);
    };

    // ldmatrix lane addressing
    int a_row_l  = wm + (lane & 15);
    int a_col_l  = (lane >> 4) * 8;
    int b_krow_l = lane & 15;
    int b_ncol_l = wn + (lane >> 4) * 8;

    float acc[2][4][4];
    #pragma unroll
    for (int a = 0; a < 2; a++)
        #pragma unroll
        for (int b = 0; b < 4; b++)
            #pragma unroll
            for (int c = 0; c < 4; c++) acc[a][b][c] = 0.f;

    auto compute = [&](int s) {
        #pragma unroll
        for (int kk = 0; kk < BK; kk += 16) {
            unsigned afh[2][4], afl[2][4];
            #pragma unroll
            for (int mt = 0; mt < 2; mt++) {
                unsigned off = ((a_row_l + mt * 16) * SPADA + a_col_l + kk) * 2;
                ldsm4(afh[mt], baseAh[s] + off);
                ldsm4(afl[mt], baseAl[s] + off);
            }
            unsigned bfh[2][4], bfl[2][4];
            #pragma unroll
            for (int p = 0; p < 2; p++) {
                unsigned off = ((kk + b_krow_l) * SPADB + b_ncol_l + p * 16) * 2;
                ldsm4t(bfh[p], baseBh[s] + off);
                ldsm4t(bfl[p], baseBl[s] + off);
            }
            #pragma unroll
            for (int mt = 0; mt < 2; mt++) {
                #pragma unroll
                for (int nt = 0; nt < 4; nt++) {
                    unsigned* bh2 = &bfh[nt >> 1][(nt & 1) * 2];
                    unsigned* bl2 = &bfl[nt >> 1][(nt & 1) * 2];
                    mma16816(acc[mt][nt], afh[mt], bh2);
                    mma16816(acc[mt][nt], afh[mt], bl2);
                    mma16816(acc[mt][nt], afl[mt], bh2);
                }
            }
        }
    };

    // 3-stage pipeline: loads run two chunks ahead, one sync per iteration
    int nchunk = K / BK;
    issue(0, 0);       cpa_commit();
    issue(1, BK);      cpa_commit();
    for (int ch = 0; ch < nchunk; ch++) {
        cpa_wait<1>();          // stage ch complete (ch+1 may be in flight)
        __syncthreads();        // also fences: stage (ch+2)%3 fully read in iter ch-1
        int nx = ch + 2;
        if (nx < nchunk) issue(nx % NSTAGE, nx * BK);
        cpa_commit();           // uniform group bookkeeping (empty ok)
        compute(ch % NSTAGE);
    }

    // epilogue
    #pragma unroll
    for (int mt = 0; mt < 2; mt++) {
        #pragma unroll
        for (int nt = 0; nt < 4; nt++) {
            int row = bm + wm + mt * 16 + g;
            int col = bn + wn + nt * 8 + tg * 2;
            float2 o0 = make_float2(acc[mt][nt][0], acc[mt][nt][1]);
            float2 o1 = make_float2(acc[mt][nt][2], acc[mt][nt][3]);
            if (EPI >= 1) {
                float2 bb = *(const float2*)(bias + col);
                o0.x += bb.x; o0.y += bb.y; o1.x += bb.x; o1.y += bb.y;
            }
            if (EPI == 3) {
                float2 r0 = *(const float2*)(res + (size_t)row * N + col);
                float2 r1 = *(const float2*)(res + (size_t)(row + 8) * N + col);
                o0.x += r0.x; o0.y += r0.y; o1.x += r1.x; o1.y += r1.y;
            }
            if (EPI == 4) {
                o0.x = fmaxf(o0.x, 0.f); o0.y = fmaxf(o0.y, 0.f);
                o1.x = fmaxf(o1.x, 0.f); o1.y = fmaxf(o1.y, 0.f);
                unsigned h0, l0, h1, l1;
                split2(o0.x, o0.y, h0, l0);
                split2(o1.x, o1.y, h1, l1);
                *(unsigned*)(Chi + (size_t)row * N + col)       = h0;
                *(unsigned*)(Clo + (size_t)row * N + col)       = l0;
                *(unsigned*)(Chi + (size_t)(row + 8) * N + col) = h1;
                *(unsigned*)(Clo + (size_t)(row + 8) * N + col) = l1;
            } else {
                *(float2*)(C + (size_t)row * N + col) = o0;
                *(float2*)(C + (size_t)(row + 8) * N + col) = o1;
            }
        }
    }
}

// ---------------- fused causal GQA attention (fp32 in, bf16-split out) ----------------
__global__ __launch_bounds__(64) void attn_kernel(const float* __restrict__ QKV,
                                                  bf16* __restrict__ Yhi,
                                                  bf16* __restrict__ Ylo) {
    __shared__ __align__(16) float ks[64][64];
    __shared__ __align__(16) float vs[64][64];
    __shared__ float ss[64][65];

    int itile = blockIdx.x;
    int h     = blockIdx.y;
    int b     = blockIdx.z;
    int kvh   = h >> 2;
    int tid   = threadIdx.x;
    int i     = itile * 64 + tid;

    const float scale = 0.125f;
    float q[64], o[64];
    const float* qrow = QKV + ((size_t)(b * SEQ + i)) * QKVD + h * HSZ;
    #pragma unroll
    for (int d = 0; d < 64; d += 4) {
        float4 t = *(const float4*)(qrow + d);
        q[d] = t.x * scale; q[d+1] = t.y * scale; q[d+2] = t.z * scale; q[d+3] = t.w * scale;
    }
    #pragma unroll
    for (int d = 0; d < 64; d++) o[d] = 0.f;
    float m = -1e30f, l = 0.f;

    for (int j0 = 0; j0 <= itile * 64; j0 += 64) {
        const float* krow = QKV + ((size_t)(b * SEQ + j0 + tid)) * QKVD + DIM + kvh * HSZ;
        const float* vrow = krow + KVD;
        #pragma unroll
        for (int d = 0; d < 64; d += 4) {
            *(float4*)&ks[tid][d] = *(const float4*)(krow + d);
            *(float4*)&vs[tid][d] = *(const float4*)(vrow + d);
        }
        __syncthreads();

        float mt = m;
        #pragma unroll 4
        for (int j = 0; j < 64; j++) {
            float acc = 0.f;
            #pragma unroll
            for (int d = 0; d < 64; d += 4) {
                float4 kk = *(const float4*)&ks[j][d];
                acc = fmaf(q[d],   kk.x, acc);
                acc = fmaf(q[d+1], kk.y, acc);
                acc = fmaf(q[d+2], kk.z, acc);
                acc = fmaf(q[d+3], kk.w, acc);
            }
            if (j0 + j > i) acc = -1e30f;
            ss[tid][j] = acc;
            mt = fmaxf(mt, acc);
        }

        float corr = __expf(m - mt);
        l *= corr;
        #pragma unroll
        for (int d = 0; d < 64; d++) o[d] *= corr;

        #pragma unroll 2
        for (int j = 0; j < 64; j++) {
            float p = __expf(ss[tid][j] - mt);
            l += p;
            #pragma unroll
            for (int d = 0; d < 64; d += 4) {
                float4 vv = *(const float4*)&vs[j][d];
                o[d]   = fmaf(p, vv.x, o[d]);
                o[d+1] = fmaf(p, vv.y, o[d+1]);
                o[d+2] = fmaf(p, vv.z, o[d+2]);
                o[d+3] = fmaf(p, vv.w, o[d+3]);
            }
        }
        m = mt;
        __syncthreads();
    }

    float inv = 1.0f / l;
    size_t yo = ((size_t)(b * SEQ + i)) * DIM + h * HSZ;
    #pragma unroll
    for (int d = 0; d < 64; d += 4) {
        uint2 ph, pl;
        split2(o[d] * inv,   o[d+1] * inv, ph.x, pl.x);
        split2(o[d+2] * inv, o[d+3] * inv, ph.y, pl.y);
        *(uint2*)(Yhi + yo + d) = ph;
        *(uint2*)(Ylo + yo + d) = pl;
    }
}

// ---------------- host ----------------
template <typename Tp>
static void* sym_addr(Tp& s) {
    void* p = nullptr;
    cudaGetSymbolAddress(&p, s);
    return p;
}

static void launch_gemm(int epi, const bf16* Ah, const bf16* Al,
                        const bf16* Bh, const bf16* Bl,
                        const float* bias, const float* res,
                        float* C, bf16* Chi, bf16* Clo, int M, int N, int K) {
    dim3 grid(N / 128, M / 128);
    switch (epi) {
        case 0: gemm_bf<0><<<grid, 512>>>(Ah, Al, Bh, Bl, bias, res, C, Chi, Clo, M, N, K); break;
        case 1: gemm_bf<1><<<grid, 512>>>(Ah, Al, Bh, Bl, bias, res, C, Chi, Clo, M, N, K); break;
        case 3: gemm_bf<3><<<grid, 512>>>(Ah, Al, Bh, Bl, bias, res, C, Chi, Clo, M, N, K); break;
        case 4: gemm_bf<4><<<grid, 512>>>(Ah, Al, Bh, Bl, bias, res, C, Chi, Clo, M, N, K); break;
    }
}

extern "C" void kernel_launch(void* const* d_in, const int* in_sizes, int n_in,
                              void* d_out, int out_size) {
    const int*   tok   = (const int*)  d_in[0];
    const float* te    = (const float*)d_in[1];
    const float* pe    = (const float*)d_in[2];
    const float* ln1g  = (const float*)d_in[3];
    const float* ln1b  = (const float*)d_in[4];
    const float* Wq    = (const float*)d_in[5];
    const float* Wk    = (const float*)d_in[6];
    const float* Wv    = (const float*)d_in[7];
    const float* Wo    = (const float*)d_in[8];
    const float* bo    = (const float*)d_in[9];
    const float* ln2g  = (const float*)d_in[10];
    const float* ln2b  = (const float*)d_in[11];
    const float* W1    = (const float*)d_in[12];
    const float* b1    = (const float*)d_in[13];
    const float* W2    = (const float*)d_in[14];
    const float* b2    = (const float*)d_in[15];
    const float* lnfg  = (const float*)d_in[16];
    const float* lnfb  = (const float*)d_in[17];
    const float* Wlm   = (const float*)d_in[18];
    const float* blm   = (const float*)d_in[19];
    float* out = (float*)d_out;

    float* x    = (float*)sym_addr(g_x);
    float* qkv  = (float*)sym_addr(g_qkv);
    bf16* h_hi  = (bf16*)sym_addr(g_h_hi),  * h_lo  = (bf16*)sym_addr(g_h_lo);
    bf16* y_hi  = (bf16*)sym_addr(g_y_hi),  * y_lo  = (bf16*)sym_addr(g_y_lo);
    bf16* ff_hi = (bf16*)sym_addr(g_ff_hi), * ff_lo = (bf16*)sym_addr(g_ff_lo);
    bf16* wqkv_hi = (bf16*)sym_addr(g_wqkv_hi), * wqkv_lo = (bf16*)sym_addr(g_wqkv_lo);
    bf16* wo_hi   = (bf16*)sym_addr(g_wo_hi),   * wo_lo   = (bf16*)sym_addr(g_wo_lo);
    bf16* w1_hi   = (bf16*)sym_addr(g_w1_hi),   * w1_lo   = (bf16*)sym_addr(g_w1_lo);
    bf16* w2_hi   = (bf16*)sym_addr(g_w2_hi),   * w2_lo   = (bf16*)sym_addr(g_w2_lo);
    bf16* wlm_hi  = (bf16*)sym_addr(g_wlm_hi),  * wlm_lo  = (bf16*)sym_addr(g_wlm_lo);

    // --- weight pre-split (once per pass) ---
    {
        int n4;
        n4 = NLAYER * DIM * (QKVD / 4);
        concat_split_qkv<<<(n4 + 255) / 256, 256>>>(Wq, Wk, Wv, wqkv_hi, wqkv_lo);
        n4 = NLAYER * DIM * DIM / 4;
        split_kernel<<<(n4 + 255) / 256, 256>>>(Wo, wo_hi, wo_lo, n4);
        n4 = NLAYER * DIM * FFD / 4;
        split_kernel<<<(n4 + 255) / 256, 256>>>(W1, w1_hi, w1_lo, n4);
        n4 = NLAYER * FFD * DIM / 4;
        split_kernel<<<(n4 + 255) / 256, 256>>>(W2, w2_hi, w2_lo, n4);
        n4 = DIM * VOCAB / 4;
        split_kernel<<<(n4 + 255) / 256, 256>>>(Wlm, wlm_hi, wlm_lo, n4);
    }

    embed_kernel<<<NTOK * DIM / 256, 256>>>(tok, te, pe, x);

    for (int l = 0; l < NLAYER; l++) {
        const bf16* wqh = wqkv_hi + (size_t)l * DIM * QKVD;
        const bf16* wql = wqkv_lo + (size_t)l * DIM * QKVD;
        const bf16* woh = wo_hi   + (size_t)l * DIM * DIM;
        const bf16* wol = wo_lo   + (size_t)l * DIM * DIM;
        const bf16* w1h = w1_hi   + (size_t)l * DIM * FFD;
        const bf16* w1l = w1_lo   + (size_t)l * DIM * FFD;
        const bf16* w2h = w2_hi   + (size_t)l * FFD * DIM;
        const bf16* w2l = w2_lo   + (size_t)l * FFD * DIM;

        ln_kernel<<<NTOK, 256>>>(x, ln1g + l * DIM, ln1b + l * DIM, h_hi, h_lo);

        launch_gemm(0, h_hi, h_lo, wqh, wql, nullptr, nullptr, qkv, nullptr, nullptr,
                    NTOK, QKVD, DIM);

        attn_kernel<<<dim3(SEQ / 64, NH, NB), 64>>>(qkv, y_hi, y_lo);

        launch_gemm(3, y_hi, y_lo, woh, wol, bo + l * DIM, x, x, nullptr, nullptr,
                    NTOK, DIM, DIM);

        ln_kernel<<<NTOK, 256>>>(x, ln2g + l * DIM, ln2b + l * DIM, h_hi, h_lo);

        launch_gemm(4, h_hi, h_lo, w1h, w1l, b1 + (size_t)l * FFD, nullptr,
                    nullptr, ff_hi, ff_lo, NTOK, FFD, DIM);
        launch_gemm(3, ff_hi, ff_lo, w2h, w2l, b2 + l * DIM, x, x, nullptr, nullptr,
                    NTOK, DIM, FFD);
    }

    ln_kernel<<<NTOK, 256>>>(x, lnfg, lnfb, h_hi, h_lo);
    launch_gemm(1, h_hi, h_lo, wlm_hi, wlm_lo, blm, nullptr, out, nullptr, nullptr,
                NTOK, VOCAB, DIM);
}

// round 10
// speedup vs baseline: 2.6053x; 1.0415x over previous
#include <cuda_runtime.h>
#include <cuda_bf16.h>

// ---------------- problem dims ----------------
#define NB     2
#define SEQ    1024
#define DIM    1024
#define NH     16
#define NKV    4
#define HSZ    64
#define NLAYER 6
#define VOCAB  32000
#define FFD    4096
#define NTOK   (NB*SEQ)          // 2048
#define KVD    (NKV*HSZ)         // 256
#define QKVD   (DIM + 2*KVD)     // 1536

typedef __nv_bfloat16 bf16;

// ---------------- scratch (256B-aligned) ----------------
__device__ __align__(256) float g_x  [NTOK*DIM];
__device__ __align__(256) float g_qkv[NTOK*QKVD];
__device__ __align__(256) bf16 g_h_hi [NTOK*DIM];
__device__ __align__(256) bf16 g_h_lo [NTOK*DIM];
__device__ __align__(256) bf16 g_y_hi [NTOK*DIM];
__device__ __align__(256) bf16 g_y_lo [NTOK*DIM];
__device__ __align__(256) bf16 g_ff_hi[NTOK*FFD];
__device__ __align__(256) bf16 g_ff_lo[NTOK*FFD];
__device__ __align__(256) bf16 g_wqkv_hi[NLAYER*DIM*QKVD];
__device__ __align__(256) bf16 g_wqkv_lo[NLAYER*DIM*QKVD];
__device__ __align__(256) bf16 g_wo_hi  [NLAYER*DIM*DIM];
__device__ __align__(256) bf16 g_wo_lo  [NLAYER*DIM*DIM];
__device__ __align__(256) bf16 g_w1_hi  [NLAYER*DIM*FFD];
__device__ __align__(256) bf16 g_w1_lo  [NLAYER*DIM*FFD];
__device__ __align__(256) bf16 g_w2_hi  [NLAYER*FFD*DIM];
__device__ __align__(256) bf16 g_w2_lo  [NLAYER*FFD*DIM];
__device__ __align__(256) bf16 g_wlm_hi [DIM*VOCAB];
__device__ __align__(256) bf16 g_wlm_lo [DIM*VOCAB];

// ---------------- helpers ----------------
__device__ __forceinline__ unsigned packbf2(float a, float b) {
    __nv_bfloat162 t = __floats2bfloat162_rn(a, b);
    return *(unsigned*)&t;
}
__device__ __forceinline__ void split2(float a, float b, unsigned& hi, unsigned& lo) {
    bf16 ha = __float2bfloat16(a), hb = __float2bfloat16(b);
    float la = a - __bfloat162float(ha);
    float lb = b - __bfloat162float(hb);
    __nv_bfloat162 h2 = __halves2bfloat162(ha, hb);
    hi = *(unsigned*)&h2;
    lo = packbf2(la, lb);
}

// ---------------- embedding ----------------
__global__ void embed_kernel(const int* __restrict__ tok, const float* __restrict__ te,
                             const float* __restrict__ pe, float* __restrict__ x) {
    int idx = blockIdx.x * 256 + threadIdx.x;
    int row = idx >> 10;
    int d   = idx & (DIM - 1);
    int t   = row & (SEQ - 1);
    x[idx] = te[(size_t)tok[row] * DIM + d] + pe[t * DIM + d];
}

// ---------------- split fp32 -> bf16 hi/lo (bulk, float4) ----------------
__global__ void split_kernel(const float* __restrict__ src, bf16* __restrict__ hi,
                             bf16* __restrict__ lo, int n4) {
    int i = blockIdx.x * 256 + threadIdx.x;
    if (i >= n4) return;
    float4 v = ((const float4*)src)[i];
    uint2 ph, pl;
    split2(v.x, v.y, ph.x, pl.x);
    split2(v.z, v.w, ph.y, pl.y);
    ((uint2*)hi)[i] = ph;
    ((uint2*)lo)[i] = pl;
}

// ---------------- concat Wq|Wk|Wv (all layers) + split ----------------
__global__ void concat_split_qkv(const float* __restrict__ Wq, const float* __restrict__ Wk,
                                 const float* __restrict__ Wv,
                                 bf16* __restrict__ hi, bf16* __restrict__ lo) {
    int idx4 = blockIdx.x * 256 + threadIdx.x;
    if (idx4 >= NLAYER * DIM * (QKVD / 4)) return;
    int l   = idx4 / (DIM * (QKVD / 4));
    int r   = idx4 % (DIM * (QKVD / 4));
    int row = r / (QKVD / 4);
    int col = (r % (QKVD / 4)) * 4;
    float4 v;
    if (col < DIM)            v = *(const float4*)(Wq + ((size_t)l * DIM + row) * DIM + col);
    else if (col < DIM + KVD) v = *(const float4*)(Wk + ((size_t)l * DIM + row) * KVD + (col - DIM));
    else                      v = *(const float4*)(Wv + ((size_t)l * DIM + row) * KVD + (col - DIM - KVD));
    uint2 ph, pl;
    split2(v.x, v.y, ph.x, pl.x);
    split2(v.z, v.w, ph.y, pl.y);
    size_t o = ((size_t)l * DIM + row) * QKVD + col;
    *(uint2*)(hi + o) = ph;
    *(uint2*)(lo + o) = pl;
}

// ---------------- layernorm -> split bf16 hi/lo ----------------
__global__ __launch_bounds__(256) void ln_kernel(const float* __restrict__ x,
                                                 const float* __restrict__ g,
                                                 const float* __restrict__ b,
                                                 bf16* __restrict__ yhi,
                                                 bf16* __restrict__ ylo) {
    int row = blockIdx.x;
    int tid = threadIdx.x;
    const float* xr = x + (size_t)row * DIM;
    float4 v = *(const float4*)(xr + tid * 4);
    float sum = v.x + v.y + v.z + v.w;
    float sq  = v.x*v.x + v.y*v.y + v.z*v.z + v.w*v.w;
    #pragma unroll
    for (int o = 16; o > 0; o >>= 1) {
        sum += __shfl_xor_sync(0xffffffffu, sum, o);
        sq  += __shfl_xor_sync(0xffffffffu, sq,  o);
    }
    __shared__ float sh[18];
    int wid = tid >> 5, lane = tid & 31;
    if (lane == 0) { sh[wid] = sum; sh[8 + wid] = sq; }
    __syncthreads();
    if (tid == 0) {
        float a = 0.f, c = 0.f;
        #pragma unroll
        for (int w = 0; w < 8; w++) { a += sh[w]; c += sh[8 + w]; }
        float mu  = a * (1.0f / DIM);
        float var = c * (1.0f / DIM) - mu * mu;
        sh[16] = mu;
        sh[17] = rsqrtf(var + 1e-5f);
    }
    __syncthreads();
    float mu = sh[16], rstd = sh[17];
    float4 gg = *(const float4*)(g + tid * 4);
    float4 bb = *(const float4*)(b + tid * 4);
    float o0 = (v.x - mu) * rstd * gg.x + bb.x;
    float o1 = (v.y - mu) * rstd * gg.y + bb.y;
    float o2 = (v.z - mu) * rstd * gg.z + bb.z;
    float o3 = (v.w - mu) * rstd * gg.w + bb.w;
    uint2 ph, pl;
    split2(o0, o1, ph.x, pl.x);
    split2(o2, o3, ph.y, pl.y);
    *(uint2*)(yhi + (size_t)row * DIM + tid * 4) = ph;
    *(uint2*)(ylo + (size_t)row * DIM + tid * 4) = pl;
}

// =====================================================================
// bf16 split-GEMM — 512 threads / 16 warps (4M x 4N, 32x32 warp tiles),
// BK=64 chunks, 2-stage cp.async double buffer (one sync per 4 k-steps),
// ldmatrix + mma.  C = (Ah+Al)(MxK) @ (Bh+Bl)(KxN), 3-term fp32 acc.
// EPI: 0 plain, 1 +bias, 3 +bias+res, 4 +bias+relu -> bf16 hi/lo
// =====================================================================
#define BK     64
#define SPADA  72      // 64 + 8 pad (row stride 144B -> ldmatrix banks 4i mod 32, distinct)
#define SPADB  136
#define NSTAGE 2

__device__ __forceinline__ void mma16816(float* c, const unsigned* a, const unsigned* b) {
    asm volatile(
        "mma.sync.aligned.m16n8k16.row.col.f32.bf16.bf16.f32 "
        "{%0,%1,%2,%3}, {%4,%5,%6,%7}, {%8,%9}, {%0,%1,%2,%3};\n"
        : "+f"(c[0]), "+f"(c[1]), "+f"(c[2]), "+f"(c[3])
        : "r"(a[0]), "r"(a[1]), "r"(a[2]), "r"(a[3]), "r"(b[0]), "r"(b[1]));
}
__device__ __forceinline__ void ldsm4(unsigned* r, unsigned addr) {
    asm volatile("ldmatrix.sync.aligned.m8n8.x4.shared.b16 {%0,%1,%2,%3}, [%4];\n"
                 : "=r"(r[0]), "=r"(r[1]), "=r"(r[2]), "=r"(r[3]) : "r"(addr));
}
__device__ __forceinline__ void ldsm4t(unsigned* r, unsigned addr) {
    asm volatile("ldmatrix.sync.aligned.m8n8.x4.trans.shared.b16 {%0,%1,%2,%3}, [%4];\n"
                 : "=r"(r[0]), "=r"(r[1]), "=r"(r[2]), "=r"(r[3]) : "r"(addr));
}
__device__ __forceinline__ void cpa16(unsigned dst, const void* src) {
    asm volatile("cp.async.cg.shared.global [%0], [%1], 16;\n" :: "r"(dst), "l"(src) : "memory");
}
__device__ __forceinline__ void cpa_commit() {
    asm volatile("cp.async.commit_group;\n" ::: "memory");
}
template <int Npend>
__device__ __forceinline__ void cpa_wait() {
    asm volatile("cp.async.wait_group %0;\n" :: "n"(Npend) : "memory");
}

template <int EPI>
__global__ __launch_bounds__(512, 1) void gemm_bf(const bf16* __restrict__ Ah_g,
                                                  const bf16* __restrict__ Al_g,
                                                  const bf16* __restrict__ Bh_g,
                                                  const bf16* __restrict__ Bl_g,
                                                  const float* __restrict__ bias,
                                                  const float* __restrict__ res,
                                                  float* __restrict__ C,
                                                  bf16* __restrict__ Chi,
                                                  bf16* __restrict__ Clo,
                                                  int M, int N, int K) {
    __shared__ __align__(16) bf16 Ah[NSTAGE][128][SPADA], Al[NSTAGE][128][SPADA];
    __shared__ __align__(16) bf16 Bh[NSTAGE][BK][SPADB],  Bl[NSTAGE][BK][SPADB];

    int tid = threadIdx.x;
    int bm = blockIdx.y * 128, bn = blockIdx.x * 128;
    int wid = tid >> 5, lane = tid & 31;
    int wm = (wid & 3) * 32;           // 4 warps along M
    int wn = (wid >> 2) * 32;          // 4 warps along N
    int g  = lane >> 2, tg = lane & 3;

    // cp.async fill mapping: A tile 128x64, B tile 64x128; 2 shots of 16B per array
    int a_row[2], a_col[2], b_row[2], b_col[2];
    #pragma unroll
    for (int i = 0; i < 2; i++) {
        int idx = tid + i * 512;
        a_row[i] = idx >> 3;  a_col[i] = (idx & 7) * 8;    // cols 0..56
        b_row[i] = idx >> 4;  b_col[i] = (idx & 15) * 8;   // cols 0..120
    }

    unsigned baseAh[NSTAGE], baseAl[NSTAGE], baseBh[NSTAGE], baseBl[NSTAGE];
    #pragma unroll
    for (int s = 0; s < NSTAGE; s++) {
        baseAh[s] = (unsigned)__cvta_generic_to_shared(&Ah[s][0][0]);
        baseAl[s] = (unsigned)__cvta_generic_to_shared(&Al[s][0][0]);
        baseBh[s] = (unsigned)__cvta_generic_to_shared(&Bh[s][0][0]);
        baseBl[s] = (unsigned)__cvta_generic_to_shared(&Bl[s][0][0]);
    }
    unsigned dA[2], dB[2];
    #pragma unroll
    for (int i = 0; i < 2; i++) {
        dA[i] = (a_row[i] * SPADA + a_col[i]) * 2;   // 16B multiple (col*2 = 0..112 step 16)
        dB[i] = (b_row[i] * SPADB + b_col[i]) * 2;
    }

    auto issue = [&](int s, int k0) {
        #pragma unroll
        for (int i = 0; i < 2; i++) {
            size_t ao = (size_t)(bm + a_row[i]) * K + k0 + a_col[i];
            size_t bo = (size_t)(k0 + b_row[i]) * N + bn + b_col[i];
            cpa16(baseAh[s] + dA[i], Ah_g + ao);
            cpa16(baseAl[s] + dA[i], Al_g + ao);
            cpa16(baseBh[s] + dB[i], Bh_g + bo);
            cpa16(baseBl[s] + dB[i], Bl_g + bo);
        }
    };

    // ldmatrix lane addressing
    int a_row_l  = wm + (lane & 15);
    int a_col_l  = (lane >> 4) * 8;
    int b_krow_l = lane & 15;
    int b_ncol_l = wn + (lane >> 4) * 8;

    float acc[2][4][4];
    #pragma unroll
    for (int a = 0; a < 2; a++)
        #pragma unroll
        for (int b = 0; b < 4; b++)
            #pragma unroll
            for (int c = 0; c < 4; c++) acc[a][b][c] = 0.f;

    auto compute = [&](int s) {
        #pragma unroll
        for (int kk = 0; kk < BK; kk += 16) {
            unsigned afh[2][4], afl[2][4];
            #pragma unroll
            for (int mt = 0; mt < 2; mt++) {
                unsigned off = ((a_row_l + mt * 16) * SPADA + a_col_l + kk) * 2;
                ldsm4(afh[mt], baseAh[s] + off);
                ldsm4(afl[mt], baseAl[s] + off);
            }
            unsigned bfh[2][4], bfl[2][4];
            #pragma unroll
            for (int p = 0; p < 2; p++) {
                unsigned off = ((kk + b_krow_l) * SPADB + b_ncol_l + p * 16) * 2;
                ldsm4t(bfh[p], baseBh[s] + off);
                ldsm4t(bfl[p], baseBl[s] + off);
            }
            #pragma unroll
            for (int mt = 0; mt < 2; mt++) {
                #pragma unroll
                for (int nt = 0; nt < 4; nt++) {
                    unsigned* bh2 = &bfh[nt >> 1][(nt & 1) * 2];
                    unsigned* bl2 = &bfl[nt >> 1][(nt & 1) * 2];
                    mma16816(acc[mt][nt], afh[mt], bh2);
                    mma16816(acc[mt][nt], afh[mt], bl2);
                    mma16816(acc[mt][nt], afl[mt], bh2);
                }
            }
        }
    };

    // 2-stage double buffer: load of chunk ch+1 overlaps compute of chunk ch
    int nchunk = K / BK;
    issue(0, 0);
    cpa_commit();
    for (int ch = 0; ch < nchunk; ch++) {
        cpa_wait<0>();          // chunk ch resident
        __syncthreads();        // all warps done with buffer ch^1 (read in iter ch-1)
        if (ch + 1 < nchunk) { issue((ch + 1) & 1, (ch + 1) * BK); cpa_commit(); }
        compute(ch & 1);
    }

    // epilogue
    #pragma unroll
    for (int mt = 0; mt < 2; mt++) {
        #pragma unroll
        for (int nt = 0; nt < 4; nt++) {
            int row = bm + wm + mt * 16 + g;
            int col = bn + wn + nt * 8 + tg * 2;
            float2 o0 = make_float2(acc[mt][nt][0], acc[mt][nt][1]);
            float2 o1 = make_float2(acc[mt][nt][2], acc[mt][nt][3]);
            if (EPI >= 1) {
                float2 bb = *(const float2*)(bias + col);
                o0.x += bb.x; o0.y += bb.y; o1.x += bb.x; o1.y += bb.y;
            }
            if (EPI == 3) {
                float2 r0 = *(const float2*)(res + (size_t)row * N + col);
                float2 r1 = *(const float2*)(res + (size_t)(row + 8) * N + col);
                o0.x += r0.x; o0.y += r0.y; o1.x += r1.x; o1.y += r1.y;
            }
            if (EPI == 4) {
                o0.x = fmaxf(o0.x, 0.f); o0.y = fmaxf(o0.y, 0.f);
                o1.x = fmaxf(o1.x, 0.f); o1.y = fmaxf(o1.y, 0.f);
                unsigned h0, l0, h1, l1;
                split2(o0.x, o0.y, h0, l0);
                split2(o1.x, o1.y, h1, l1);
                *(unsigned*)(Chi + (size_t)row * N + col)       = h0;
                *(unsigned*)(Clo + (size_t)row * N + col)       = l0;
                *(unsigned*)(Chi + (size_t)(row + 8) * N + col) = h1;
                *(unsigned*)(Clo + (size_t)(row + 8) * N + col) = l1;
            } else {
                *(float2*)(C + (size_t)row * N + col) = o0;
                *(float2*)(C + (size_t)(row + 8) * N + col) = o1;
            }
        }
    }
}

// ---------------- fused causal GQA attention (fp32 in, bf16-split out) ----------------
__global__ __launch_bounds__(64) void attn_kernel(const float* __restrict__ QKV,
                                                  bf16* __restrict__ Yhi,
                                                  bf16* __restrict__ Ylo) {
    __shared__ __align__(16) float ks[64][64];
    __shared__ __align__(16) float vs[64][64];
    __shared__ float ss[64][65];

    int itile = blockIdx.x;
    int h     = blockIdx.y;
    int b     = blockIdx.z;
    int kvh   = h >> 2;
    int tid   = threadIdx.x;
    int i     = itile * 64 + tid;

    const float scale = 0.125f;
    float q[64], o[64];
    const float* qrow = QKV + ((size_t)(b * SEQ + i)) * QKVD + h * HSZ;
    #pragma unroll
    for (int d = 0; d < 64; d += 4) {
        float4 t = *(const float4*)(qrow + d);
        q[d] = t.x * scale; q[d+1] = t.y * scale; q[d+2] = t.z * scale; q[d+3] = t.w * scale;
    }
    #pragma unroll
    for (int d = 0; d < 64; d++) o[d] = 0.f;
    float m = -1e30f, l = 0.f;

    for (int j0 = 0; j0 <= itile * 64; j0 += 64) {
        const float* krow = QKV + ((size_t)(b * SEQ + j0 + tid)) * QKVD + DIM + kvh * HSZ;
        const float* vrow = krow + KVD;
        #pragma unroll
        for (int d = 0; d < 64; d += 4) {
            *(float4*)&ks[tid][d] = *(const float4*)(krow + d);
            *(float4*)&vs[tid][d] = *(const float4*)(vrow + d);
        }
        __syncthreads();

        float mt = m;
        #pragma unroll 4
        for (int j = 0; j < 64; j++) {
            float acc = 0.f;
            #pragma unroll
            for (int d = 0; d < 64; d += 4) {
                float4 kk = *(const float4*)&ks[j][d];
                acc = fmaf(q[d],   kk.x, acc);
                acc = fmaf(q[d+1], kk.y, acc);
                acc = fmaf(q[d+2], kk.z, acc);
                acc = fmaf(q[d+3], kk.w, acc);
            }
            if (j0 + j > i) acc = -1e30f;
            ss[tid][j] = acc;
            mt = fmaxf(mt, acc);
        }

        float corr = __expf(m - mt);
        l *= corr;
        #pragma unroll
        for (int d = 0; d < 64; d++) o[d] *= corr;

        #pragma unroll 2
        for (int j = 0; j < 64; j++) {
            float p = __expf(ss[tid][j] - mt);
            l += p;
            #pragma unroll
            for (int d = 0; d < 64; d += 4) {
                float4 vv = *(const float4*)&vs[j][d];
                o[d]   = fmaf(p, vv.x, o[d]);
                o[d+1] = fmaf(p, vv.y, o[d+1]);
                o[d+2] = fmaf(p, vv.z, o[d+2]);
                o[d+3] = fmaf(p, vv.w, o[d+3]);
            }
        }
        m = mt;
        __syncthreads();
    }

    float inv = 1.0f / l;
    size_t yo = ((size_t)(b * SEQ + i)) * DIM + h * HSZ;
    #pragma unroll
    for (int d = 0; d < 64; d += 4) {
        uint2 ph, pl;
        split2(o[d] * inv,   o[d+1] * inv, ph.x, pl.x);
        split2(o[d+2] * inv, o[d+3] * inv, ph.y, pl.y);
        *(uint2*)(Yhi + yo + d) = ph;
        *(uint2*)(Ylo + yo + d) = pl;
    }
}

// ---------------- host ----------------
template <typename Tp>
static void* sym_addr(Tp& s) {
    void* p = nullptr;
    cudaGetSymbolAddress(&p, s);
    return p;
}

static void launch_gemm(int epi, const bf16* Ah, const bf16* Al,
                        const bf16* Bh, const bf16* Bl,
                        const float* bias, const float* res,
                        float* C, bf16* Chi, bf16* Clo, int M, int N, int K) {
    dim3 grid(N / 128, M / 128);
    switch (epi) {
        case 0: gemm_bf<0><<<grid, 512>>>(Ah, Al, Bh, Bl, bias, res, C, Chi, Clo, M, N, K); break;
        case 1: gemm_bf<1><<<grid, 512>>>(Ah, Al, Bh, Bl, bias, res, C, Chi, Clo, M, N, K); break;
        case 3: gemm_bf<3><<<grid, 512>>>(Ah, Al, Bh, Bl, bias, res, C, Chi, Clo, M, N, K); break;
        case 4: gemm_bf<4><<<grid, 512>>>(Ah, Al, Bh, Bl, bias, res, C, Chi, Clo, M, N, K); break;
    }
}

extern "C" void kernel_launch(void* const* d_in, const int* in_sizes, int n_in,
                              void* d_out, int out_size) {
    const int*   tok   = (const int*)  d_in[0];
    const float* te    = (const float*)d_in[1];
    const float* pe    = (const float*)d_in[2];
    const float* ln1g  = (const float*)d_in[3];
    const float* ln1b  = (const float*)d_in[4];
    const float* Wq    = (const float*)d_in[5];
    const float* Wk    = (const float*)d_in[6];
    const float* Wv    = (const float*)d_in[7];
    const float* Wo    = (const float*)d_in[8];
    const float* bo    = (const float*)d_in[9];
    const float* ln2g  = (const float*)d_in[10];
    const float* ln2b  = (const float*)d_in[11];
    const float* W1    = (const float*)d_in[12];
    const float* b1    = (const float*)d_in[13];
    const float* W2    = (const float*)d_in[14];
    const float* b2    = (const float*)d_in[15];
    const float* lnfg  = (const float*)d_in[16];
    const float* lnfb  = (const float*)d_in[17];
    const float* Wlm   = (const float*)d_in[18];
    const float* blm   = (const float*)d_in[19];
    float* out = (float*)d_out;

    float* x    = (float*)sym_addr(g_x);
    float* qkv  = (float*)sym_addr(g_qkv);
    bf16* h_hi  = (bf16*)sym_addr(g_h_hi),  * h_lo  = (bf16*)sym_addr(g_h_lo);
    bf16* y_hi  = (bf16*)sym_addr(g_y_hi),  * y_lo  = (bf16*)sym_addr(g_y_lo);
    bf16* ff_hi = (bf16*)sym_addr(g_ff_hi), * ff_lo = (bf16*)sym_addr(g_ff_lo);
    bf16* wqkv_hi = (bf16*)sym_addr(g_wqkv_hi), * wqkv_lo = (bf16*)sym_addr(g_wqkv_lo);
    bf16* wo_hi   = (bf16*)sym_addr(g_wo_hi),   * wo_lo   = (bf16*)sym_addr(g_wo_lo);
    bf16* w1_hi   = (bf16*)sym_addr(g_w1_hi),   * w1_lo   = (bf16*)sym_addr(g_w1_lo);
    bf16* w2_hi   = (bf16*)sym_addr(g_w2_hi),   * w2_lo   = (bf16*)sym_addr(g_w2_lo);
    bf16* wlm_hi  = (bf16*)sym_addr(g_wlm_hi),  * wlm_lo  = (bf16*)sym_addr(g_wlm_lo);

    // --- weight pre-split (once per pass) ---
    {
        int n4;
        n4 = NLAYER * DIM * (QKVD / 4);
        concat_split_qkv<<<(n4 + 255) / 256, 256>>>(Wq, Wk, Wv, wqkv_hi, wqkv_lo);
        n4 = NLAYER * DIM * DIM / 4;
        split_kernel<<<(n4 + 255) / 256, 256>>>(Wo, wo_hi, wo_lo, n4);
        n4 = NLAYER * DIM * FFD / 4;
        split_kernel<<<(n4 + 255) / 256, 256>>>(W1, w1_hi, w1_lo, n4);
        n4 = NLAYER * FFD * DIM / 4;
        split_kernel<<<(n4 + 255) / 256, 256>>>(W2, w2_hi, w2_lo, n4);
        n4 = DIM * VOCAB / 4;
        split_kernel<<<(n4 + 255) / 256, 256>>>(Wlm, wlm_hi, wlm_lo, n4);
    }

    embed_kernel<<<NTOK * DIM / 256, 256>>>(tok, te, pe, x);

    for (int l = 0; l < NLAYER; l++) {
        const bf16* wqh = wqkv_hi + (size_t)l * DIM * QKVD;
        const bf16* wql = wqkv_lo + (size_t)l * DIM * QKVD;
        const bf16* woh = wo_hi   + (size_t)l * DIM * DIM;
        const bf16* wol = wo_lo   + (size_t)l * DIM * DIM;
        const bf16* w1h = w1_hi   + (size_t)l * DIM * FFD;
        const bf16* w1l = w1_lo   + (size_t)l * DIM * FFD;
        const bf16* w2h = w2_hi   + (size_t)l * FFD * DIM;
        const bf16* w2l = w2_lo   + (size_t)l * FFD * DIM;

        ln_kernel<<<NTOK, 256>>>(x, ln1g + l * DIM, ln1b + l * DIM, h_hi, h_lo);

        launch_gemm(0, h_hi, h_lo, wqh, wql, nullptr, nullptr, qkv, nullptr, nullptr,
                    NTOK, QKVD, DIM);

        attn_kernel<<<dim3(SEQ / 64, NH, NB), 64>>>(qkv, y_hi, y_lo);

        launch_gemm(3, y_hi, y_lo, woh, wol, bo + l * DIM, x, x, nullptr, nullptr,
                    NTOK, DIM, DIM);

        ln_kernel<<<NTOK, 256>>>(x, ln2g + l * DIM, ln2b + l * DIM, h_hi, h_lo);

        launch_gemm(4, h_hi, h_lo, w1h, w1l, b1 + (size_t)l * FFD, nullptr,
                    nullptr, ff_hi, ff_lo, NTOK, FFD, DIM);
        launch_gemm(3, ff_hi, ff_lo, w2h, w2l, b2 + l * DIM, x, x, nullptr, nullptr,
                    NTOK, DIM, FFD);
    }

    ln_kernel<<<NTOK, 256>>>(x, lnfg, lnfb, h_hi, h_lo);
    launch_gemm(1, h_hi, h_lo, wlm_hi, wlm_lo, blm, nullptr, out, nullptr, nullptr,
                NTOK, VOCAB, DIM);
}

// round 11
// speedup vs baseline: 2.6762x; 1.0272x over previous
#include <cuda_runtime.h>
#include <cuda_bf16.h>

// ---------------- problem dims ----------------
#define NB     2
#define SEQ    1024
#define DIM    1024
#define NH     16
#define NKV    4
#define HSZ    64
#define NLAYER 6
#define VOCAB  32000
#define FFD    4096
#define NTOK   (NB*SEQ)          // 2048
#define KVD    (NKV*HSZ)         // 256
#define QKVD   (DIM + 2*KVD)     // 1536

typedef __nv_bfloat16 bf16;

// ---------------- scratch (256B-aligned) ----------------
__device__ __align__(256) float g_x  [NTOK*DIM];
__device__ __align__(256) float g_qkv[NTOK*QKVD];
__device__ __align__(256) bf16 g_h_hi [NTOK*DIM];
__device__ __align__(256) bf16 g_h_lo [NTOK*DIM];
__device__ __align__(256) bf16 g_y_hi [NTOK*DIM];
__device__ __align__(256) bf16 g_y_lo [NTOK*DIM];
__device__ __align__(256) bf16 g_ff_hi[NTOK*FFD];
__device__ __align__(256) bf16 g_ff_lo[NTOK*FFD];
__device__ __align__(256) bf16 g_wqkv_hi[NLAYER*DIM*QKVD];
__device__ __align__(256) bf16 g_wqkv_lo[NLAYER*DIM*QKVD];
__device__ __align__(256) bf16 g_wo_hi  [NLAYER*DIM*DIM];
__device__ __align__(256) bf16 g_wo_lo  [NLAYER*DIM*DIM];
__device__ __align__(256) bf16 g_w1_hi  [NLAYER*DIM*FFD];
__device__ __align__(256) bf16 g_w1_lo  [NLAYER*DIM*FFD];
__device__ __align__(256) bf16 g_w2_hi  [NLAYER*FFD*DIM];
__device__ __align__(256) bf16 g_w2_lo  [NLAYER*FFD*DIM];
__device__ __align__(256) bf16 g_wlm_hi [DIM*VOCAB];
__device__ __align__(256) bf16 g_wlm_lo [DIM*VOCAB];

// ---------------- helpers ----------------
__device__ __forceinline__ unsigned packbf2(float a, float b) {
    __nv_bfloat162 t = __floats2bfloat162_rn(a, b);
    return *(unsigned*)&t;
}
__device__ __forceinline__ void split2(float a, float b, unsigned& hi, unsigned& lo) {
    bf16 ha = __float2bfloat16(a), hb = __float2bfloat16(b);
    float la = a - __bfloat162float(ha);
    float lb = b - __bfloat162float(hb);
    __nv_bfloat162 h2 = __halves2bfloat162(ha, hb);
    hi = *(unsigned*)&h2;
    lo = packbf2(la, lb);
}

// ---------------- embedding ----------------
__global__ void embed_kernel(const int* __restrict__ tok, const float* __restrict__ te,
                             const float* __restrict__ pe, float* __restrict__ x) {
    int idx = blockIdx.x * 256 + threadIdx.x;
    int row = idx >> 10;
    int d   = idx & (DIM - 1);
    int t   = row & (SEQ - 1);
    x[idx] = te[(size_t)tok[row] * DIM + d] + pe[t * DIM + d];
}

// ---------------- split fp32 -> bf16 hi/lo (bulk, float4) ----------------
__global__ void split_kernel(const float* __restrict__ src, bf16* __restrict__ hi,
                             bf16* __restrict__ lo, int n4) {
    int i = blockIdx.x * 256 + threadIdx.x;
    if (i >= n4) return;
    float4 v = ((const float4*)src)[i];
    uint2 ph, pl;
    split2(v.x, v.y, ph.x, pl.x);
    split2(v.z, v.w, ph.y, pl.y);
    ((uint2*)hi)[i] = ph;
    ((uint2*)lo)[i] = pl;
}

// ---------------- concat Wq|Wk|Wv (all layers) + split ----------------
__global__ void concat_split_qkv(const float* __restrict__ Wq, const float* __restrict__ Wk,
                                 const float* __restrict__ Wv,
                                 bf16* __restrict__ hi, bf16* __restrict__ lo) {
    int idx4 = blockIdx.x * 256 + threadIdx.x;
    if (idx4 >= NLAYER * DIM * (QKVD / 4)) return;
    int l   = idx4 / (DIM * (QKVD / 4));
    int r   = idx4 % (DIM * (QKVD / 4));
    int row = r / (QKVD / 4);
    int col = (r % (QKVD / 4)) * 4;
    float4 v;
    if (col < DIM)            v = *(const float4*)(Wq + ((size_t)l * DIM + row) * DIM + col);
    else if (col < DIM + KVD) v = *(const float4*)(Wk + ((size_t)l * DIM + row) * KVD + (col - DIM));
    else                      v = *(const float4*)(Wv + ((size_t)l * DIM + row) * KVD + (col - DIM - KVD));
    uint2 ph, pl;
    split2(v.x, v.y, ph.x, pl.x);
    split2(v.z, v.w, ph.y, pl.y);
    size_t o = ((size_t)l * DIM + row) * QKVD + col;
    *(uint2*)(hi + o) = ph;
    *(uint2*)(lo + o) = pl;
}

// ---------------- layernorm -> split bf16 hi/lo ----------------
__global__ __launch_bounds__(256) void ln_kernel(const float* __restrict__ x,
                                                 const float* __restrict__ g,
                                                 const float* __restrict__ b,
                                                 bf16* __restrict__ yhi,
                                                 bf16* __restrict__ ylo) {
    int row = blockIdx.x;
    int tid = threadIdx.x;
    const float* xr = x + (size_t)row * DIM;
    float4 v = *(const float4*)(xr + tid * 4);
    float sum = v.x + v.y + v.z + v.w;
    float sq  = v.x*v.x + v.y*v.y + v.z*v.z + v.w*v.w;
    #pragma unroll
    for (int o = 16; o > 0; o >>= 1) {
        sum += __shfl_xor_sync(0xffffffffu, sum, o);
        sq  += __shfl_xor_sync(0xffffffffu, sq,  o);
    }
    __shared__ float sh[18];
    int wid = tid >> 5, lane = tid & 31;
    if (lane == 0) { sh[wid] = sum; sh[8 + wid] = sq; }
    __syncthreads();
    if (tid == 0) {
        float a = 0.f, c = 0.f;
        #pragma unroll
        for (int w = 0; w < 8; w++) { a += sh[w]; c += sh[8 + w]; }
        float mu  = a * (1.0f / DIM);
        float var = c * (1.0f / DIM) - mu * mu;
        sh[16] = mu;
        sh[17] = rsqrtf(var + 1e-5f);
    }
    __syncthreads();
    float mu = sh[16], rstd = sh[17];
    float4 gg = *(const float4*)(g + tid * 4);
    float4 bb = *(const float4*)(b + tid * 4);
    float o0 = (v.x - mu) * rstd * gg.x + bb.x;
    float o1 = (v.y - mu) * rstd * gg.y + bb.y;
    float o2 = (v.z - mu) * rstd * gg.z + bb.z;
    float o3 = (v.w - mu) * rstd * gg.w + bb.w;
    uint2 ph, pl;
    split2(o0, o1, ph.x, pl.x);
    split2(o2, o3, ph.y, pl.y);
    *(uint2*)(yhi + (size_t)row * DIM + tid * 4) = ph;
    *(uint2*)(ylo + (size_t)row * DIM + tid * 4) = pl;
}

// =====================================================================
// bf16 split-GEMM — 512 threads / 16 warps (4M x 4N, 32x32 warp tiles),
// BK=64 chunks, 3-stage cp.async pipeline, M-fastest grid (L2 reuse).
// C = (Ah+Al)(MxK) @ (Bh+Bl)(KxN), 3-term fp32 acc.
// EPI: 0 plain, 1 +bias, 3 +bias+res, 4 +bias+relu -> bf16 hi/lo
// =====================================================================
#define BK     64
#define SPADA  72      // row stride 144B -> ldmatrix rows hit distinct bank-chunks
#define SPADB  136
#define NSTAGE 3

__device__ __forceinline__ void mma16816(float* c, const unsigned* a, const unsigned* b) {
    asm volatile(
        "mma.sync.aligned.m16n8k16.row.col.f32.bf16.bf16.f32 "
        "{%0,%1,%2,%3}, {%4,%5,%6,%7}, {%8,%9}, {%0,%1,%2,%3};\n"
        : "+f"(c[0]), "+f"(c[1]), "+f"(c[2]), "+f"(c[3])
        : "r"(a[0]), "r"(a[1]), "r"(a[2]), "r"(a[3]), "r"(b[0]), "r"(b[1]));
}
__device__ __forceinline__ void ldsm4(unsigned* r, unsigned addr) {
    asm volatile("ldmatrix.sync.aligned.m8n8.x4.shared.b16 {%0,%1,%2,%3}, [%4];\n"
                 : "=r"(r[0]), "=r"(r[1]), "=r"(r[2]), "=r"(r[3]) : "r"(addr));
}
__device__ __forceinline__ void ldsm4t(unsigned* r, unsigned addr) {
    asm volatile("ldmatrix.sync.aligned.m8n8.x4.trans.shared.b16 {%0,%1,%2,%3}, [%4];\n"
                 : "=r"(r[0]), "=r"(r[1]), "=r"(r[2]), "=r"(r[3]) : "r"(addr));
}
__device__ __forceinline__ void cpa16(unsigned dst, const void* src) {
    asm volatile("cp.async.cg.shared.global [%0], [%1], 16;\n" :: "r"(dst), "l"(src) : "memory");
}
__device__ __forceinline__ void cpa_commit() {
    asm volatile("cp.async.commit_group;\n" ::: "memory");
}
template <int Npend>
__device__ __forceinline__ void cpa_wait() {
    asm volatile("cp.async.wait_group %0;\n" :: "n"(Npend) : "memory");
}

template <int EPI>
__global__ __launch_bounds__(512, 1) void gemm_bf(const bf16* __restrict__ Ah_g,
                                                  const bf16* __restrict__ Al_g,
                                                  const bf16* __restrict__ Bh_g,
                                                  const bf16* __restrict__ Bl_g,
                                                  const float* __restrict__ bias,
                                                  const float* __restrict__ res,
                                                  float* __restrict__ C,
                                                  bf16* __restrict__ Chi,
                                                  bf16* __restrict__ Clo,
                                                  int M, int N, int K) {
    __shared__ __align__(16) bf16 Ah[NSTAGE][128][SPADA], Al[NSTAGE][128][SPADA];
    __shared__ __align__(16) bf16 Bh[NSTAGE][BK][SPADB],  Bl[NSTAGE][BK][SPADB];

    int tid = threadIdx.x;
    // M-fastest grid: a wave spans all M-tiles and few N-strips -> B stays in L2
    int bm = blockIdx.x * 128, bn = blockIdx.y * 128;
    int wid = tid >> 5, lane = tid & 31;
    int wm = (wid & 3) * 32;           // 4 warps along M
    int wn = (wid >> 2) * 32;          // 4 warps along N
    int g  = lane >> 2, tg = lane & 3;

    // cp.async fill mapping: A tile 128x64, B tile 64x128; 2 shots of 16B per array
    int a_row[2], a_col[2], b_row[2], b_col[2];
    #pragma unroll
    for (int i = 0; i < 2; i++) {
        int idx = tid + i * 512;
        a_row[i] = idx >> 3;  a_col[i] = (idx & 7) * 8;    // cols 0..56
        b_row[i] = idx >> 4;  b_col[i] = (idx & 15) * 8;   // cols 0..120
    }

    unsigned baseAh[NSTAGE], baseAl[NSTAGE], baseBh[NSTAGE], baseBl[NSTAGE];
    #pragma unroll
    for (int s = 0; s < NSTAGE; s++) {
        baseAh[s] = (unsigned)__cvta_generic_to_shared(&Ah[s][0][0]);
        baseAl[s] = (unsigned)__cvta_generic_to_shared(&Al[s][0][0]);
        baseBh[s] = (unsigned)__cvta_generic_to_shared(&Bh[s][0][0]);
        baseBl[s] = (unsigned)__cvta_generic_to_shared(&Bl[s][0][0]);
    }
    unsigned dA[2], dB[2];
    #pragma unroll
    for (int i = 0; i < 2; i++) {
        dA[i] = (a_row[i] * SPADA + a_col[i]) * 2;   // 16B multiples
        dB[i] = (b_row[i] * SPADB + b_col[i]) * 2;
    }

    auto issue = [&](int s, int k0) {
        #pragma unroll
        for (int i = 0; i < 2; i++) {
            size_t ao = (size_t)(bm + a_row[i]) * K + k0 + a_col[i];
            size_t bo = (size_t)(k0 + b_row[i]) * N + bn + b_col[i];
            cpa16(baseAh[s] + dA[i], Ah_g + ao);
            cpa16(baseAl[s] + dA[i], Al_g + ao);
            cpa16(baseBh[s] + dB[i], Bh_g + bo);
            cpa16(baseBl[s] + dB[i], Bl_g + bo);
        }
    };

    // ldmatrix lane addressing
    int a_row_l  = wm + (lane & 15);
    int a_col_l  = (lane >> 4) * 8;
    int b_krow_l = lane & 15;
    int b_ncol_l = wn + (lane >> 4) * 8;

    float acc[2][4][4];
    #pragma unroll
    for (int a = 0; a < 2; a++)
        #pragma unroll
        for (int b = 0; b < 4; b++)
            #pragma unroll
            for (int c = 0; c < 4; c++) acc[a][b][c] = 0.f;

    auto compute = [&](int s) {
        #pragma unroll
        for (int kk = 0; kk < BK; kk += 16) {
            unsigned afh[2][4], afl[2][4];
            #pragma unroll
            for (int mt = 0; mt < 2; mt++) {
                unsigned off = ((a_row_l + mt * 16) * SPADA + a_col_l + kk) * 2;
                ldsm4(afh[mt], baseAh[s] + off);
                ldsm4(afl[mt], baseAl[s] + off);
            }
            unsigned bfh[2][4], bfl[2][4];
            #pragma unroll
            for (int p = 0; p < 2; p++) {
                unsigned off = ((kk + b_krow_l) * SPADB + b_ncol_l + p * 16) * 2;
                ldsm4t(bfh[p], baseBh[s] + off);
                ldsm4t(bfl[p], baseBl[s] + off);
            }
            #pragma unroll
            for (int mt = 0; mt < 2; mt++) {
                #pragma unroll
                for (int nt = 0; nt < 4; nt++) {
                    unsigned* bh2 = &bfh[nt >> 1][(nt & 1) * 2];
                    unsigned* bl2 = &bfl[nt >> 1][(nt & 1) * 2];
                    mma16816(acc[mt][nt], afh[mt], bh2);
                    mma16816(acc[mt][nt], afh[mt], bl2);
                    mma16816(acc[mt][nt], afl[mt], bh2);
                }
            }
        }
    };

    // 3-stage pipeline: loads run two chunks ahead, one sync per iteration
    int nchunk = K / BK;
    issue(0, 0);       cpa_commit();
    issue(1, BK);      cpa_commit();
    for (int ch = 0; ch < nchunk; ch++) {
        cpa_wait<1>();          // stage ch resident (ch+1 may be in flight)
        __syncthreads();        // also fences: stage (ch+2)%3 fully read in iter ch-1
        int nx = ch + 2;
        if (nx < nchunk) issue(nx % NSTAGE, nx * BK);
        cpa_commit();           // uniform group bookkeeping (empty ok)
        compute(ch % NSTAGE);
    }

    // epilogue
    #pragma unroll
    for (int mt = 0; mt < 2; mt++) {
        #pragma unroll
        for (int nt = 0; nt < 4; nt++) {
            int row = bm + wm + mt * 16 + g;
            int col = bn + wn + nt * 8 + tg * 2;
            float2 o0 = make_float2(acc[mt][nt][0], acc[mt][nt][1]);
            float2 o1 = make_float2(acc[mt][nt][2], acc[mt][nt][3]);
            if (EPI >= 1) {
                float2 bb = *(const float2*)(bias + col);
                o0.x += bb.x; o0.y += bb.y; o1.x += bb.x; o1.y += bb.y;
            }
            if (EPI == 3) {
                float2 r0 = *(const float2*)(res + (size_t)row * N + col);
                float2 r1 = *(const float2*)(res + (size_t)(row + 8) * N + col);
                o0.x += r0.x; o0.y += r0.y; o1.x += r1.x; o1.y += r1.y;
            }
            if (EPI == 4) {
                o0.x = fmaxf(o0.x, 0.f); o0.y = fmaxf(o0.y, 0.f);
                o1.x = fmaxf(o1.x, 0.f); o1.y = fmaxf(o1.y, 0.f);
                unsigned h0, l0, h1, l1;
                split2(o0.x, o0.y, h0, l0);
                split2(o1.x, o1.y, h1, l1);
                *(unsigned*)(Chi + (size_t)row * N + col)       = h0;
                *(unsigned*)(Clo + (size_t)row * N + col)       = l0;
                *(unsigned*)(Chi + (size_t)(row + 8) * N + col) = h1;
                *(unsigned*)(Clo + (size_t)(row + 8) * N + col) = l1;
            } else {
                *(float2*)(C + (size_t)row * N + col) = o0;
                *(float2*)(C + (size_t)(row + 8) * N + col) = o1;
            }
        }
    }
}

// ---------------- fused causal GQA attention (fp32 in, bf16-split out) ----------------
__global__ __launch_bounds__(64) void attn_kernel(const float* __restrict__ QKV,
                                                  bf16* __restrict__ Yhi,
                                                  bf16* __restrict__ Ylo) {
    __shared__ __align__(16) float ks[64][64];
    __shared__ __align__(16) float vs[64][64];
    __shared__ float ss[64][65];

    int itile = blockIdx.x;
    int h     = blockIdx.y;
    int b     = blockIdx.z;
    int kvh   = h >> 2;
    int tid   = threadIdx.x;
    int i     = itile * 64 + tid;

    const float scale = 0.125f;
    float q[64], o[64];
    const float* qrow = QKV + ((size_t)(b * SEQ + i)) * QKVD + h * HSZ;
    #pragma unroll
    for (int d = 0; d < 64; d += 4) {
        float4 t = *(const float4*)(qrow + d);
        q[d] = t.x * scale; q[d+1] = t.y * scale; q[d+2] = t.z * scale; q[d+3] = t.w * scale;
    }
    #pragma unroll
    for (int d = 0; d < 64; d++) o[d] = 0.f;
    float m = -1e30f, l = 0.f;

    for (int j0 = 0; j0 <= itile * 64; j0 += 64) {
        const float* krow = QKV + ((size_t)(b * SEQ + j0 + tid)) * QKVD + DIM + kvh * HSZ;
        const float* vrow = krow + KVD;
        #pragma unroll
        for (int d = 0; d < 64; d += 4) {
            *(float4*)&ks[tid][d] = *(const float4*)(krow + d);
            *(float4*)&vs[tid][d] = *(const float4*)(vrow + d);
        }
        __syncthreads();

        float mt = m;
        #pragma unroll 4
        for (int j = 0; j < 64; j++) {
            float acc = 0.f;
            #pragma unroll
            for (int d = 0; d < 64; d += 4) {
                float4 kk = *(const float4*)&ks[j][d];
                acc = fmaf(q[d],   kk.x, acc);
                acc = fmaf(q[d+1], kk.y, acc);
                acc = fmaf(q[d+2], kk.z, acc);
                acc = fmaf(q[d+3], kk.w, acc);
            }
            if (j0 + j > i) acc = -1e30f;
            ss[tid][j] = acc;
            mt = fmaxf(mt, acc);
        }

        float corr = __expf(m - mt);
        l *= corr;
        #pragma unroll
        for (int d = 0; d < 64; d++) o[d] *= corr;

        #pragma unroll 2
        for (int j = 0; j < 64; j++) {
            float p = __expf(ss[tid][j] - mt);
            l += p;
            #pragma unroll
            for (int d = 0; d < 64; d += 4) {
                float4 vv = *(const float4*)&vs[j][d];
                o[d]   = fmaf(p, vv.x, o[d]);
                o[d+1] = fmaf(p, vv.y, o[d+1]);
                o[d+2] = fmaf(p, vv.z, o[d+2]);
                o[d+3] = fmaf(p, vv.w, o[d+3]);
            }
        }
        m = mt;
        __syncthreads();
    }

    float inv = 1.0f / l;
    size_t yo = ((size_t)(b * SEQ + i)) * DIM + h * HSZ;
    #pragma unroll
    for (int d = 0; d < 64; d += 4) {
        uint2 ph, pl;
        split2(o[d] * inv,   o[d+1] * inv, ph.x, pl.x);
        split2(o[d+2] * inv, o[d+3] * inv, ph.y, pl.y);
        *(uint2*)(Yhi + yo + d) = ph;
        *(uint2*)(Ylo + yo + d) = pl;
    }
}

// ---------------- host ----------------
template <typename Tp>
static void* sym_addr(Tp& s) {
    void* p = nullptr;
    cudaGetSymbolAddress(&p, s);
    return p;
}

static void launch_gemm(int epi, const bf16* Ah, const bf16* Al,
                        const bf16* Bh, const bf16* Bl,
                        const float* bias, const float* res,
                        float* C, bf16* Chi, bf16* Clo, int M, int N, int K) {
    dim3 grid(M / 128, N / 128);   // M-fastest
    switch (epi) {
        case 0: gemm_bf<0><<<grid, 512>>>(Ah, Al, Bh, Bl, bias, res, C, Chi, Clo, M, N, K); break;
        case 1: gemm_bf<1><<<grid, 512>>>(Ah, Al, Bh, Bl, bias, res, C, Chi, Clo, M, N, K); break;
        case 3: gemm_bf<3><<<grid, 512>>>(Ah, Al, Bh, Bl, bias, res, C, Chi, Clo, M, N, K); break;
        case 4: gemm_bf<4><<<grid, 512>>>(Ah, Al, Bh, Bl, bias, res, C, Chi, Clo, M, N, K); break;
    }
}

extern "C" void kernel_launch(void* const* d_in, const int* in_sizes, int n_in,
                              void* d_out, int out_size) {
    const int*   tok   = (const int*)  d_in[0];
    const float* te    = (const float*)d_in[1];
    const float* pe    = (const float*)d_in[2];
    const float* ln1g  = (const float*)d_in[3];
    const float* ln1b  = (const float*)d_in[4];
    const float* Wq    = (const float*)d_in[5];
    const float* Wk    = (const float*)d_in[6];
    const float* Wv    = (const float*)d_in[7];
    const float* Wo    = (const float*)d_in[8];
    const float* bo    = (const float*)d_in[9];
    const float* ln2g  = (const float*)d_in[10];
    const float* ln2b  = (const float*)d_in[11];
    const float* W1    = (const float*)d_in[12];
    const float* b1    = (const float*)d_in[13];
    const float* W2    = (const float*)d_in[14];
    const float* b2    = (const float*)d_in[15];
    const float* lnfg  = (const float*)d_in[16];
    const float* lnfb  = (const float*)d_in[17];
    const float* Wlm   = (const float*)d_in[18];
    const float* blm   = (const float*)d_in[19];
    float* out = (float*)d_out;

    float* x    = (float*)sym_addr(g_x);
    float* qkv  = (float*)sym_addr(g_qkv);
    bf16* h_hi  = (bf16*)sym_addr(g_h_hi),  * h_lo  = (bf16*)sym_addr(g_h_lo);
    bf16* y_hi  = (bf16*)sym_addr(g_y_hi),  * y_lo  = (bf16*)sym_addr(g_y_lo);
    bf16* ff_hi = (bf16*)sym_addr(g_ff_hi), * ff_lo = (bf16*)sym_addr(g_ff_lo);
    bf16* wqkv_hi = (bf16*)sym_addr(g_wqkv_hi), * wqkv_lo = (bf16*)sym_addr(g_wqkv_lo);
    bf16* wo_hi   = (bf16*)sym_addr(g_wo_hi),   * wo_lo   = (bf16*)sym_addr(g_wo_lo);
    bf16* w1_hi   = (bf16*)sym_addr(g_w1_hi),   * w1_lo   = (bf16*)sym_addr(g_w1_lo);
    bf16* w2_hi   = (bf16*)sym_addr(g_w2_hi),   * w2_lo   = (bf16*)sym_addr(g_w2_lo);
    bf16* wlm_hi  = (bf16*)sym_addr(g_wlm_hi),  * wlm_lo  = (bf16*)sym_addr(g_wlm_lo);

    // --- weight pre-split (once per pass) ---
    {
        int n4;
        n4 = NLAYER * DIM * (QKVD / 4);
        concat_split_qkv<<<(n4 + 255) / 256, 256>>>(Wq, Wk, Wv, wqkv_hi, wqkv_lo);
        n4 = NLAYER * DIM * DIM / 4;
        split_kernel<<<(n4 + 255) / 256, 256>>>(Wo, wo_hi, wo_lo, n4);
        n4 = NLAYER * DIM * FFD / 4;
        split_kernel<<<(n4 + 255) / 256, 256>>>(W1, w1_hi, w1_lo, n4);
        n4 = NLAYER * FFD * DIM / 4;
        split_kernel<<<(n4 + 255) / 256, 256>>>(W2, w2_hi, w2_lo, n4);
        n4 = DIM * VOCAB / 4;
        split_kernel<<<(n4 + 255) / 256, 256>>>(Wlm, wlm_hi, wlm_lo, n4);
    }

    embed_kernel<<<NTOK * DIM / 256, 256>>>(tok, te, pe, x);

    for (int l = 0; l < NLAYER; l++) {
        const bf16* wqh = wqkv_hi + (size_t)l * DIM * QKVD;
        const bf16* wql = wqkv_lo + (size_t)l * DIM * QKVD;
        const bf16* woh = wo_hi   + (size_t)l * DIM * DIM;
        const bf16* wol = wo_lo   + (size_t)l * DIM * DIM;
        const bf16* w1h = w1_hi   + (size_t)l * DIM * FFD;
        const bf16* w1l = w1_lo   + (size_t)l * DIM * FFD;
        const bf16* w2h = w2_hi   + (size_t)l * FFD * DIM;
        const bf16* w2l = w2_lo   + (size_t)l * FFD * DIM;

        ln_kernel<<<NTOK, 256>>>(x, ln1g + l * DIM, ln1b + l * DIM, h_hi, h_lo);

        launch_gemm(0, h_hi, h_lo, wqh, wql, nullptr, nullptr, qkv, nullptr, nullptr,
                    NTOK, QKVD, DIM);

        attn_kernel<<<dim3(SEQ / 64, NH, NB), 64>>>(qkv, y_hi, y_lo);

        launch_gemm(3, y_hi, y_lo, woh, wol, bo + l * DIM, x, x, nullptr, nullptr,
                    NTOK, DIM, DIM);

        ln_kernel<<<NTOK, 256>>>(x, ln2g + l * DIM, ln2b + l * DIM, h_hi, h_lo);

        launch_gemm(4, h_hi, h_lo, w1h, w1l, b1 + (size_t)l * FFD, nullptr,
                    nullptr, ff_hi, ff_lo, NTOK, FFD, DIM);
        launch_gemm(3, ff_hi, ff_lo, w2h, w2l, b2 + l * DIM, x, x, nullptr, nullptr,
                    NTOK, DIM, FFD);
    }

    ln_kernel<<<NTOK, 256>>>(x, lnfg, lnfb, h_hi, h_lo);
    launch_gemm(1, h_hi, h_lo, wlm_hi, wlm_lo, blm, nullptr, out, nullptr, nullptr,
                NTOK, VOCAB, DIM);
}

// round 12
// speedup vs baseline: 2.7023x; 1.0098x over previous
#include <cuda_runtime.h>
#include <cuda_bf16.h>

// ---------------- problem dims ----------------
#define NB     2
#define SEQ    1024
#define DIM    1024
#define NH     16
#define NKV    4
#define HSZ    64
#define NLAYER 6
#define VOCAB  32000
#define FFD    4096
#define NTOK   (NB*SEQ)          // 2048
#define KVD    (NKV*HSZ)         // 256
#define QKVD   (DIM + 2*KVD)     // 1536

typedef __nv_bfloat16 bf16;

// ---------------- scratch (256B-aligned) ----------------
__device__ __align__(256) float g_x  [NTOK*DIM];
__device__ __align__(256) float g_qkv[NTOK*QKVD];
__device__ __align__(256) bf16 g_h_hi [NTOK*DIM];
__device__ __align__(256) bf16 g_h_lo [NTOK*DIM];
__device__ __align__(256) bf16 g_y_hi [NTOK*DIM];
__device__ __align__(256) bf16 g_y_lo [NTOK*DIM];
__device__ __align__(256) bf16 g_ff_hi[NTOK*FFD];
__device__ __align__(256) bf16 g_ff_lo[NTOK*FFD];
__device__ __align__(256) bf16 g_wqkv_hi[NLAYER*DIM*QKVD];
__device__ __align__(256) bf16 g_wqkv_lo[NLAYER*DIM*QKVD];
__device__ __align__(256) bf16 g_wo_hi  [NLAYER*DIM*DIM];
__device__ __align__(256) bf16 g_wo_lo  [NLAYER*DIM*DIM];
__device__ __align__(256) bf16 g_w1_hi  [NLAYER*DIM*FFD];
__device__ __align__(256) bf16 g_w1_lo  [NLAYER*DIM*FFD];
__device__ __align__(256) bf16 g_w2_hi  [NLAYER*FFD*DIM];
__device__ __align__(256) bf16 g_w2_lo  [NLAYER*FFD*DIM];
__device__ __align__(256) bf16 g_wlm_hi [DIM*VOCAB];
__device__ __align__(256) bf16 g_wlm_lo [DIM*VOCAB];

// ---------------- helpers ----------------
__device__ __forceinline__ unsigned packbf2(float a, float b) {
    __nv_bfloat162 t = __floats2bfloat162_rn(a, b);
    return *(unsigned*)&t;
}
__device__ __forceinline__ void split2(float a, float b, unsigned& hi, unsigned& lo) {
    bf16 ha = __float2bfloat16(a), hb = __float2bfloat16(b);
    float la = a - __bfloat162float(ha);
    float lb = b - __bfloat162float(hb);
    __nv_bfloat162 h2 = __halves2bfloat162(ha, hb);
    hi = *(unsigned*)&h2;
    lo = packbf2(la, lb);
}

// ---------------- embedding ----------------
__global__ void embed_kernel(const int* __restrict__ tok, const float* __restrict__ te,
                             const float* __restrict__ pe, float* __restrict__ x) {
    int idx = blockIdx.x * 256 + threadIdx.x;
    int row = idx >> 10;
    int d   = idx & (DIM - 1);
    int t   = row & (SEQ - 1);
    x[idx] = te[(size_t)tok[row] * DIM + d] + pe[t * DIM + d];
}

// ---------------- split fp32 -> bf16 hi/lo (bulk, float4) ----------------
__global__ void split_kernel(const float* __restrict__ src, bf16* __restrict__ hi,
                             bf16* __restrict__ lo, int n4) {
    int i = blockIdx.x * 256 + threadIdx.x;
    if (i >= n4) return;
    float4 v = ((const float4*)src)[i];
    uint2 ph, pl;
    split2(v.x, v.y, ph.x, pl.x);
    split2(v.z, v.w, ph.y, pl.y);
    ((uint2*)hi)[i] = ph;
    ((uint2*)lo)[i] = pl;
}

// ---------------- concat Wq|Wk|Wv (all layers) + split ----------------
__global__ void concat_split_qkv(const float* __restrict__ Wq, const float* __restrict__ Wk,
                                 const float* __restrict__ Wv,
                                 bf16* __restrict__ hi, bf16* __restrict__ lo) {
    int idx4 = blockIdx.x * 256 + threadIdx.x;
    if (idx4 >= NLAYER * DIM * (QKVD / 4)) return;
    int l   = idx4 / (DIM * (QKVD / 4));
    int r   = idx4 % (DIM * (QKVD / 4));
    int row = r / (QKVD / 4);
    int col = (r % (QKVD / 4)) * 4;
    float4 v;
    if (col < DIM)            v = *(const float4*)(Wq + ((size_t)l * DIM + row) * DIM + col);
    else if (col < DIM + KVD) v = *(const float4*)(Wk + ((size_t)l * DIM + row) * KVD + (col - DIM));
    else                      v = *(const float4*)(Wv + ((size_t)l * DIM + row) * KVD + (col - DIM - KVD));
    uint2 ph, pl;
    split2(v.x, v.y, ph.x, pl.x);
    split2(v.z, v.w, ph.y, pl.y);
    size_t o = ((size_t)l * DIM + row) * QKVD + col;
    *(uint2*)(hi + o) = ph;
    *(uint2*)(lo + o) = pl;
}

// ---------------- layernorm -> split bf16 hi/lo ----------------
__global__ __launch_bounds__(256) void ln_kernel(const float* __restrict__ x,
                                                 const float* __restrict__ g,
                                                 const float* __restrict__ b,
                                                 bf16* __restrict__ yhi,
                                                 bf16* __restrict__ ylo) {
    int row = blockIdx.x;
    int tid = threadIdx.x;
    const float* xr = x + (size_t)row * DIM;
    float4 v = *(const float4*)(xr + tid * 4);
    float sum = v.x + v.y + v.z + v.w;
    float sq  = v.x*v.x + v.y*v.y + v.z*v.z + v.w*v.w;
    #pragma unroll
    for (int o = 16; o > 0; o >>= 1) {
        sum += __shfl_xor_sync(0xffffffffu, sum, o);
        sq  += __shfl_xor_sync(0xffffffffu, sq,  o);
    }
    __shared__ float sh[18];
    int wid = tid >> 5, lane = tid & 31;
    if (lane == 0) { sh[wid] = sum; sh[8 + wid] = sq; }
    __syncthreads();
    if (tid == 0) {
        float a = 0.f, c = 0.f;
        #pragma unroll
        for (int w = 0; w < 8; w++) { a += sh[w]; c += sh[8 + w]; }
        float mu  = a * (1.0f / DIM);
        float var = c * (1.0f / DIM) - mu * mu;
        sh[16] = mu;
        sh[17] = rsqrtf(var + 1e-5f);
    }
    __syncthreads();
    float mu = sh[16], rstd = sh[17];
    float4 gg = *(const float4*)(g + tid * 4);
    float4 bb = *(const float4*)(b + tid * 4);
    float o0 = (v.x - mu) * rstd * gg.x + bb.x;
    float o1 = (v.y - mu) * rstd * gg.y + bb.y;
    float o2 = (v.z - mu) * rstd * gg.z + bb.z;
    float o3 = (v.w - mu) * rstd * gg.w + bb.w;
    uint2 ph, pl;
    split2(o0, o1, ph.x, pl.x);
    split2(o2, o3, ph.y, pl.y);
    *(uint2*)(yhi + (size_t)row * DIM + tid * 4) = ph;
    *(uint2*)(ylo + (size_t)row * DIM + tid * 4) = pl;
}

// =====================================================================
// bf16 split-GEMM — 256 threads / 8 warps (2M x 4N, 64x32 warp tiles),
// BK=64 chunks, 3-stage cp.async pipeline, M-fastest grid (L2 reuse).
// Warp tile enlarged: 12 LDSM per 48 MMA per k16-step (ratio 4.0).
// C = (Ah+Al)(MxK) @ (Bh+Bl)(KxN), 3-term fp32 acc.
// EPI: 0 plain, 1 +bias, 3 +bias+res, 4 +bias+relu -> bf16 hi/lo
// =====================================================================
#define BK     64
#define SPADA  72      // row stride 144B -> ldmatrix rows hit distinct bank-chunks
#define SPADB  136
#define NSTAGE 3

__device__ __forceinline__ void mma16816(float* c, const unsigned* a, const unsigned* b) {
    asm volatile(
        "mma.sync.aligned.m16n8k16.row.col.f32.bf16.bf16.f32 "
        "{%0,%1,%2,%3}, {%4,%5,%6,%7}, {%8,%9}, {%0,%1,%2,%3};\n"
        : "+f"(c[0]), "+f"(c[1]), "+f"(c[2]), "+f"(c[3])
        : "r"(a[0]), "r"(a[1]), "r"(a[2]), "r"(a[3]), "r"(b[0]), "r"(b[1]));
}
__device__ __forceinline__ void ldsm4(unsigned* r, unsigned addr) {
    asm volatile("ldmatrix.sync.aligned.m8n8.x4.shared.b16 {%0,%1,%2,%3}, [%4];\n"
                 : "=r"(r[0]), "=r"(r[1]), "=r"(r[2]), "=r"(r[3]) : "r"(addr));
}
__device__ __forceinline__ void ldsm4t(unsigned* r, unsigned addr) {
    asm volatile("ldmatrix.sync.aligned.m8n8.x4.trans.shared.b16 {%0,%1,%2,%3}, [%4];\n"
                 : "=r"(r[0]), "=r"(r[1]), "=r"(r[2]), "=r"(r[3]) : "r"(addr));
}
__device__ __forceinline__ void cpa16(unsigned dst, const void* src) {
    asm volatile("cp.async.cg.shared.global [%0], [%1], 16;\n" :: "r"(dst), "l"(src) : "memory");
}
__device__ __forceinline__ void cpa_commit() {
    asm volatile("cp.async.commit_group;\n" ::: "memory");
}
template <int Npend>
__device__ __forceinline__ void cpa_wait() {
    asm volatile("cp.async.wait_group %0;\n" :: "n"(Npend) : "memory");
}

template <int EPI>
__global__ __launch_bounds__(256, 1) void gemm_bf(const bf16* __restrict__ Ah_g,
                                                  const bf16* __restrict__ Al_g,
                                                  const bf16* __restrict__ Bh_g,
                                                  const bf16* __restrict__ Bl_g,
                                                  const float* __restrict__ bias,
                                                  const float* __restrict__ res,
                                                  float* __restrict__ C,
                                                  bf16* __restrict__ Chi,
                                                  bf16* __restrict__ Clo,
                                                  int M, int N, int K) {
    __shared__ __align__(16) bf16 Ah[NSTAGE][128][SPADA], Al[NSTAGE][128][SPADA];
    __shared__ __align__(16) bf16 Bh[NSTAGE][BK][SPADB],  Bl[NSTAGE][BK][SPADB];

    int tid = threadIdx.x;
    // M-fastest grid: a wave spans all M-tiles and few N-strips -> B stays in L2
    int bm = blockIdx.x * 128, bn = blockIdx.y * 128;
    int wid = tid >> 5, lane = tid & 31;
    int wm = (wid & 1) * 64;           // 2 warps along M, warp tile 64 rows
    int wn = (wid >> 1) * 32;          // 4 warps along N, warp tile 32 cols
    int g  = lane >> 2, tg = lane & 3;

    // cp.async fill mapping: A tile 128x64 (1024 16B-chunks), B tile 64x128
    // (1024 chunks); 256 threads -> 4 shots per array
    int a_row[4], a_col[4], b_row[4], b_col[4];
    #pragma unroll
    for (int i = 0; i < 4; i++) {
        int idx = tid + i * 256;
        a_row[i] = idx >> 3;  a_col[i] = (idx & 7) * 8;    // cols 0..56
        b_row[i] = idx >> 4;  b_col[i] = (idx & 15) * 8;   // cols 0..120
    }

    unsigned baseAh[NSTAGE], baseAl[NSTAGE], baseBh[NSTAGE], baseBl[NSTAGE];
    #pragma unroll
    for (int s = 0; s < NSTAGE; s++) {
        baseAh[s] = (unsigned)__cvta_generic_to_shared(&Ah[s][0][0]);
        baseAl[s] = (unsigned)__cvta_generic_to_shared(&Al[s][0][0]);
        baseBh[s] = (unsigned)__cvta_generic_to_shared(&Bh[s][0][0]);
        baseBl[s] = (unsigned)__cvta_generic_to_shared(&Bl[s][0][0]);
    }
    unsigned dA[4], dB[4];
    #pragma unroll
    for (int i = 0; i < 4; i++) {
        dA[i] = (a_row[i] * SPADA + a_col[i]) * 2;   // 16B multiples
        dB[i] = (b_row[i] * SPADB + b_col[i]) * 2;
    }

    auto issue = [&](int s, int k0) {
        #pragma unroll
        for (int i = 0; i < 4; i++) {
            size_t ao = (size_t)(bm + a_row[i]) * K + k0 + a_col[i];
            size_t bo = (size_t)(k0 + b_row[i]) * N + bn + b_col[i];
            cpa16(baseAh[s] + dA[i], Ah_g + ao);
            cpa16(baseAl[s] + dA[i], Al_g + ao);
            cpa16(baseBh[s] + dB[i], Bh_g + bo);
            cpa16(baseBl[s] + dB[i], Bl_g + bo);
        }
    };

    // ldmatrix lane addressing
    int a_row_l  = wm + (lane & 15);
    int a_col_l  = (lane >> 4) * 8;
    int b_krow_l = lane & 15;
    int b_ncol_l = wn + (lane >> 4) * 8;

    float acc[4][4][4];
    #pragma unroll
    for (int a = 0; a < 4; a++)
        #pragma unroll
        for (int b = 0; b < 4; b++)
            #pragma unroll
            for (int c = 0; c < 4; c++) acc[a][b][c] = 0.f;

    auto compute = [&](int s) {
        #pragma unroll
        for (int kk = 0; kk < BK; kk += 16) {
            unsigned afh[4][4], afl[4][4];
            #pragma unroll
            for (int mt = 0; mt < 4; mt++) {
                unsigned off = ((a_row_l + mt * 16) * SPADA + a_col_l + kk) * 2;
                ldsm4(afh[mt], baseAh[s] + off);
                ldsm4(afl[mt], baseAl[s] + off);
            }
            unsigned bfh[2][4], bfl[2][4];
            #pragma unroll
            for (int p = 0; p < 2; p++) {
                unsigned off = ((kk + b_krow_l) * SPADB + b_ncol_l + p * 16) * 2;
                ldsm4t(bfh[p], baseBh[s] + off);
                ldsm4t(bfl[p], baseBl[s] + off);
            }
            #pragma unroll
            for (int mt = 0; mt < 4; mt++) {
                #pragma unroll
                for (int nt = 0; nt < 4; nt++) {
                    unsigned* bh2 = &bfh[nt >> 1][(nt & 1) * 2];
                    unsigned* bl2 = &bfl[nt >> 1][(nt & 1) * 2];
                    mma16816(acc[mt][nt], afh[mt], bh2);
                    mma16816(acc[mt][nt], afh[mt], bl2);
                    mma16816(acc[mt][nt], afl[mt], bh2);
                }
            }
        }
    };

    // 3-stage pipeline: loads run two chunks ahead, one sync per iteration
    int nchunk = K / BK;
    issue(0, 0);       cpa_commit();
    issue(1, BK);      cpa_commit();
    for (int ch = 0; ch < nchunk; ch++) {
        cpa_wait<1>();          // stage ch resident (ch+1 may be in flight)
        __syncthreads();        // also fences: stage (ch+2)%3 fully read in iter ch-1
        int nx = ch + 2;
        if (nx < nchunk) issue(nx % NSTAGE, nx * BK);
        cpa_commit();           // uniform group bookkeeping (empty ok)
        compute(ch % NSTAGE);
    }

    // epilogue
    #pragma unroll
    for (int mt = 0; mt < 4; mt++) {
        #pragma unroll
        for (int nt = 0; nt < 4; nt++) {
            int row = bm + wm + mt * 16 + g;
            int col = bn + wn + nt * 8 + tg * 2;
            float2 o0 = make_float2(acc[mt][nt][0], acc[mt][nt][1]);
            float2 o1 = make_float2(acc[mt][nt][2], acc[mt][nt][3]);
            if (EPI >= 1) {
                float2 bb = *(const float2*)(bias + col);
                o0.x += bb.x; o0.y += bb.y; o1.x += bb.x; o1.y += bb.y;
            }
            if (EPI == 3) {
                float2 r0 = *(const float2*)(res + (size_t)row * N + col);
                float2 r1 = *(const float2*)(res + (size_t)(row + 8) * N + col);
                o0.x += r0.x; o0.y += r0.y; o1.x += r1.x; o1.y += r1.y;
            }
            if (EPI == 4) {
                o0.x = fmaxf(o0.x, 0.f); o0.y = fmaxf(o0.y, 0.f);
                o1.x = fmaxf(o1.x, 0.f); o1.y = fmaxf(o1.y, 0.f);
                unsigned h0, l0, h1, l1;
                split2(o0.x, o0.y, h0, l0);
                split2(o1.x, o1.y, h1, l1);
                *(unsigned*)(Chi + (size_t)row * N + col)       = h0;
                *(unsigned*)(Clo + (size_t)row * N + col)       = l0;
                *(unsigned*)(Chi + (size_t)(row + 8) * N + col) = h1;
                *(unsigned*)(Clo + (size_t)(row + 8) * N + col) = l1;
            } else {
                *(float2*)(C + (size_t)row * N + col) = o0;
                *(float2*)(C + (size_t)(row + 8) * N + col) = o1;
            }
        }
    }
}

// ---------------- fused causal GQA attention (fp32 in, bf16-split out) ----------------
__global__ __launch_bounds__(64) void attn_kernel(const float* __restrict__ QKV,
                                                  bf16* __restrict__ Yhi,
                                                  bf16* __restrict__ Ylo) {
    __shared__ __align__(16) float ks[64][64];
    __shared__ __align__(16) float vs[64][64];
    __shared__ float ss[64][65];

    int itile = blockIdx.x;
    int h     = blockIdx.y;
    int b     = blockIdx.z;
    int kvh   = h >> 2;
    int tid   = threadIdx.x;
    int i     = itile * 64 + tid;

    const float scale = 0.125f;
    float q[64], o[64];
    const float* qrow = QKV + ((size_t)(b * SEQ + i)) * QKVD + h * HSZ;
    #pragma unroll
    for (int d = 0; d < 64; d += 4) {
        float4 t = *(const float4*)(qrow + d);
        q[d] = t.x * scale; q[d+1] = t.y * scale; q[d+2] = t.z * scale; q[d+3] = t.w * scale;
    }
    #pragma unroll
    for (int d = 0; d < 64; d++) o[d] = 0.f;
    float m = -1e30f, l = 0.f;

    for (int j0 = 0; j0 <= itile * 64; j0 += 64) {
        const float* krow = QKV + ((size_t)(b * SEQ + j0 + tid)) * QKVD + DIM + kvh * HSZ;
        const float* vrow = krow + KVD;
        #pragma unroll
        for (int d = 0; d < 64; d += 4) {
            *(float4*)&ks[tid][d] = *(const float4*)(krow + d);
            *(float4*)&vs[tid][d] = *(const float4*)(vrow + d);
        }
        __syncthreads();

        float mt = m;
        #pragma unroll 4
        for (int j = 0; j < 64; j++) {
            float acc = 0.f;
            #pragma unroll
            for (int d = 0; d < 64; d += 4) {
                float4 kk = *(const float4*)&ks[j][d];
                acc = fmaf(q[d],   kk.x, acc);
                acc = fmaf(q[d+1], kk.y, acc);
                acc = fmaf(q[d+2], kk.z, acc);
                acc = fmaf(q[d+3], kk.w, acc);
            }
            if (j0 + j > i) acc = -1e30f;
            ss[tid][j] = acc;
            mt = fmaxf(mt, acc);
        }

        float corr = __expf(m - mt);
        l *= corr;
        #pragma unroll
        for (int d = 0; d < 64; d++) o[d] *= corr;

        #pragma unroll 2
        for (int j = 0; j < 64; j++) {
            float p = __expf(ss[tid][j] - mt);
            l += p;
            #pragma unroll
            for (int d = 0; d < 64; d += 4) {
                float4 vv = *(const float4*)&vs[j][d];
                o[d]   = fmaf(p, vv.x, o[d]);
                o[d+1] = fmaf(p, vv.y, o[d+1]);
                o[d+2] = fmaf(p, vv.z, o[d+2]);
                o[d+3] = fmaf(p, vv.w, o[d+3]);
            }
        }
        m = mt;
        __syncthreads();
    }

    float inv = 1.0f / l;
    size_t yo = ((size_t)(b * SEQ + i)) * DIM + h * HSZ;
    #pragma unroll
    for (int d = 0; d < 64; d += 4) {
        uint2 ph, pl;
        split2(o[d] * inv,   o[d+1] * inv, ph.x, pl.x);
        split2(o[d+2] * inv, o[d+3] * inv, ph.y, pl.y);
        *(uint2*)(Yhi + yo + d) = ph;
        *(uint2*)(Ylo + yo + d) = pl;
    }
}

// ---------------- host ----------------
template <typename Tp>
static void* sym_addr(Tp& s) {
    void* p = nullptr;
    cudaGetSymbolAddress(&p, s);
    return p;
}

static void launch_gemm(int epi, const bf16* Ah, const bf16* Al,
                        const bf16* Bh, const bf16* Bl,
                        const float* bias, const float* res,
                        float* C, bf16* Chi, bf16* Clo, int M, int N, int K) {
    dim3 grid(M / 128, N / 128);   // M-fastest
    switch (epi) {
        case 0: gemm_bf<0><<<grid, 256>>>(Ah, Al, Bh, Bl, bias, res, C, Chi, Clo, M, N, K); break;
        case 1: gemm_bf<1><<<grid, 256>>>(Ah, Al, Bh, Bl, bias, res, C, Chi, Clo, M, N, K); break;
        case 3: gemm_bf<3><<<grid, 256>>>(Ah, Al, Bh, Bl, bias, res, C, Chi, Clo, M, N, K); break;
        case 4: gemm_bf<4><<<grid, 256>>>(Ah, Al, Bh, Bl, bias, res, C, Chi, Clo, M, N, K); break;
    }
}

extern "C" void kernel_launch(void* const* d_in, const int* in_sizes, int n_in,
                              void* d_out, int out_size) {
    const int*   tok   = (const int*)  d_in[0];
    const float* te    = (const float*)d_in[1];
    const float* pe    = (const float*)d_in[2];
    const float* ln1g  = (const float*)d_in[3];
    const float* ln1b  = (const float*)d_in[4];
    const float* Wq    = (const float*)d_in[5];
    const float* Wk    = (const float*)d_in[6];
    const float* Wv    = (const float*)d_in[7];
    const float* Wo    = (const float*)d_in[8];
    const float* bo    = (const float*)d_in[9];
    const float* ln2g  = (const float*)d_in[10];
    const float* ln2b  = (const float*)d_in[11];
    const float* W1    = (const float*)d_in[12];
    const float* b1    = (const float*)d_in[13];
    const float* W2    = (const float*)d_in[14];
    const float* b2    = (const float*)d_in[15];
    const float* lnfg  = (const float*)d_in[16];
    const float* lnfb  = (const float*)d_in[17];
    const float* Wlm   = (const float*)d_in[18];
    const float* blm   = (const float*)d_in[19];
    float* out = (float*)d_out;

    float* x    = (float*)sym_addr(g_x);
    float* qkv  = (float*)sym_addr(g_qkv);
    bf16* h_hi  = (bf16*)sym_addr(g_h_hi),  * h_lo  = (bf16*)sym_addr(g_h_lo);
    bf16* y_hi  = (bf16*)sym_addr(g_y_hi),  * y_lo  = (bf16*)sym_addr(g_y_lo);
    bf16* ff_hi = (bf16*)sym_addr(g_ff_hi), * ff_lo = (bf16*)sym_addr(g_ff_lo);
    bf16* wqkv_hi = (bf16*)sym_addr(g_wqkv_hi), * wqkv_lo = (bf16*)sym_addr(g_wqkv_lo);
    bf16* wo_hi   = (bf16*)sym_addr(g_wo_hi),   * wo_lo   = (bf16*)sym_addr(g_wo_lo);
    bf16* w1_hi   = (bf16*)sym_addr(g_w1_hi),   * w1_lo   = (bf16*)sym_addr(g_w1_lo);
    bf16* w2_hi   = (bf16*)sym_addr(g_w2_hi),   * w2_lo   = (bf16*)sym_addr(g_w2_lo);
    bf16* wlm_hi  = (bf16*)sym_addr(g_wlm_hi),  * wlm_lo  = (bf16*)sym_addr(g_wlm_lo);

    // --- weight pre-split (once per pass) ---
    {
        int n4;
        n4 = NLAYER * DIM * (QKVD / 4);
        concat_split_qkv<<<(n4 + 255) / 256, 256>>>(Wq, Wk, Wv, wqkv_hi, wqkv_lo);
        n4 = NLAYER * DIM * DIM / 4;
        split_kernel<<<(n4 + 255) / 256, 256>>>(Wo, wo_hi, wo_lo, n4);
        n4 = NLAYER * DIM * FFD / 4;
        split_kernel<<<(n4 + 255) / 256, 256>>>(W1, w1_hi, w1_lo, n4);
        n4 = NLAYER * FFD * DIM / 4;
        split_kernel<<<(n4 + 255) / 256, 256>>>(W2, w2_hi, w2_lo, n4);
        n4 = DIM * VOCAB / 4;
        split_kernel<<<(n4 + 255) / 256, 256>>>(Wlm, wlm_hi, wlm_lo, n4);
    }

    embed_kernel<<<NTOK * DIM / 256, 256>>>(tok, te, pe, x);

    for (int l = 0; l < NLAYER; l++) {
        const bf16* wqh = wqkv_hi + (size_t)l * DIM * QKVD;
        const bf16* wql = wqkv_lo + (size_t)l * DIM * QKVD;
        const bf16* woh = wo_hi   + (size_t)l * DIM * DIM;
        const bf16* wol = wo_lo   + (size_t)l * DIM * DIM;
        const bf16* w1h = w1_hi   + (size_t)l * DIM * FFD;
        const bf16* w1l = w1_lo   + (size_t)l * DIM * FFD;
        const bf16* w2h = w2_hi   + (size_t)l * FFD * DIM;
        const bf16* w2l = w2_lo   + (size_t)l * FFD * DIM;

        ln_kernel<<<NTOK, 256>>>(x, ln1g + l * DIM, ln1b + l * DIM, h_hi, h_lo);

        launch_gemm(0, h_hi, h_lo, wqh, wql, nullptr, nullptr, qkv, nullptr, nullptr,
                    NTOK, QKVD, DIM);

        attn_kernel<<<dim3(SEQ / 64, NH, NB), 64>>>(qkv, y_hi, y_lo);

        launch_gemm(3, y_hi, y_lo, woh, wol, bo + l * DIM, x, x, nullptr, nullptr,
                    NTOK, DIM, DIM);

        ln_kernel<<<NTOK, 256>>>(x, ln2g + l * DIM, ln2b + l * DIM, h_hi, h_lo);

        launch_gemm(4, h_hi, h_lo, w1h, w1l, b1 + (size_t)l * FFD, nullptr,
                    nullptr, ff_hi, ff_lo, NTOK, FFD, DIM);
        launch_gemm(3, ff_hi, ff_lo, w2h, w2l, b2 + l * DIM, x, x, nullptr, nullptr,
                    NTOK, DIM, FFD);
    }

    ln_kernel<<<NTOK, 256>>>(x, lnfg, lnfb, h_hi, h_lo);
    launch_gemm(1, h_hi, h_lo, wlm_hi, wlm_lo, blm, nullptr, out, nullptr, nullptr,
                NTOK, VOCAB, DIM);
}